// round 1
// baseline (speedup 1.0000x reference)
#include <cuda_runtime.h>
#include <math.h>

// ---------------- problem constants ----------------
#define D_      2048
#define NTOK    8192        // S*B = 2048*4
#define LAT     256
#define NEXP    32
#define TOPK    4
#define EH      1024        // expert hidden
#define SH      2048        // shared hidden
#define ATOT    (NTOK*TOPK) // 32768 assignments (always exactly this)
#define MAXTILES 320

// ---------------- device scratch (no allocations allowed) ----------------
__device__ float g_hnorm [NTOK*D_];        // rmsnorm(h)            67MB
__device__ float g_scores[NTOK*NEXP];      // sigmoid router scores
__device__ float g_latent[NTOK*LAT];       // h_norm @ latent_down
__device__ float g_Y     [(size_t)ATOT*2*EH]; // expert pre-act      268MB
__device__ float g_ACT   [(size_t)ATOT*EH];   // spike*lin           134MB
__device__ float g_contrib[(size_t)ATOT*LAT]; // per-assignment out  33MB
__device__ float g_eout  [NTOK*LAT];       // combined expert out
__device__ float g_SY    [(size_t)NTOK*2*SH]; // shared pre-act      134MB
__device__ float g_ACTS  [NTOK*SH];        // shared spike*lin      67MB
__device__ float g_X     [NTOK*D_];        // routed + shared*gate  67MB
__device__ float g_gate  [NTOK];
__device__ float g_Psum  [NEXP];
__device__ int   g_count [NEXP];
__device__ int   g_off   [NEXP+1];
__device__ int   g_cursor[NEXP];
__device__ int   g_tile_e[MAXTILES];
__device__ int   g_tile_r[MAXTILES];
__device__ int   g_ntiles;
__device__ int   g_assign_tok[ATOT];
__device__ int   g_assign_exp[ATOT];
__device__ int   g_assign_pos[ATOT];       // (n,k) -> row in assign space
__device__ int   g_topi[ATOT];             // (n,k) -> expert
__device__ float g_topw[ATOT];             // (n,k) -> combine weight

// ---------------- rmsnorm ----------------
__global__ void k_rmsnorm(const float* __restrict__ h, const float* __restrict__ w)
{
    int n = blockIdx.x;
    const float4* hp = (const float4*)(h + (size_t)n * D_);
    float ss = 0.f;
    for (int i = threadIdx.x; i < D_/4; i += 256) {
        float4 v = hp[i];
        ss += v.x*v.x + v.y*v.y + v.z*v.z + v.w*v.w;
    }
    __shared__ float red[256];
    red[threadIdx.x] = ss; __syncthreads();
    for (int s = 128; s; s >>= 1) {
        if (threadIdx.x < s) red[threadIdx.x] += red[threadIdx.x + s];
        __syncthreads();
    }
    float rs = rsqrtf(red[0] * (1.f / D_) + 1e-6f);
    float4*       op = (float4*)(g_hnorm + (size_t)n * D_);
    const float4* wp = (const float4*)w;
    for (int i = threadIdx.x; i < D_/4; i += 256) {
        float4 v = hp[i], wv = wp[i];
        v.x *= rs*wv.x; v.y *= rs*wv.y; v.z *= rs*wv.z; v.w *= rs*wv.w;
        op[i] = v;
    }
}

// ---------------- router: scores = sigmoid(hnorm @ Wr + b) ----------------
// block: 32 tokens x 32 experts, 256 threads
__global__ void k_router(const float* __restrict__ rw, const float* __restrict__ rb)
{
    __shared__ float hs[32][64];
    __shared__ float ws[64][32];
    int n0 = blockIdx.x * 32;
    int tid = threadIdx.x;
    int e  = tid & 31;
    int tr = tid >> 5;
    float acc[4] = {0.f, 0.f, 0.f, 0.f};
    for (int k0 = 0; k0 < D_; k0 += 64) {
        #pragma unroll
        for (int i = 0; i < 8; i++) {
            int lin = tid + i*256;
            int t = lin >> 6, k = lin & 63;
            hs[t][k] = g_hnorm[(size_t)(n0 + t)*D_ + k0 + k];
            int kw = lin >> 5, ew = lin & 31;
            ws[kw][ew] = rw[(size_t)(k0 + kw)*NEXP + ew];
        }
        __syncthreads();
        #pragma unroll
        for (int kk = 0; kk < 64; kk++) {
            #pragma unroll
            for (int i = 0; i < 4; i++)
                acc[i] += hs[tr + 8*i][kk] * ws[kk][e];
        }
        __syncthreads();
    }
    float bias = rb[e];
    #pragma unroll
    for (int i = 0; i < 4; i++) {
        int t = tr + 8*i;
        float v = acc[i] + bias;
        g_scores[(n0 + t)*NEXP + e] = 1.f / (1.f + expf(-v));
    }
}

// ---------------- top-4 per token (warp per token) ----------------
__global__ void k_topk()
{
    int warp = threadIdx.x >> 5;
    int lane = threadIdx.x & 31;
    int n = blockIdx.x * 8 + warp;
    float s = g_scores[n*NEXP + lane];
    float topv[4]; int topi[4];
    #pragma unroll
    for (int k = 0; k < 4; k++) {
        float v = s; int bi = lane;
        #pragma unroll
        for (int off = 16; off; off >>= 1) {
            float v2 = __shfl_xor_sync(0xffffffffu, v, off);
            int   i2 = __shfl_xor_sync(0xffffffffu, bi, off);
            if (v2 > v || (v2 == v && i2 < bi)) { v = v2; bi = i2; }
        }
        topv[k] = v; topi[k] = bi;
        if (lane == bi) s = -1e30f;
    }
    if (lane == 0) {
        float sum = topv[0] + topv[1] + topv[2] + topv[3];
        float inv = 1.f / (sum + 1e-8f);
        #pragma unroll
        for (int k = 0; k < 4; k++) {
            g_topw[n*4 + k] = topv[k] * inv;
            g_topi[n*4 + k] = topi[k];
            atomicAdd(&g_count[topi[k]], 1);
        }
    }
}

// ---------------- P = column sums of scores (deterministic) ----------------
__global__ void k_colsum()
{
    int e = blockIdx.x;
    float s = 0.f;
    for (int n = threadIdx.x; n < NTOK; n += 256) s += g_scores[n*NEXP + e];
    __shared__ float red[256];
    red[threadIdx.x] = s; __syncthreads();
    for (int st = 128; st; st >>= 1) {
        if (threadIdx.x < st) red[threadIdx.x] += red[threadIdx.x + st];
        __syncthreads();
    }
    if (threadIdx.x == 0) g_Psum[e] = red[0];
}

// ---------------- expert offsets + grouped-GEMM tile table ----------------
__global__ void k_offsets()
{
    if (threadIdx.x == 0) {
        int acc = 0;
        for (int e = 0; e < NEXP; e++) {
            g_off[e] = acc; g_cursor[e] = acc; acc += g_count[e];
        }
        g_off[NEXP] = acc;
        int nt = 0;
        for (int e = 0; e < NEXP; e++) {
            int ne = g_count[e];
            for (int r = 0; r < ne; r += 128) {
                g_tile_e[nt] = e; g_tile_r[nt] = g_off[e] + r; nt++;
            }
        }
        g_ntiles = nt;
    }
}

// ---------------- scatter tokens into expert-sorted assignment lists ----------------
__global__ void k_assign()
{
    int n = blockIdx.x * 256 + threadIdx.x;
    if (n >= NTOK) return;
    #pragma unroll
    for (int k = 0; k < 4; k++) {
        int e = g_topi[n*4 + k];
        int pos = atomicAdd(&g_cursor[e], 1);
        g_assign_tok[pos] = n;
        g_assign_exp[pos] = e;
        g_assign_pos[n*4 + k] = pos;
    }
}

// ---------------- dense SGEMM: C[M,N] = A[M,K] @ B[K,N] (row-major) ----------------
// BM=BN=128, BK=8, 256 threads, 8x8 per thread, double-buffered.
// epilogue: val*rowscale[r] (+resid) (+=C)
__launch_bounds__(256)
__global__ void k_sgemm(const float* __restrict__ A, const float* __restrict__ B,
                        float* __restrict__ C, int M, int N, int K,
                        const float* __restrict__ rowscale,
                        const float* __restrict__ resid,
                        int accumulate)
{
    __shared__ float As[2][8][128];
    __shared__ float Bs[2][8][128];
    const int tid = threadIdx.x;
    const int bx = blockIdx.x, by = blockIdx.y;
    const int tx = tid & 15, ty = tid >> 4;
    const int a_row = tid >> 1, a_col = (tid & 1) * 4;
    const int b_row = tid >> 5, b_col = (tid & 31) * 4;
    const float* Aptr = A + (size_t)(by*128 + a_row) * K + a_col;
    const float* Bptr = B + (size_t)b_row * N + bx*128 + b_col;
    float acc[8][8];
    #pragma unroll
    for (int i = 0; i < 8; i++)
        #pragma unroll
        for (int j = 0; j < 8; j++) acc[i][j] = 0.f;

    float4 av = *(const float4*)Aptr;
    float4 bv = *(const float4*)Bptr;
    As[0][a_col+0][a_row] = av.x; As[0][a_col+1][a_row] = av.y;
    As[0][a_col+2][a_row] = av.z; As[0][a_col+3][a_row] = av.w;
    *(float4*)&Bs[0][b_row][b_col] = bv;
    __syncthreads();

    const int nk = K >> 3;
    for (int kt = 0; kt < nk; kt++) {
        const int cur = kt & 1;
        float4 na, nb;
        if (kt + 1 < nk) {
            na = *(const float4*)(Aptr + (kt + 1) * 8);
            nb = *(const float4*)(Bptr + (size_t)(kt + 1) * 8 * N);
        }
        #pragma unroll
        for (int kk = 0; kk < 8; kk++) {
            float4 a0 = *(const float4*)&As[cur][kk][ty*8];
            float4 a1 = *(const float4*)&As[cur][kk][ty*8 + 4];
            float4 b0 = *(const float4*)&Bs[cur][kk][tx*8];
            float4 b1 = *(const float4*)&Bs[cur][kk][tx*8 + 4];
            float ar[8] = {a0.x,a0.y,a0.z,a0.w,a1.x,a1.y,a1.z,a1.w};
            float br[8] = {b0.x,b0.y,b0.z,b0.w,b1.x,b1.y,b1.z,b1.w};
            #pragma unroll
            for (int i = 0; i < 8; i++)
                #pragma unroll
                for (int j = 0; j < 8; j++)
                    acc[i][j] += ar[i]*br[j];
        }
        if (kt + 1 < nk) {
            const int nxt = cur ^ 1;
            As[nxt][a_col+0][a_row] = na.x; As[nxt][a_col+1][a_row] = na.y;
            As[nxt][a_col+2][a_row] = na.z; As[nxt][a_col+3][a_row] = na.w;
            *(float4*)&Bs[nxt][b_row][b_col] = nb;
            __syncthreads();
        }
    }
    #pragma unroll
    for (int i = 0; i < 8; i++) {
        int r = by*128 + ty*8 + i;
        float rs = rowscale ? rowscale[r] : 1.f;
        size_t base = (size_t)r * N + bx*128 + tx*8;
        #pragma unroll
        for (int j = 0; j < 8; j += 4) {
            float4 v;
            v.x = acc[i][j+0]*rs; v.y = acc[i][j+1]*rs;
            v.z = acc[i][j+2]*rs; v.w = acc[i][j+3]*rs;
            if (resid) {
                float4 rv = *(const float4*)&resid[base + j];
                v.x += rv.x; v.y += rv.y; v.z += rv.z; v.w += rv.w;
            }
            if (accumulate) {
                float4 cv = *(const float4*)&C[base + j];
                v.x += cv.x; v.y += cv.y; v.z += cv.z; v.w += cv.w;
            }
            *(float4*)&C[base + j] = v;
        }
    }
}

// ---------------- grouped GEMM 1: Y = latent[tokens_e] @ W1_e   (K=256, N=2048) ----------------
__launch_bounds__(256)
__global__ void k_gemm_exp1(const float* __restrict__ latent, const float* __restrict__ W1)
{
    const int bt = blockIdx.x;
    if (bt >= g_ntiles) return;
    const int e    = g_tile_e[bt];
    const int r0   = g_tile_r[bt];
    const int rend = g_off[e + 1];
    const int bx   = blockIdx.y;           // N tile (16 tiles of 128 over 2048)

    __shared__ float As[2][8][128];
    __shared__ float Bs[2][8][128];
    const int tid = threadIdx.x;
    const int tx = tid & 15, ty = tid >> 4;
    const int a_row = tid >> 1, a_col = (tid & 1) * 4;
    const int b_row = tid >> 5, b_col = (tid & 31) * 4;

    int ar  = r0 + a_row;
    int arc = (ar < rend) ? ar : (rend - 1);
    int tok = g_assign_tok[arc];
    const float* Aptr = latent + (size_t)tok * LAT + a_col;
    const float* Bptr = W1 + (size_t)e * (LAT * 2 * EH) + (size_t)b_row * (2*EH) + bx*128 + b_col;

    float acc[8][8];
    #pragma unroll
    for (int i = 0; i < 8; i++)
        #pragma unroll
        for (int j = 0; j < 8; j++) acc[i][j] = 0.f;

    float4 av = *(const float4*)Aptr;
    float4 bv = *(const float4*)Bptr;
    As[0][a_col+0][a_row] = av.x; As[0][a_col+1][a_row] = av.y;
    As[0][a_col+2][a_row] = av.z; As[0][a_col+3][a_row] = av.w;
    *(float4*)&Bs[0][b_row][b_col] = bv;
    __syncthreads();

    const int nk = LAT >> 3;  // 32
    for (int kt = 0; kt < nk; kt++) {
        const int cur = kt & 1;
        float4 na, nb;
        if (kt + 1 < nk) {
            na = *(const float4*)(Aptr + (kt + 1) * 8);
            nb = *(const float4*)(Bptr + (size_t)(kt + 1) * 8 * (2*EH));
        }
        #pragma unroll
        for (int kk = 0; kk < 8; kk++) {
            float4 a0 = *(const float4*)&As[cur][kk][ty*8];
            float4 a1 = *(const float4*)&As[cur][kk][ty*8 + 4];
            float4 b0 = *(const float4*)&Bs[cur][kk][tx*8];
            float4 b1 = *(const float4*)&Bs[cur][kk][tx*8 + 4];
            float arr[8] = {a0.x,a0.y,a0.z,a0.w,a1.x,a1.y,a1.z,a1.w};
            float brr[8] = {b0.x,b0.y,b0.z,b0.w,b1.x,b1.y,b1.z,b1.w};
            #pragma unroll
            for (int i = 0; i < 8; i++)
                #pragma unroll
                for (int j = 0; j < 8; j++)
                    acc[i][j] += arr[i]*brr[j];
        }
        if (kt + 1 < nk) {
            const int nxt = cur ^ 1;
            As[nxt][a_col+0][a_row] = na.x; As[nxt][a_col+1][a_row] = na.y;
            As[nxt][a_col+2][a_row] = na.z; As[nxt][a_col+3][a_row] = na.w;
            *(float4*)&Bs[nxt][b_row][b_col] = nb;
            __syncthreads();
        }
    }
    #pragma unroll
    for (int i = 0; i < 8; i++) {
        int r = r0 + ty*8 + i;
        if (r < rend) {
            size_t base = (size_t)r * (2*EH) + bx*128 + tx*8;
            #pragma unroll
            for (int j = 0; j < 8; j += 4) {
                float4 v; v.x = acc[i][j]; v.y = acc[i][j+1]; v.z = acc[i][j+2]; v.w = acc[i][j+3];
                *(float4*)&g_Y[base + j] = v;
            }
        }
    }
}

// ---------------- expert activation: ACT = spike(gate,vth_e) * lin ----------------
__global__ void k_expact(const float* __restrict__ vth)
{
    size_t idx = (size_t)blockIdx.x * 256 + threadIdx.x;
    int a = (int)(idx >> 10);
    int j = (int)(idx & 1023);
    int e = g_assign_exp[a];
    float gte = g_Y[(size_t)a * (2*EH) + j];
    float lin = g_Y[(size_t)a * (2*EH) + EH + j];
    float v = vth[e*EH + j];
    g_ACT[idx] = (gte >= v ? v : 0.f) * lin;
}

// ---------------- grouped GEMM 2: contrib = ACT @ W2_e   (K=1024, N=256) ----------------
__launch_bounds__(256)
__global__ void k_gemm_exp2(const float* __restrict__ W2)
{
    const int bt = blockIdx.x;
    if (bt >= g_ntiles) return;
    const int e    = g_tile_e[bt];
    const int r0   = g_tile_r[bt];
    const int rend = g_off[e + 1];
    const int bx   = blockIdx.y;           // 0..1

    __shared__ float As[2][8][128];
    __shared__ float Bs[2][8][128];
    const int tid = threadIdx.x;
    const int tx = tid & 15, ty = tid >> 4;
    const int a_row = tid >> 1, a_col = (tid & 1) * 4;
    const int b_row = tid >> 5, b_col = (tid & 31) * 4;

    int ar  = r0 + a_row;
    int arc = (ar < rend) ? ar : (rend - 1);
    const float* Aptr = g_ACT + (size_t)arc * EH + a_col;
    const float* Bptr = W2 + (size_t)e * (EH * LAT) + (size_t)b_row * LAT + bx*128 + b_col;

    float acc[8][8];
    #pragma unroll
    for (int i = 0; i < 8; i++)
        #pragma unroll
        for (int j = 0; j < 8; j++) acc[i][j] = 0.f;

    float4 av = *(const float4*)Aptr;
    float4 bv = *(const float4*)Bptr;
    As[0][a_col+0][a_row] = av.x; As[0][a_col+1][a_row] = av.y;
    As[0][a_col+2][a_row] = av.z; As[0][a_col+3][a_row] = av.w;
    *(float4*)&Bs[0][b_row][b_col] = bv;
    __syncthreads();

    const int nk = EH >> 3;  // 128
    for (int kt = 0; kt < nk; kt++) {
        const int cur = kt & 1;
        float4 na, nb;
        if (kt + 1 < nk) {
            na = *(const float4*)(Aptr + (kt + 1) * 8);
            nb = *(const float4*)(Bptr + (size_t)(kt + 1) * 8 * LAT);
        }
        #pragma unroll
        for (int kk = 0; kk < 8; kk++) {
            float4 a0 = *(const float4*)&As[cur][kk][ty*8];
            float4 a1 = *(const float4*)&As[cur][kk][ty*8 + 4];
            float4 b0 = *(const float4*)&Bs[cur][kk][tx*8];
            float4 b1 = *(const float4*)&Bs[cur][kk][tx*8 + 4];
            float arr[8] = {a0.x,a0.y,a0.z,a0.w,a1.x,a1.y,a1.z,a1.w};
            float brr[8] = {b0.x,b0.y,b0.z,b0.w,b1.x,b1.y,b1.z,b1.w};
            #pragma unroll
            for (int i = 0; i < 8; i++)
                #pragma unroll
                for (int j = 0; j < 8; j++)
                    acc[i][j] += arr[i]*brr[j];
        }
        if (kt + 1 < nk) {
            const int nxt = cur ^ 1;
            As[nxt][a_col+0][a_row] = na.x; As[nxt][a_col+1][a_row] = na.y;
            As[nxt][a_col+2][a_row] = na.z; As[nxt][a_col+3][a_row] = na.w;
            *(float4*)&Bs[nxt][b_row][b_col] = nb;
            __syncthreads();
        }
    }
    #pragma unroll
    for (int i = 0; i < 8; i++) {
        int r = r0 + ty*8 + i;
        if (r < rend) {
            size_t base = (size_t)r * LAT + bx*128 + tx*8;
            #pragma unroll
            for (int j = 0; j < 8; j += 4) {
                float4 v; v.x = acc[i][j]; v.y = acc[i][j+1]; v.z = acc[i][j+2]; v.w = acc[i][j+3];
                *(float4*)&g_contrib[base + j] = v;
            }
        }
    }
}

// ---------------- combine: eout[n] = sum_k w_k * contrib[pos(n,k)] (deterministic) ----------------
__global__ void k_combine()
{
    int n = blockIdx.x;
    int c = threadIdx.x;   // 256 threads == LAT
    float acc = 0.f;
    #pragma unroll
    for (int k = 0; k < 4; k++) {
        int pos = g_assign_pos[n*4 + k];
        float w = g_topw[n*4 + k];
        acc += w * g_contrib[(size_t)pos * LAT + c];
    }
    g_eout[(size_t)n * LAT + c] = acc;
}

// ---------------- shared activation ----------------
__global__ void k_shact(const float* __restrict__ svth)
{
    size_t idx = (size_t)blockIdx.x * 256 + threadIdx.x;
    int n = (int)(idx >> 11);
    int j = (int)(idx & 2047);
    float gte = g_SY[(size_t)n * (2*SH) + j];
    float lin = g_SY[(size_t)n * (2*SH) + SH + j];
    float v = svth[j];
    g_ACTS[idx] = (gte >= v ? v : 0.f) * lin;
}

// ---------------- shared gate: sigmoid(hnorm @ gate_w) ----------------
__global__ void k_gate(const float* __restrict__ gw)
{
    int n = blockIdx.x;
    float s = 0.f;
    for (int i = threadIdx.x; i < D_; i += 256)
        s += g_hnorm[(size_t)n * D_ + i] * gw[i];
    __shared__ float red[256];
    red[threadIdx.x] = s; __syncthreads();
    for (int st = 128; st; st >>= 1) {
        if (threadIdx.x < st) red[threadIdx.x] += red[threadIdx.x + st];
        __syncthreads();
    }
    if (threadIdx.x == 0) g_gate[n] = 1.f / (1.f + expf(-red[0]));
}

// ---------------- lb loss scalar ----------------
__global__ void k_lb(float* out, int out_size)
{
    if (threadIdx.x == 0 && out_size > NTOK * D_) {
        float s = 0.f;
        for (int e = 0; e < NEXP; e++) {
            float f = (float)g_count[e] / (float)NTOK;
            float P = g_Psum[e] / (float)NTOK;
            s += f * P;
        }
        out[NTOK * D_] = (float)NEXP * s * 1e-4f;
    }
}

// ---------------- launch ----------------
extern "C" void kernel_launch(void* const* d_in, const int* in_sizes, int n_in,
                              void* d_out, int out_size)
{
    const float* h          = (const float*)d_in[0];
    const float* norm_w     = (const float*)d_in[1];
    const float* latent_dw  = (const float*)d_in[2];
    const float* latent_uw  = (const float*)d_in[3];
    const float* router_w   = (const float*)d_in[4];
    const float* router_b   = (const float*)d_in[5];
    const float* ew1        = (const float*)d_in[6];
    const float* evth       = (const float*)d_in[7];
    const float* ew2        = (const float*)d_in[8];
    const float* sw1        = (const float*)d_in[9];
    const float* svth       = (const float*)d_in[10];
    const float* sw2        = (const float*)d_in[11];
    const float* sgw        = (const float*)d_in[12];
    const float* opw        = (const float*)d_in[13];
    float* out = (float*)d_out;

    void *p_count, *p_hnorm, *p_latent, *p_eout, *p_ACTS, *p_X, *p_SY, *p_gate;
    cudaGetSymbolAddress(&p_count,  g_count);
    cudaGetSymbolAddress(&p_hnorm,  g_hnorm);
    cudaGetSymbolAddress(&p_latent, g_latent);
    cudaGetSymbolAddress(&p_eout,   g_eout);
    cudaGetSymbolAddress(&p_ACTS,   g_ACTS);
    cudaGetSymbolAddress(&p_X,      g_X);
    cudaGetSymbolAddress(&p_SY,     g_SY);
    cudaGetSymbolAddress(&p_gate,   g_gate);

    cudaMemsetAsync(p_count, 0, NEXP * sizeof(int));

    // normalization + routing
    k_rmsnorm<<<NTOK, 256>>>(h, norm_w);
    k_router <<<NTOK/32, 256>>>(router_w, router_b);
    k_topk   <<<NTOK/8, 256>>>();
    k_colsum <<<NEXP, 256>>>();
    k_offsets<<<1, 32>>>();
    k_assign <<<NTOK/256, 256>>>();

    // latent projection: latent = hnorm @ latent_down   (8192 x 256, K=2048)
    k_sgemm<<<dim3(LAT/128, NTOK/128), 256>>>((const float*)p_hnorm, latent_dw,
                                              (float*)p_latent, NTOK, LAT, D_,
                                              nullptr, nullptr, 0);

    // experts (grouped, sparse)
    k_gemm_exp1<<<dim3(MAXTILES, (2*EH)/128), 256>>>((const float*)p_latent, ew1);
    k_expact   <<<(int)(((size_t)ATOT*EH)/256), 256>>>(evth);
    k_gemm_exp2<<<dim3(MAXTILES, LAT/128), 256>>>(ew2);
    k_combine  <<<NTOK, LAT>>>();

    // routed: X = eout @ latent_up   (8192 x 2048, K=256)
    k_sgemm<<<dim3(D_/128, NTOK/128), 256>>>((const float*)p_eout, latent_uw,
                                             (float*)p_X, NTOK, D_, LAT,
                                             nullptr, nullptr, 0);

    // shared expert
    k_sgemm<<<dim3((2*SH)/128, NTOK/128), 256>>>((const float*)p_hnorm, sw1,
                                                 (float*)p_SY, NTOK, 2*SH, D_,
                                                 nullptr, nullptr, 0);
    k_shact<<<(int)(((size_t)NTOK*SH)/256), 256>>>(svth);
    k_gate <<<NTOK, 256>>>(sgw);
    // X += (ACTS @ shared_w2) * gate[row]
    k_sgemm<<<dim3(D_/128, NTOK/128), 256>>>((const float*)p_ACTS, sw2,
                                             (float*)p_X, NTOK, D_, SH,
                                             (const float*)p_gate, nullptr, 1);

    // out = h + X @ out_proj
    k_sgemm<<<dim3(D_/128, NTOK/128), 256>>>((const float*)p_X, opw,
                                             out, NTOK, D_, D_,
                                             nullptr, h, 0);

    k_lb<<<1, 32>>>(out, out_size);
}

// round 2
// speedup vs baseline: 3.4572x; 3.4572x over previous
#include <cuda_runtime.h>
#include <cuda_bf16.h>
#include <mma.h>
#include <math.h>

using namespace nvcuda;

// ---------------- problem constants ----------------
#define D_      2048
#define NTOK    8192        // S*B
#define LAT     256
#define NEXP    32
#define TOPK    4
#define EH      1024
#define SH      2048
#define ATOT    (NTOK*TOPK)            // 32768 real assignments
#define ATOTP   (ATOT + NEXP*128)      // padded to full 128-row tiles: 36864
#define MAXTILES (ATOTP/128)           // 288

// ---------------- device scratch ----------------
__device__ float g_hnorm [NTOK*D_];
__device__ __nv_bfloat16 g_hnorm_bf[NTOK*D_];
__device__ float g_scores[NTOK*NEXP];
__device__ float g_latent[NTOK*LAT];
__device__ __nv_bfloat16 g_latent_bf[NTOK*LAT];
__device__ float g_Y     [(size_t)ATOTP*2*EH];
__device__ __nv_bfloat16 g_ACTb[(size_t)ATOTP*EH];
__device__ float g_contrib[(size_t)ATOTP*LAT];
__device__ __nv_bfloat16 g_eout_bf[NTOK*LAT];
__device__ float g_SY    [(size_t)NTOK*2*SH];
__device__ __nv_bfloat16 g_ACTSb[(size_t)NTOK*SH];
__device__ float g_X     [(size_t)NTOK*D_];
__device__ __nv_bfloat16 g_Xb[(size_t)NTOK*D_];
__device__ float g_gate  [NTOK];
__device__ float g_Psum  [NEXP];
__device__ int   g_count [NEXP];
__device__ int   g_off   [NEXP+1];
__device__ int   g_cursor[NEXP];
__device__ int   g_tile_e[MAXTILES];
__device__ int   g_tile_r[MAXTILES];
__device__ int   g_ntiles;
__device__ int   g_assign_tok[ATOTP];
__device__ int   g_assign_exp[ATOTP];
__device__ int   g_assign_pos[ATOT];
__device__ int   g_topi[ATOT];
__device__ float g_topw[ATOT];

// bf16 weight copies (converted each call)
__device__ __nv_bfloat16 g_ldw_bf[(size_t)D_*LAT];
__device__ __nv_bfloat16 g_luw_bf[(size_t)LAT*D_];
__device__ __nv_bfloat16 g_ew1_bf[(size_t)NEXP*LAT*2*EH];
__device__ __nv_bfloat16 g_ew2_bf[(size_t)NEXP*EH*LAT];
__device__ __nv_bfloat16 g_sw1_bf[(size_t)D_*2*SH];
__device__ __nv_bfloat16 g_sw2_bf[(size_t)SH*D_];
__device__ __nv_bfloat16 g_opw_bf[(size_t)D_*D_];

// ---------------- fp32 -> bf16 convert ----------------
__global__ void k_cvt(const float* __restrict__ a, __nv_bfloat16* __restrict__ b, long n)
{
    long i = ((long)blockIdx.x*256 + threadIdx.x) * 8;
    if (i >= n) return;
    float4 v0 = *(const float4*)(a + i);
    float4 v1 = *(const float4*)(a + i + 4);
    __nv_bfloat162 o[4];
    o[0] = __floats2bfloat162_rn(v0.x, v0.y);
    o[1] = __floats2bfloat162_rn(v0.z, v0.w);
    o[2] = __floats2bfloat162_rn(v1.x, v1.y);
    o[3] = __floats2bfloat162_rn(v1.z, v1.w);
    *(uint4*)(b + i) = *(uint4*)o;
}

// ---------------- rmsnorm (writes fp32 + bf16) ----------------
__global__ void k_rmsnorm(const float* __restrict__ h, const float* __restrict__ w)
{
    int n = blockIdx.x;
    const float4* hp = (const float4*)(h + (size_t)n * D_);
    float ss = 0.f;
    for (int i = threadIdx.x; i < D_/4; i += 256) {
        float4 v = hp[i];
        ss += v.x*v.x + v.y*v.y + v.z*v.z + v.w*v.w;
    }
    __shared__ float red[256];
    red[threadIdx.x] = ss; __syncthreads();
    for (int s = 128; s; s >>= 1) {
        if (threadIdx.x < s) red[threadIdx.x] += red[threadIdx.x + s];
        __syncthreads();
    }
    float rs = rsqrtf(red[0] * (1.f / D_) + 1e-6f);
    float4* op = (float4*)(g_hnorm + (size_t)n * D_);
    __nv_bfloat162* bp = (__nv_bfloat162*)(g_hnorm_bf + (size_t)n * D_);
    const float4* wp = (const float4*)w;
    for (int i = threadIdx.x; i < D_/4; i += 256) {
        float4 v = hp[i], wv = wp[i];
        v.x *= rs*wv.x; v.y *= rs*wv.y; v.z *= rs*wv.z; v.w *= rs*wv.w;
        op[i] = v;
        bp[i*2+0] = __floats2bfloat162_rn(v.x, v.y);
        bp[i*2+1] = __floats2bfloat162_rn(v.z, v.w);
    }
}

// ---------------- router (fp32, exact) ----------------
__global__ void k_router(const float* __restrict__ rw, const float* __restrict__ rb)
{
    __shared__ float hs[32][64];
    __shared__ float ws[64][32];
    int n0 = blockIdx.x * 32;
    int tid = threadIdx.x;
    int e  = tid & 31;
    int tr = tid >> 5;
    float acc[4] = {0.f, 0.f, 0.f, 0.f};
    for (int k0 = 0; k0 < D_; k0 += 64) {
        #pragma unroll
        for (int i = 0; i < 8; i++) {
            int lin = tid + i*256;
            int t = lin >> 6, k = lin & 63;
            hs[t][k] = g_hnorm[(size_t)(n0 + t)*D_ + k0 + k];
            int kw = lin >> 5, ew = lin & 31;
            ws[kw][ew] = rw[(size_t)(k0 + kw)*NEXP + ew];
        }
        __syncthreads();
        #pragma unroll
        for (int kk = 0; kk < 64; kk++) {
            #pragma unroll
            for (int i = 0; i < 4; i++)
                acc[i] += hs[tr + 8*i][kk] * ws[kk][e];
        }
        __syncthreads();
    }
    float bias = rb[e];
    #pragma unroll
    for (int i = 0; i < 4; i++) {
        int t = tr + 8*i;
        float v = acc[i] + bias;
        g_scores[(n0 + t)*NEXP + e] = 1.f / (1.f + expf(-v));
    }
}

// ---------------- top-4 per token ----------------
__global__ void k_topk()
{
    int warp = threadIdx.x >> 5;
    int lane = threadIdx.x & 31;
    int n = blockIdx.x * 8 + warp;
    float s = g_scores[n*NEXP + lane];
    float topv[4]; int topi[4];
    #pragma unroll
    for (int k = 0; k < 4; k++) {
        float v = s; int bi = lane;
        #pragma unroll
        for (int off = 16; off; off >>= 1) {
            float v2 = __shfl_xor_sync(0xffffffffu, v, off);
            int   i2 = __shfl_xor_sync(0xffffffffu, bi, off);
            if (v2 > v || (v2 == v && i2 < bi)) { v = v2; bi = i2; }
        }
        topv[k] = v; topi[k] = bi;
        if (lane == bi) s = -1e30f;
    }
    if (lane == 0) {
        float sum = topv[0] + topv[1] + topv[2] + topv[3];
        float inv = 1.f / (sum + 1e-8f);
        #pragma unroll
        for (int k = 0; k < 4; k++) {
            g_topw[n*4 + k] = topv[k] * inv;
            g_topi[n*4 + k] = topi[k];
            atomicAdd(&g_count[topi[k]], 1);
        }
    }
}

// ---------------- P = column sums ----------------
__global__ void k_colsum()
{
    int e = blockIdx.x;
    float s = 0.f;
    for (int n = threadIdx.x; n < NTOK; n += 256) s += g_scores[n*NEXP + e];
    __shared__ float red[256];
    red[threadIdx.x] = s; __syncthreads();
    for (int st = 128; st; st >>= 1) {
        if (threadIdx.x < st) red[threadIdx.x] += red[threadIdx.x + st];
        __syncthreads();
    }
    if (threadIdx.x == 0) g_Psum[e] = red[0];
}

// ---------------- offsets padded to 128-row tiles ----------------
__global__ void k_offsets()
{
    if (threadIdx.x == 0) {
        int acc = 0, nt = 0;
        for (int e = 0; e < NEXP; e++) {
            g_off[e] = acc; g_cursor[e] = acc;
            int ne = g_count[e];
            int nep = (ne + 127) & ~127;
            for (int r = 0; r < nep; r += 128) {
                g_tile_e[nt] = e; g_tile_r[nt] = acc + r; nt++;
            }
            acc += nep;
        }
        g_off[NEXP] = acc;
        g_ntiles = nt;
    }
}

// ---------------- scatter assignments ----------------
__global__ void k_assign()
{
    int n = blockIdx.x * 256 + threadIdx.x;
    if (n >= NTOK) return;
    #pragma unroll
    for (int k = 0; k < 4; k++) {
        int e = g_topi[n*4 + k];
        int pos = atomicAdd(&g_cursor[e], 1);
        g_assign_tok[pos] = n;
        g_assign_exp[pos] = e;
        g_assign_pos[n*4 + k] = pos;
    }
}

// ================= dense bf16 wmma GEMM: C[M,N] = A[M,K]@B[K,N] =================
// 128x128x32 tile, 256 threads (8 warps, 2x4 warp grid, 64x32 per warp)
__launch_bounds__(256)
__global__ void k_wgemm(const __nv_bfloat16* __restrict__ A,
                        const __nv_bfloat16* __restrict__ B,
                        float* __restrict__ C, int M, int N, int K,
                        const float* __restrict__ resid, int accumulate)
{
    __shared__ __align__(16) __nv_bfloat16 As[2][128][48];
    __shared__ __align__(16) __nv_bfloat16 Bs[2][32][136];
    const int tid = threadIdx.x;
    const int bx = blockIdx.x, by = blockIdx.y;
    const int w  = tid >> 5;
    const int wm = w >> 2, wn = w & 3;
    const int ar = tid >> 2,  ac = (tid & 3)  * 8;
    const int br = tid >> 4,  bc = (tid & 15) * 8;

    const __nv_bfloat16* Ap = A + (size_t)(by*128 + ar) * K + ac;
    const __nv_bfloat16* Bp = B + (size_t)br * N + bx*128 + bc;

    wmma::fragment<wmma::accumulator, 16, 16, 16, float> acc[4][2];
    #pragma unroll
    for (int i = 0; i < 4; i++)
        #pragma unroll
        for (int j = 0; j < 2; j++) wmma::fill_fragment(acc[i][j], 0.f);

    uint4 pa0 = *(const uint4*)(Ap);
    uint4 pa1 = *(const uint4*)(Ap + (size_t)64*K);
    uint4 pb0 = *(const uint4*)(Bp);
    uint4 pb1 = *(const uint4*)(Bp + (size_t)16*N);
    *(uint4*)&As[0][ar   ][ac] = pa0;
    *(uint4*)&As[0][ar+64][ac] = pa1;
    *(uint4*)&Bs[0][br   ][bc] = pb0;
    *(uint4*)&Bs[0][br+16][bc] = pb1;
    __syncthreads();

    const int nk = K >> 5;
    for (int kt = 0; kt < nk; kt++) {
        const int cur = kt & 1;
        if (kt + 1 < nk) {
            const __nv_bfloat16* Ap2 = Ap + (kt+1)*32;
            const __nv_bfloat16* Bp2 = Bp + (size_t)(kt+1)*32*N;
            pa0 = *(const uint4*)(Ap2);
            pa1 = *(const uint4*)(Ap2 + (size_t)64*K);
            pb0 = *(const uint4*)(Bp2);
            pb1 = *(const uint4*)(Bp2 + (size_t)16*N);
        }
        #pragma unroll
        for (int kk = 0; kk < 2; kk++) {
            wmma::fragment<wmma::matrix_a, 16,16,16, __nv_bfloat16, wmma::row_major> af[4];
            wmma::fragment<wmma::matrix_b, 16,16,16, __nv_bfloat16, wmma::row_major> bf[2];
            #pragma unroll
            for (int i = 0; i < 4; i++)
                wmma::load_matrix_sync(af[i], &As[cur][wm*64 + i*16][kk*16], 48);
            #pragma unroll
            for (int j = 0; j < 2; j++)
                wmma::load_matrix_sync(bf[j], &Bs[cur][kk*16][wn*32 + j*16], 136);
            #pragma unroll
            for (int i = 0; i < 4; i++)
                #pragma unroll
                for (int j = 0; j < 2; j++)
                    wmma::mma_sync(acc[i][j], af[i], bf[j], acc[i][j]);
        }
        if (kt + 1 < nk) {
            const int nxt = cur ^ 1;
            *(uint4*)&As[nxt][ar   ][ac] = pa0;
            *(uint4*)&As[nxt][ar+64][ac] = pa1;
            *(uint4*)&Bs[nxt][br   ][bc] = pb0;
            *(uint4*)&Bs[nxt][br+16][bc] = pb1;
            __syncthreads();
        }
    }

    #pragma unroll
    for (int i = 0; i < 4; i++)
        #pragma unroll
        for (int j = 0; j < 2; j++) {
            int r = by*128 + wm*64 + i*16;
            int c = bx*128 + wn*32 + j*16;
            float* Cp = C + (size_t)r * N + c;
            if (resid) {
                wmma::fragment<wmma::accumulator,16,16,16,float> rf;
                wmma::load_matrix_sync(rf, resid + (size_t)r*N + c, N, wmma::mem_row_major);
                #pragma unroll
                for (int t = 0; t < rf.num_elements; t++) acc[i][j].x[t] += rf.x[t];
            }
            if (accumulate) {
                wmma::fragment<wmma::accumulator,16,16,16,float> cf;
                wmma::load_matrix_sync(cf, Cp, N, wmma::mem_row_major);
                #pragma unroll
                for (int t = 0; t < cf.num_elements; t++) acc[i][j].x[t] += cf.x[t];
            }
            wmma::store_matrix_sync(Cp, acc[i][j], N, wmma::mem_row_major);
        }
}

// ============ grouped bf16 wmma GEMM (per-expert tiles, optional row gather) ============
__launch_bounds__(256)
__global__ void k_wgemm_g(const __nv_bfloat16* __restrict__ A, int lda,
                          const int* __restrict__ gather,
                          const __nv_bfloat16* __restrict__ Bbase, size_t bstride,
                          float* __restrict__ C, int N, int K)
{
    const int bt = blockIdx.x;
    if (bt >= g_ntiles) return;
    const int e  = g_tile_e[bt];
    const int r0 = g_tile_r[bt];
    const int bx = blockIdx.y;

    __shared__ __align__(16) __nv_bfloat16 As[2][128][48];
    __shared__ __align__(16) __nv_bfloat16 Bs[2][32][136];
    const int tid = threadIdx.x;
    const int w  = tid >> 5;
    const int wm = w >> 2, wn = w & 3;
    const int ar = tid >> 2,  ac = (tid & 3)  * 8;
    const int br = tid >> 4,  bc = (tid & 15) * 8;

    int row0 = gather ? gather[r0 + ar]      : (r0 + ar);
    int row1 = gather ? gather[r0 + ar + 64] : (r0 + ar + 64);
    const __nv_bfloat16* Ap0 = A + (size_t)row0 * lda + ac;
    const __nv_bfloat16* Ap1 = A + (size_t)row1 * lda + ac;
    const __nv_bfloat16* Bp  = Bbase + (size_t)e * bstride + (size_t)br * N + bx*128 + bc;

    wmma::fragment<wmma::accumulator, 16, 16, 16, float> acc[4][2];
    #pragma unroll
    for (int i = 0; i < 4; i++)
        #pragma unroll
        for (int j = 0; j < 2; j++) wmma::fill_fragment(acc[i][j], 0.f);

    uint4 pa0 = *(const uint4*)(Ap0);
    uint4 pa1 = *(const uint4*)(Ap1);
    uint4 pb0 = *(const uint4*)(Bp);
    uint4 pb1 = *(const uint4*)(Bp + (size_t)16*N);
    *(uint4*)&As[0][ar   ][ac] = pa0;
    *(uint4*)&As[0][ar+64][ac] = pa1;
    *(uint4*)&Bs[0][br   ][bc] = pb0;
    *(uint4*)&Bs[0][br+16][bc] = pb1;
    __syncthreads();

    const int nk = K >> 5;
    for (int kt = 0; kt < nk; kt++) {
        const int cur = kt & 1;
        if (kt + 1 < nk) {
            pa0 = *(const uint4*)(Ap0 + (kt+1)*32);
            pa1 = *(const uint4*)(Ap1 + (kt+1)*32);
            pb0 = *(const uint4*)(Bp + (size_t)(kt+1)*32*N);
            pb1 = *(const uint4*)(Bp + (size_t)(kt+1)*32*N + (size_t)16*N);
        }
        #pragma unroll
        for (int kk = 0; kk < 2; kk++) {
            wmma::fragment<wmma::matrix_a, 16,16,16, __nv_bfloat16, wmma::row_major> af[4];
            wmma::fragment<wmma::matrix_b, 16,16,16, __nv_bfloat16, wmma::row_major> bf[2];
            #pragma unroll
            for (int i = 0; i < 4; i++)
                wmma::load_matrix_sync(af[i], &As[cur][wm*64 + i*16][kk*16], 48);
            #pragma unroll
            for (int j = 0; j < 2; j++)
                wmma::load_matrix_sync(bf[j], &Bs[cur][kk*16][wn*32 + j*16], 136);
            #pragma unroll
            for (int i = 0; i < 4; i++)
                #pragma unroll
                for (int j = 0; j < 2; j++)
                    wmma::mma_sync(acc[i][j], af[i], bf[j], acc[i][j]);
        }
        if (kt + 1 < nk) {
            const int nxt = cur ^ 1;
            *(uint4*)&As[nxt][ar   ][ac] = pa0;
            *(uint4*)&As[nxt][ar+64][ac] = pa1;
            *(uint4*)&Bs[nxt][br   ][bc] = pb0;
            *(uint4*)&Bs[nxt][br+16][bc] = pb1;
            __syncthreads();
        }
    }

    #pragma unroll
    for (int i = 0; i < 4; i++)
        #pragma unroll
        for (int j = 0; j < 2; j++) {
            int r = r0 + wm*64 + i*16;
            int c = bx*128 + wn*32 + j*16;
            wmma::store_matrix_sync(C + (size_t)r * N + c, acc[i][j], N, wmma::mem_row_major);
        }
}

// ---------------- expert activation: ACT = spike(gate,vth_e)*lin (bf16 out) ----------------
__global__ void k_expact(const float* __restrict__ vth)
{
    size_t idx = (size_t)blockIdx.x * 256 + threadIdx.x;
    int a = (int)(idx >> 10);
    int j = (int)(idx & 1023);
    int e = g_assign_exp[a];
    float gte = g_Y[(size_t)a * (2*EH) + j];
    float lin = g_Y[(size_t)a * (2*EH) + EH + j];
    float v = vth[e*EH + j];
    g_ACTb[idx] = __float2bfloat16((gte >= v ? v : 0.f) * lin);
}

// ---------------- combine top-k contributions (deterministic gather) ----------------
__global__ void k_combine()
{
    int n = blockIdx.x;
    int c = threadIdx.x;   // LAT threads
    float acc = 0.f;
    #pragma unroll
    for (int k = 0; k < 4; k++) {
        int pos = g_assign_pos[n*4 + k];
        float w = g_topw[n*4 + k];
        acc += w * g_contrib[(size_t)pos * LAT + c];
    }
    g_eout_bf[(size_t)n * LAT + c] = __float2bfloat16(acc);
}

// ---------------- shared activation (gate folded in, bf16 out) ----------------
__global__ void k_shact(const float* __restrict__ svth)
{
    size_t idx = (size_t)blockIdx.x * 256 + threadIdx.x;
    int n = (int)(idx >> 11);
    int j = (int)(idx & 2047);
    float gte = g_SY[(size_t)n * (2*SH) + j];
    float lin = g_SY[(size_t)n * (2*SH) + SH + j];
    float v = svth[j];
    g_ACTSb[idx] = __float2bfloat16((gte >= v ? v : 0.f) * lin * g_gate[n]);
}

// ---------------- shared gate ----------------
__global__ void k_gate(const float* __restrict__ gw)
{
    int n = blockIdx.x;
    float s = 0.f;
    for (int i = threadIdx.x; i < D_; i += 256)
        s += g_hnorm[(size_t)n * D_ + i] * gw[i];
    __shared__ float red[256];
    red[threadIdx.x] = s; __syncthreads();
    for (int st = 128; st; st >>= 1) {
        if (threadIdx.x < st) red[threadIdx.x] += red[threadIdx.x + st];
        __syncthreads();
    }
    if (threadIdx.x == 0) g_gate[n] = 1.f / (1.f + expf(-red[0]));
}

// ---------------- lb loss ----------------
__global__ void k_lb(float* out, int out_size)
{
    if (threadIdx.x == 0 && out_size > NTOK * D_) {
        float s = 0.f;
        for (int e = 0; e < NEXP; e++) {
            float f = (float)g_count[e] / (float)NTOK;
            float P = g_Psum[e] / (float)NTOK;
            s += f * P;
        }
        out[NTOK * D_] = (float)NEXP * s * 1e-4f;
    }
}

// ---------------- launch ----------------
static inline int cvtGrid(long n) { return (int)((n/8 + 255) / 256); }

extern "C" void kernel_launch(void* const* d_in, const int* in_sizes, int n_in,
                              void* d_out, int out_size)
{
    const float* h         = (const float*)d_in[0];
    const float* norm_w    = (const float*)d_in[1];
    const float* latent_dw = (const float*)d_in[2];
    const float* latent_uw = (const float*)d_in[3];
    const float* router_w  = (const float*)d_in[4];
    const float* router_b  = (const float*)d_in[5];
    const float* ew1       = (const float*)d_in[6];
    const float* evth      = (const float*)d_in[7];
    const float* ew2       = (const float*)d_in[8];
    const float* sw1       = (const float*)d_in[9];
    const float* svth      = (const float*)d_in[10];
    const float* sw2       = (const float*)d_in[11];
    const float* sgw       = (const float*)d_in[12];
    const float* opw       = (const float*)d_in[13];
    float* out = (float*)d_out;

    void *p_count, *p_atok, *p_aexp;
    void *p_hnormbf, *p_latent, *p_latentbf, *p_Y, *p_ACTb, *p_contrib;
    void *p_eoutbf, *p_SY, *p_ACTSb, *p_X, *p_Xb;
    void *p_ldw, *p_luw, *p_ew1, *p_ew2, *p_sw1, *p_sw2, *p_opw;
    cudaGetSymbolAddress(&p_count,   g_count);
    cudaGetSymbolAddress(&p_atok,    g_assign_tok);
    cudaGetSymbolAddress(&p_aexp,    g_assign_exp);
    cudaGetSymbolAddress(&p_hnormbf, g_hnorm_bf);
    cudaGetSymbolAddress(&p_latent,  g_latent);
    cudaGetSymbolAddress(&p_latentbf,g_latent_bf);
    cudaGetSymbolAddress(&p_Y,       g_Y);
    cudaGetSymbolAddress(&p_ACTb,    g_ACTb);
    cudaGetSymbolAddress(&p_contrib, g_contrib);
    cudaGetSymbolAddress(&p_eoutbf,  g_eout_bf);
    cudaGetSymbolAddress(&p_SY,      g_SY);
    cudaGetSymbolAddress(&p_ACTSb,   g_ACTSb);
    cudaGetSymbolAddress(&p_X,       g_X);
    cudaGetSymbolAddress(&p_Xb,      g_Xb);
    cudaGetSymbolAddress(&p_ldw,     g_ldw_bf);
    cudaGetSymbolAddress(&p_luw,     g_luw_bf);
    cudaGetSymbolAddress(&p_ew1,     g_ew1_bf);
    cudaGetSymbolAddress(&p_ew2,     g_ew2_bf);
    cudaGetSymbolAddress(&p_sw1,     g_sw1_bf);
    cudaGetSymbolAddress(&p_sw2,     g_sw2_bf);
    cudaGetSymbolAddress(&p_opw,     g_opw_bf);

    cudaMemsetAsync(p_count, 0, NEXP * sizeof(int));
    cudaMemsetAsync(p_atok,  0, ATOTP * sizeof(int));
    cudaMemsetAsync(p_aexp,  0, ATOTP * sizeof(int));

    // weight conversions (independent of data path)
    k_cvt<<<cvtGrid((long)D_*LAT), 256>>>(latent_dw, (__nv_bfloat16*)p_ldw, (long)D_*LAT);
    k_cvt<<<cvtGrid((long)LAT*D_), 256>>>(latent_uw, (__nv_bfloat16*)p_luw, (long)LAT*D_);
    k_cvt<<<cvtGrid((long)NEXP*LAT*2*EH), 256>>>(ew1, (__nv_bfloat16*)p_ew1, (long)NEXP*LAT*2*EH);
    k_cvt<<<cvtGrid((long)NEXP*EH*LAT), 256>>>(ew2, (__nv_bfloat16*)p_ew2, (long)NEXP*EH*LAT);
    k_cvt<<<cvtGrid((long)D_*2*SH), 256>>>(sw1, (__nv_bfloat16*)p_sw1, (long)D_*2*SH);
    k_cvt<<<cvtGrid((long)SH*D_), 256>>>(sw2, (__nv_bfloat16*)p_sw2, (long)SH*D_);
    k_cvt<<<cvtGrid((long)D_*D_), 256>>>(opw, (__nv_bfloat16*)p_opw, (long)D_*D_);

    // normalization + routing (fp32)
    k_rmsnorm<<<NTOK, 256>>>(h, norm_w);
    k_router <<<NTOK/32, 256>>>(router_w, router_b);
    k_topk   <<<NTOK/8, 256>>>();
    k_colsum <<<NEXP, 256>>>();
    k_offsets<<<1, 32>>>();
    k_assign <<<NTOK/256, 256>>>();

    // latent = hnorm @ latent_down   (8192 x 256, K=2048)
    k_wgemm<<<dim3(LAT/128, NTOK/128), 256>>>((const __nv_bfloat16*)p_hnormbf,
        (const __nv_bfloat16*)p_ldw, (float*)p_latent, NTOK, LAT, D_, nullptr, 0);
    k_cvt<<<cvtGrid((long)NTOK*LAT), 256>>>((const float*)p_latent,
        (__nv_bfloat16*)p_latentbf, (long)NTOK*LAT);

    // experts (grouped, padded tiles)
    k_wgemm_g<<<dim3(MAXTILES, (2*EH)/128), 256>>>((const __nv_bfloat16*)p_latentbf, LAT,
        (const int*)p_atok, (const __nv_bfloat16*)p_ew1, (size_t)LAT*2*EH,
        (float*)p_Y, 2*EH, LAT);
    k_expact<<<(int)(((size_t)ATOTP*EH)/256), 256>>>(evth);
    k_wgemm_g<<<dim3(MAXTILES, LAT/128), 256>>>((const __nv_bfloat16*)p_ACTb, EH,
        nullptr, (const __nv_bfloat16*)p_ew2, (size_t)EH*LAT,
        (float*)p_contrib, LAT, EH);
    k_combine<<<NTOK, LAT>>>();

    // routed: X = eout @ latent_up   (8192 x 2048, K=256)
    k_wgemm<<<dim3(D_/128, NTOK/128), 256>>>((const __nv_bfloat16*)p_eoutbf,
        (const __nv_bfloat16*)p_luw, (float*)p_X, NTOK, D_, LAT, nullptr, 0);

    // shared expert
    k_wgemm<<<dim3((2*SH)/128, NTOK/128), 256>>>((const __nv_bfloat16*)p_hnormbf,
        (const __nv_bfloat16*)p_sw1, (float*)p_SY, NTOK, 2*SH, D_, nullptr, 0);
    k_gate <<<NTOK, 256>>>(sgw);
    k_shact<<<(int)(((size_t)NTOK*SH)/256), 256>>>(svth);
    // X += ACTS(gated) @ shared_w2
    k_wgemm<<<dim3(D_/128, NTOK/128), 256>>>((const __nv_bfloat16*)p_ACTSb,
        (const __nv_bfloat16*)p_sw2, (float*)p_X, NTOK, D_, SH, nullptr, 1);
    k_cvt<<<cvtGrid((long)NTOK*D_), 256>>>((const float*)p_X,
        (__nv_bfloat16*)p_Xb, (long)NTOK*D_);

    // out = h + X @ out_proj
    k_wgemm<<<dim3(D_/128, NTOK/128), 256>>>((const __nv_bfloat16*)p_Xb,
        (const __nv_bfloat16*)p_opw, out, NTOK, D_, D_, h, 0);

    k_lb<<<1, 32>>>(out, out_size);
}

// round 4
// speedup vs baseline: 5.8032x; 1.6785x over previous
#include <cuda_runtime.h>
#include <cuda_bf16.h>
#include <math.h>
#include <stdint.h>

// ---------------- problem constants ----------------
#define D_      2048
#define NTOK    8192
#define LAT     256
#define NEXP    32
#define EH      1024
#define SH      2048
#define ATOT    (NTOK*4)
#define ATOTP   (ATOT + NEXP*128)   // 36864
#define MAXTILES (ATOTP/128)        // 288

#define BM 128
#define BN 128
#define BK 32
#define STG 3

// ---------------- device scratch ----------------
__device__ float g_hnorm [NTOK*D_];
__device__ __nv_bfloat16 g_hnorm_bf[NTOK*D_];
__device__ float g_scores[NTOK*NEXP];
__device__ __nv_bfloat16 g_latent_bf[NTOK*LAT];
__device__ __nv_bfloat16 g_ACTb[(size_t)ATOTP*EH];
__device__ float g_contrib[(size_t)ATOTP*LAT];
__device__ __nv_bfloat16 g_eout_bf[NTOK*LAT];
__device__ __nv_bfloat16 g_ACTSb[(size_t)NTOK*SH];
__device__ float g_X  [(size_t)NTOK*D_];
__device__ __nv_bfloat16 g_Xb[(size_t)NTOK*D_];
__device__ float g_gate  [NTOK];
__device__ float g_Psum  [NEXP];
__device__ int   g_count [NEXP];
__device__ int   g_off   [NEXP+1];
__device__ int   g_cursor[NEXP];
__device__ int   g_tile_e[MAXTILES];
__device__ int   g_tile_r[MAXTILES];
__device__ int   g_ntiles;
__device__ int   g_assign_tok[ATOTP];
__device__ int   g_assign_pos[ATOT];
__device__ int   g_topi[ATOT];
__device__ float g_topw[ATOT];

// bf16 weights (same layout as input, converted per call)
__device__ __nv_bfloat16 g_ldw_bf[(size_t)D_*LAT];
__device__ __nv_bfloat16 g_luw_bf[(size_t)LAT*D_];
__device__ __nv_bfloat16 g_ew1_bf[(size_t)NEXP*LAT*2*EH];
__device__ __nv_bfloat16 g_ew2_bf[(size_t)NEXP*EH*LAT];
__device__ __nv_bfloat16 g_sw1_bf[(size_t)D_*2*SH];
__device__ __nv_bfloat16 g_sw2_bf[(size_t)SH*D_];
__device__ __nv_bfloat16 g_opw_bf[(size_t)D_*D_];

// ---------------- asm helpers ----------------
__device__ __forceinline__ uint32_t s2u(const void* p) {
    uint32_t a;
    asm("{ .reg .u64 t; cvta.to.shared.u64 t, %1; cvt.u32.u64 %0, t; }" : "=r"(a) : "l"(p));
    return a;
}
__device__ __forceinline__ void cp16(uint32_t d, const void* s) {
    asm volatile("cp.async.cg.shared.global [%0], [%1], 16;" :: "r"(d), "l"(s));
}
__device__ __forceinline__ void ldmx4(uint32_t* r, uint32_t a) {
    asm volatile("ldmatrix.sync.aligned.m8n8.x4.shared.b16 {%0,%1,%2,%3}, [%4];"
        : "=r"(r[0]), "=r"(r[1]), "=r"(r[2]), "=r"(r[3]) : "r"(a));
}
__device__ __forceinline__ void ldmx4t(uint32_t* r, uint32_t a) {
    asm volatile("ldmatrix.sync.aligned.m8n8.x4.trans.shared.b16 {%0,%1,%2,%3}, [%4];"
        : "=r"(r[0]), "=r"(r[1]), "=r"(r[2]), "=r"(r[3]) : "r"(a));
}
__device__ __forceinline__ void mma16816(float* c, const uint32_t* a, const uint32_t* b) {
    asm volatile("mma.sync.aligned.m16n8k16.row.col.f32.bf16.bf16.f32 "
        "{%0,%1,%2,%3},{%4,%5,%6,%7},{%8,%9},{%0,%1,%2,%3};"
        : "+f"(c[0]), "+f"(c[1]), "+f"(c[2]), "+f"(c[3])
        : "r"(a[0]), "r"(a[1]), "r"(a[2]), "r"(a[3]), "r"(b[0]), "r"(b[1]));
}

// ---------------- elementwise / routing ----------------
__global__ void k_rmsnorm(const float* __restrict__ h, const float* __restrict__ w)
{
    int n = blockIdx.x;
    const float4* hp = (const float4*)(h + (size_t)n * D_);
    float ss = 0.f;
    for (int i = threadIdx.x; i < D_/4; i += 256) {
        float4 v = hp[i];
        ss += v.x*v.x + v.y*v.y + v.z*v.z + v.w*v.w;
    }
    __shared__ float red[256];
    red[threadIdx.x] = ss; __syncthreads();
    for (int s = 128; s; s >>= 1) {
        if (threadIdx.x < s) red[threadIdx.x] += red[threadIdx.x + s];
        __syncthreads();
    }
    float rs = rsqrtf(red[0] * (1.f / D_) + 1e-6f);
    float4* op = (float4*)(g_hnorm + (size_t)n * D_);
    __nv_bfloat162* bp = (__nv_bfloat162*)(g_hnorm_bf + (size_t)n * D_);
    const float4* wp = (const float4*)w;
    for (int i = threadIdx.x; i < D_/4; i += 256) {
        float4 v = hp[i], wv = wp[i];
        v.x *= rs*wv.x; v.y *= rs*wv.y; v.z *= rs*wv.z; v.w *= rs*wv.w;
        op[i] = v;
        bp[i*2+0] = __floats2bfloat162_rn(v.x, v.y);
        bp[i*2+1] = __floats2bfloat162_rn(v.z, v.w);
    }
}

__global__ void k_router(const float* __restrict__ rw, const float* __restrict__ rb)
{
    __shared__ float hs[32][64];
    __shared__ float ws[64][32];
    int n0 = blockIdx.x * 32;
    int tid = threadIdx.x;
    int e = tid & 31, tr = tid >> 5;
    float acc[4] = {0.f,0.f,0.f,0.f};
    for (int k0 = 0; k0 < D_; k0 += 64) {
        #pragma unroll
        for (int i = 0; i < 8; i++) {
            int lin = tid + i*256;
            int t = lin >> 6, k = lin & 63;
            hs[t][k] = g_hnorm[(size_t)(n0 + t)*D_ + k0 + k];
            int kw = lin >> 5, ew = lin & 31;
            ws[kw][ew] = rw[(size_t)(k0 + kw)*NEXP + ew];
        }
        __syncthreads();
        #pragma unroll
        for (int kk = 0; kk < 64; kk++)
            #pragma unroll
            for (int i = 0; i < 4; i++)
                acc[i] += hs[tr + 8*i][kk] * ws[kk][e];
        __syncthreads();
    }
    float bias = rb[e];
    #pragma unroll
    for (int i = 0; i < 4; i++) {
        float v = acc[i] + bias;
        g_scores[(n0 + tr + 8*i)*NEXP + e] = 1.f / (1.f + expf(-v));
    }
}

__global__ void k_topk()
{
    int warp = threadIdx.x >> 5, lane = threadIdx.x & 31;
    int n = blockIdx.x * 8 + warp;
    float s = g_scores[n*NEXP + lane];
    float topv[4]; int topi[4];
    #pragma unroll
    for (int k = 0; k < 4; k++) {
        float v = s; int bi = lane;
        #pragma unroll
        for (int off = 16; off; off >>= 1) {
            float v2 = __shfl_xor_sync(0xffffffffu, v, off);
            int   i2 = __shfl_xor_sync(0xffffffffu, bi, off);
            if (v2 > v || (v2 == v && i2 < bi)) { v = v2; bi = i2; }
        }
        topv[k] = v; topi[k] = bi;
        if (lane == bi) s = -1e30f;
    }
    if (lane == 0) {
        float inv = 1.f / (topv[0]+topv[1]+topv[2]+topv[3] + 1e-8f);
        #pragma unroll
        for (int k = 0; k < 4; k++) {
            g_topw[n*4 + k] = topv[k] * inv;
            g_topi[n*4 + k] = topi[k];
            atomicAdd(&g_count[topi[k]], 1);
        }
    }
}

__global__ void k_colsum()
{
    int e = blockIdx.x;
    float s = 0.f;
    for (int n = threadIdx.x; n < NTOK; n += 256) s += g_scores[n*NEXP + e];
    __shared__ float red[256];
    red[threadIdx.x] = s; __syncthreads();
    for (int st = 128; st; st >>= 1) {
        if (threadIdx.x < st) red[threadIdx.x] += red[threadIdx.x + st];
        __syncthreads();
    }
    if (threadIdx.x == 0) g_Psum[e] = red[0];
}

__global__ void k_offsets()
{
    if (threadIdx.x == 0) {
        int acc = 0, nt = 0;
        for (int e = 0; e < NEXP; e++) {
            g_off[e] = acc; g_cursor[e] = acc;
            int nep = (g_count[e] + 127) & ~127;
            for (int r = 0; r < nep; r += 128) {
                g_tile_e[nt] = e; g_tile_r[nt] = acc + r; nt++;
            }
            acc += nep;
        }
        g_off[NEXP] = acc;
        g_ntiles = nt;
    }
}

__global__ void k_assign()
{
    int n = blockIdx.x * 256 + threadIdx.x;
    if (n >= NTOK) return;
    #pragma unroll
    for (int k = 0; k < 4; k++) {
        int e = g_topi[n*4 + k];
        int pos = atomicAdd(&g_cursor[e], 1);
        g_assign_tok[pos] = n;
        g_assign_pos[n*4 + k] = pos;
    }
}

__global__ void k_gate(const float* __restrict__ gw)
{
    int n = blockIdx.x;
    float s = 0.f;
    for (int i = threadIdx.x; i < D_; i += 256)
        s += g_hnorm[(size_t)n * D_ + i] * gw[i];
    __shared__ float red[256];
    red[threadIdx.x] = s; __syncthreads();
    for (int st = 128; st; st >>= 1) {
        if (threadIdx.x < st) red[threadIdx.x] += red[threadIdx.x + st];
        __syncthreads();
    }
    if (threadIdx.x == 0) g_gate[n] = 1.f / (1.f + expf(-red[0]));
}

__global__ void k_combine()
{
    int n = blockIdx.x, c = threadIdx.x;
    float acc = 0.f;
    #pragma unroll
    for (int k = 0; k < 4; k++) {
        int pos = g_assign_pos[n*4 + k];
        acc += g_topw[n*4 + k] * g_contrib[(size_t)pos * LAT + c];
    }
    g_eout_bf[(size_t)n * LAT + c] = __float2bfloat16(acc);
}

__global__ void k_lb(float* out, int out_size)
{
    if (threadIdx.x == 0 && out_size > NTOK * D_) {
        float s = 0.f;
        for (int e = 0; e < NEXP; e++)
            s += ((float)g_count[e] / NTOK) * (g_Psum[e] / NTOK);
        out[NTOK * D_] = (float)NEXP * s * 1e-4f;
    }
}

__global__ void k_cvt(const float* __restrict__ a, __nv_bfloat16* __restrict__ b, long n)
{
    long i = ((long)blockIdx.x*256 + threadIdx.x) * 8;
    if (i >= n) return;
    float4 v0 = *(const float4*)(a + i);
    float4 v1 = *(const float4*)(a + i + 4);
    __nv_bfloat162 o[4];
    o[0] = __floats2bfloat162_rn(v0.x, v0.y);
    o[1] = __floats2bfloat162_rn(v0.z, v0.w);
    o[2] = __floats2bfloat162_rn(v1.x, v1.y);
    o[3] = __floats2bfloat162_rn(v1.z, v1.w);
    *(uint4*)(b + i) = *(uint4*)o;
}

// =========== mma.sync bf16 GEMM: 128x128 tile, 256 thr, BK=32, 3-stage cp.async ===========
// GROUPED: expert tile list; GATHER: A-row gather via g_assign_tok;
// DUAL: gate tile @n0 + lin tile @n0+HID, emit spike(gate,vth)*lin (*g_gate if GATED) bf16;
// RESID: add fp32 resid; OUTBF: bf16 output (else fp32).
template<bool GROUPED, bool GATHER, bool DUAL, bool GATED, bool RESID, bool OUTBF>
__global__ void __launch_bounds__(256)
k_mm(const __nv_bfloat16* __restrict__ A, int lda,
     const __nv_bfloat16* __restrict__ Bt, long bstride, int ldb,
     void* __restrict__ Cout, int ldc,
     const float* __restrict__ resid, int ldr,
     const float* __restrict__ vth, int HID, int K)
{
    extern __shared__ __align__(16) char smem[];
    __shared__ int s_tok[BM];

    const int tid = threadIdx.x;
    const int lane = tid & 31;
    const int wid = tid >> 5;
    const int wm = wid >> 2, wn = wid & 3;

    int e = 0, r0, n0;
    if (GROUPED) {
        int bt = blockIdx.x;
        if (bt >= g_ntiles) return;
        e = g_tile_e[bt]; r0 = g_tile_r[bt]; n0 = blockIdx.y * BN;
    } else {
        r0 = blockIdx.y * BM; n0 = blockIdx.x * BN;
    }
    const __nv_bfloat16* B = Bt + (GROUPED ? (size_t)e * bstride : 0);

    const uint32_t sb = s2u(smem);
    const uint32_t LDA_B = (BK + 8) * 2;   // 80 B per A row
    const uint32_t LDB_B = (BN + 8) * 2;   // 272 B per B row
    const uint32_t A_ST = BM * LDA_B;      // 10240
    const uint32_t B_ST = BK * LDB_B;      // 8704
    const uint32_t bOff  = STG * A_ST;
    const uint32_t b2Off = STG * (A_ST + B_ST);

    if (GATHER) {
        if (tid < BM) s_tok[tid] = g_assign_tok[r0 + tid];
        __syncthreads();
    }

    const int nk = K / BK;

    auto issue = [&](int kt) {
        int st = kt % STG;
        uint32_t sa  = sb + st * A_ST;
        uint32_t sbb = sb + bOff + st * B_ST;
        #pragma unroll
        for (int i = 0; i < 2; i++) {
            int lin = i*256 + tid;
            int row = lin >> 2, c8 = (lin & 3) * 8;
            const __nv_bfloat16* src = GATHER
                ? A + (size_t)s_tok[row]*lda + kt*BK + c8
                : A + (size_t)(r0 + row)*lda + kt*BK + c8;
            cp16(sa + row*LDA_B + c8*2, src);
        }
        #pragma unroll
        for (int i = 0; i < 2; i++) {
            int lin = i*256 + tid;
            int row = lin >> 4, c8 = (lin & 15) * 8;
            cp16(sbb + row*LDB_B + c8*2, B + (size_t)(kt*BK + row)*ldb + n0 + c8);
        }
        if (DUAL) {
            uint32_t sb2 = sb + b2Off + st * B_ST;
            #pragma unroll
            for (int i = 0; i < 2; i++) {
                int lin = i*256 + tid;
                int row = lin >> 4, c8 = (lin & 15) * 8;
                cp16(sb2 + row*LDB_B + c8*2, B + (size_t)(kt*BK + row)*ldb + (n0 + HID) + c8);
            }
        }
        asm volatile("cp.async.commit_group;" ::: "memory");
    };

    float acc [4][4][4];
    float acc2[4][4][4];
    #pragma unroll
    for (int i = 0; i < 4; i++)
        #pragma unroll
        for (int j = 0; j < 4; j++)
            #pragma unroll
            for (int t = 0; t < 4; t++) { acc[i][j][t] = 0.f; if (DUAL) acc2[i][j][t] = 0.f; }

    issue(0); issue(1);

    for (int kt = 0; kt < nk; kt++) {
        if (kt + 2 < nk) asm volatile("cp.async.wait_group 1;" ::: "memory");
        else             asm volatile("cp.async.wait_group 0;" ::: "memory");
        __syncthreads();
        if (kt + 2 < nk) issue(kt + 2);

        int st = kt % STG;
        uint32_t sa  = sb + st * A_ST;
        uint32_t sbb = sb + bOff + st * B_ST;
        uint32_t sb2 = sb + b2Off + st * B_ST;

        #pragma unroll
        for (int k16 = 0; k16 < 2; k16++) {
            uint32_t a[4][4];
            #pragma unroll
            for (int mi = 0; mi < 4; mi++) {
                uint32_t addr = sa + (wm*64 + mi*16 + (lane & 15))*LDA_B
                                   + (k16*16 + (lane >> 4)*8)*2;
                ldmx4(a[mi], addr);
            }
            uint32_t b[4][2], b2[4][2];
            #pragma unroll
            for (int nj = 0; nj < 2; nj++) {
                uint32_t addr = sbb + (k16*16 + (lane & 15))*LDB_B
                                    + (wn*32 + nj*16 + (lane >> 4)*8)*2;
                uint32_t r[4]; ldmx4t(r, addr);
                b[nj*2][0] = r[0]; b[nj*2][1] = r[1];
                b[nj*2+1][0] = r[2]; b[nj*2+1][1] = r[3];
                if (DUAL) {
                    uint32_t addr2 = sb2 + (k16*16 + (lane & 15))*LDB_B
                                         + (wn*32 + nj*16 + (lane >> 4)*8)*2;
                    uint32_t r2[4]; ldmx4t(r2, addr2);
                    b2[nj*2][0] = r2[0]; b2[nj*2][1] = r2[1];
                    b2[nj*2+1][0] = r2[2]; b2[nj*2+1][1] = r2[3];
                }
            }
            #pragma unroll
            for (int mi = 0; mi < 4; mi++)
                #pragma unroll
                for (int n8 = 0; n8 < 4; n8++) {
                    mma16816(acc[mi][n8], a[mi], b[n8]);
                    if (DUAL) mma16816(acc2[mi][n8], a[mi], b2[n8]);
                }
        }
    }

    // ---------------- epilogue (mma acc layout: r=lane/4 (+8), c=(lane%4)*2 (+1)) ----------------
    const int rbase = r0 + wm*64;
    const int cbase = wn*32;          // within this CTA's 128-col tile
    const float* vthE = DUAL ? (vth + (GROUPED ? (size_t)e * HID : 0)) : nullptr;

    if (DUAL) {
        __nv_bfloat16* op = (__nv_bfloat16*)Cout;
        #pragma unroll
        for (int mi = 0; mi < 4; mi++) {
            int r = rbase + mi*16 + (lane >> 2);
            float gs0 = GATED ? g_gate[r]     : 1.f;
            float gs1 = GATED ? g_gate[r + 8] : 1.f;
            #pragma unroll
            for (int n8 = 0; n8 < 4; n8++) {
                int c = n0 + cbase + n8*8 + (lane & 3)*2;
                float v0 = vthE[c], v1 = vthE[c + 1];
                float g0 = acc[mi][n8][0], g1 = acc[mi][n8][1];
                float g2 = acc[mi][n8][2], g3 = acc[mi][n8][3];
                float l0 = acc2[mi][n8][0], l1 = acc2[mi][n8][1];
                float l2 = acc2[mi][n8][2], l3 = acc2[mi][n8][3];
                float o0 = (g0 >= v0 ? v0 : 0.f) * l0 * gs0;
                float o1 = (g1 >= v1 ? v1 : 0.f) * l1 * gs0;
                float o2 = (g2 >= v0 ? v0 : 0.f) * l2 * gs1;
                float o3 = (g3 >= v1 ? v1 : 0.f) * l3 * gs1;
                *(__nv_bfloat162*)(op + (size_t)r*ldc + c)       = __floats2bfloat162_rn(o0, o1);
                *(__nv_bfloat162*)(op + (size_t)(r+8)*ldc + c)   = __floats2bfloat162_rn(o2, o3);
            }
        }
    } else {
        #pragma unroll
        for (int mi = 0; mi < 4; mi++) {
            int r = rbase + mi*16 + (lane >> 2);
            #pragma unroll
            for (int n8 = 0; n8 < 4; n8++) {
                int c = n0 + cbase + n8*8 + (lane & 3)*2;
                float o0 = acc[mi][n8][0], o1 = acc[mi][n8][1];
                float o2 = acc[mi][n8][2], o3 = acc[mi][n8][3];
                if (RESID) {
                    float2 r0v = *(const float2*)(resid + (size_t)r*ldr + c);
                    float2 r1v = *(const float2*)(resid + (size_t)(r+8)*ldr + c);
                    o0 += r0v.x; o1 += r0v.y; o2 += r1v.x; o3 += r1v.y;
                }
                if (OUTBF) {
                    __nv_bfloat16* op = (__nv_bfloat16*)Cout;
                    *(__nv_bfloat162*)(op + (size_t)r*ldc + c)     = __floats2bfloat162_rn(o0, o1);
                    *(__nv_bfloat162*)(op + (size_t)(r+8)*ldc + c) = __floats2bfloat162_rn(o2, o3);
                } else {
                    float* op = (float*)Cout;
                    *(float2*)(op + (size_t)r*ldc + c)     = make_float2(o0, o1);
                    *(float2*)(op + (size_t)(r+8)*ldc + c) = make_float2(o2, o3);
                }
            }
        }
    }
}

// ---------------- launch ----------------
static inline int cvtGrid(long n) { return (int)((n/8 + 255) / 256); }

extern "C" void kernel_launch(void* const* d_in, const int* in_sizes, int n_in,
                              void* d_out, int out_size)
{
    const float* h         = (const float*)d_in[0];
    const float* norm_w    = (const float*)d_in[1];
    const float* latent_dw = (const float*)d_in[2];
    const float* latent_uw = (const float*)d_in[3];
    const float* router_w  = (const float*)d_in[4];
    const float* router_b  = (const float*)d_in[5];
    const float* ew1       = (const float*)d_in[6];
    const float* evth      = (const float*)d_in[7];
    const float* ew2       = (const float*)d_in[8];
    const float* sw1       = (const float*)d_in[9];
    const float* svth      = (const float*)d_in[10];
    const float* sw2       = (const float*)d_in[11];
    const float* sgw       = (const float*)d_in[12];
    const float* opw       = (const float*)d_in[13];
    float* out = (float*)d_out;

    auto MMld = k_mm<false,false,false,false,false,true >;  // latent_down -> latent bf16
    auto MMe1 = k_mm<true ,true ,true ,false,false,true >;  // exp1 fused spike -> ACTb
    auto MMe2 = k_mm<true ,false,false,false,false,false>;  // exp2 -> contrib fp32
    auto MMlu = k_mm<false,false,false,false,false,false>;  // latent_up -> X fp32
    auto MMs1 = k_mm<false,false,true ,true ,false,true >;  // shared_w1 fused spike*gate -> ACTSb
    auto MMs2 = k_mm<false,false,false,false,true ,true >;  // shared_w2 + X -> Xb bf16
    auto MMop = k_mm<false,false,false,false,true ,false>;  // out_proj + h -> out fp32

    const uint32_t A_ST = BM*(BK+8)*2, B_ST = BK*(BN+8)*2;
    const int SM1 = STG*(A_ST + B_ST);          // 56832
    const int SM2 = STG*(A_ST + 2*B_ST);        // 82944
    cudaFuncSetAttribute(MMld, cudaFuncAttributeMaxDynamicSharedMemorySize, SM1);
    cudaFuncSetAttribute(MMe1, cudaFuncAttributeMaxDynamicSharedMemorySize, SM2);
    cudaFuncSetAttribute(MMe2, cudaFuncAttributeMaxDynamicSharedMemorySize, SM1);
    cudaFuncSetAttribute(MMlu, cudaFuncAttributeMaxDynamicSharedMemorySize, SM1);
    cudaFuncSetAttribute(MMs1, cudaFuncAttributeMaxDynamicSharedMemorySize, SM2);
    cudaFuncSetAttribute(MMs2, cudaFuncAttributeMaxDynamicSharedMemorySize, SM1);
    cudaFuncSetAttribute(MMop, cudaFuncAttributeMaxDynamicSharedMemorySize, SM1);

    void *p_count, *p_atok, *p_hbf, *p_lbf, *p_ACTb, *p_contrib, *p_eout, *p_ACTSb, *p_X, *p_Xb;
    void *p_ldw, *p_luw, *p_ew1, *p_ew2, *p_sw1, *p_sw2, *p_opw;
    cudaGetSymbolAddress(&p_count, g_count);
    cudaGetSymbolAddress(&p_atok,  g_assign_tok);
    cudaGetSymbolAddress(&p_hbf,   g_hnorm_bf);
    cudaGetSymbolAddress(&p_lbf,   g_latent_bf);
    cudaGetSymbolAddress(&p_ACTb,  g_ACTb);
    cudaGetSymbolAddress(&p_contrib, g_contrib);
    cudaGetSymbolAddress(&p_eout,  g_eout_bf);
    cudaGetSymbolAddress(&p_ACTSb, g_ACTSb);
    cudaGetSymbolAddress(&p_X,     g_X);
    cudaGetSymbolAddress(&p_Xb,    g_Xb);
    cudaGetSymbolAddress(&p_ldw,   g_ldw_bf);
    cudaGetSymbolAddress(&p_luw,   g_luw_bf);
    cudaGetSymbolAddress(&p_ew1,   g_ew1_bf);
    cudaGetSymbolAddress(&p_ew2,   g_ew2_bf);
    cudaGetSymbolAddress(&p_sw1,   g_sw1_bf);
    cudaGetSymbolAddress(&p_sw2,   g_sw2_bf);
    cudaGetSymbolAddress(&p_opw,   g_opw_bf);

    cudaMemsetAsync(p_count, 0, NEXP * sizeof(int));
    cudaMemsetAsync(p_atok,  0, ATOTP * sizeof(int));

    // weight conversions
    k_cvt<<<cvtGrid((long)D_*LAT), 256>>>(latent_dw, (__nv_bfloat16*)p_ldw, (long)D_*LAT);
    k_cvt<<<cvtGrid((long)LAT*D_), 256>>>(latent_uw, (__nv_bfloat16*)p_luw, (long)LAT*D_);
    k_cvt<<<cvtGrid((long)NEXP*LAT*2*EH), 256>>>(ew1, (__nv_bfloat16*)p_ew1, (long)NEXP*LAT*2*EH);
    k_cvt<<<cvtGrid((long)NEXP*EH*LAT), 256>>>(ew2, (__nv_bfloat16*)p_ew2, (long)NEXP*EH*LAT);
    k_cvt<<<cvtGrid((long)D_*2*SH), 256>>>(sw1, (__nv_bfloat16*)p_sw1, (long)D_*2*SH);
    k_cvt<<<cvtGrid((long)SH*D_), 256>>>(sw2, (__nv_bfloat16*)p_sw2, (long)SH*D_);
    k_cvt<<<cvtGrid((long)D_*D_), 256>>>(opw, (__nv_bfloat16*)p_opw, (long)D_*D_);

    // normalization + routing (fp32)
    k_rmsnorm<<<NTOK, 256>>>(h, norm_w);
    k_router <<<NTOK/32, 256>>>(router_w, router_b);
    k_topk   <<<NTOK/8, 256>>>();
    k_colsum <<<NEXP, 256>>>();
    k_offsets<<<1, 32>>>();
    k_assign <<<NTOK/256, 256>>>();
    k_gate   <<<NTOK, 256>>>(sgw);

    // latent = hnorm @ latent_down  -> bf16
    MMld<<<dim3(LAT/128, NTOK/128), 256, SM1>>>((const __nv_bfloat16*)p_hbf, D_,
        (const __nv_bfloat16*)p_ldw, 0, LAT, p_lbf, LAT, nullptr, 0, nullptr, 0, D_);

    // exp1 fused spike -> ACTb bf16
    MMe1<<<dim3(MAXTILES, EH/128), 256, SM2>>>((const __nv_bfloat16*)p_lbf, LAT,
        (const __nv_bfloat16*)p_ew1, (long)LAT*2*EH, 2*EH, p_ACTb, EH, nullptr, 0, evth, EH, LAT);

    // exp2 -> contrib fp32
    MMe2<<<dim3(MAXTILES, LAT/128), 256, SM1>>>((const __nv_bfloat16*)p_ACTb, EH,
        (const __nv_bfloat16*)p_ew2, (long)EH*LAT, LAT, p_contrib, LAT, nullptr, 0, nullptr, 0, EH);

    k_combine<<<NTOK, LAT>>>();

    // X = eout @ latent_up  (fp32)
    MMlu<<<dim3(D_/128, NTOK/128), 256, SM1>>>((const __nv_bfloat16*)p_eout, LAT,
        (const __nv_bfloat16*)p_luw, 0, D_, p_X, D_, nullptr, 0, nullptr, 0, LAT);

    // shared_w1 fused spike * gate -> ACTSb bf16
    MMs1<<<dim3(SH/128, NTOK/128), 256, SM2>>>((const __nv_bfloat16*)p_hbf, D_,
        (const __nv_bfloat16*)p_sw1, 0, 2*SH, p_ACTSb, SH, nullptr, 0, svth, SH, D_);

    // Xb = bf16(ACTS @ shared_w2 + X)
    MMs2<<<dim3(D_/128, NTOK/128), 256, SM1>>>((const __nv_bfloat16*)p_ACTSb, SH,
        (const __nv_bfloat16*)p_sw2, 0, D_, p_Xb, D_, (const float*)p_X, D_, nullptr, 0, SH);

    // out = h + Xb @ out_proj  (fp32)
    MMop<<<dim3(D_/128, NTOK/128), 256, SM1>>>((const __nv_bfloat16*)p_Xb, D_,
        (const __nv_bfloat16*)p_opw, 0, D_, out, D_, h, D_, nullptr, 0, D_);

    k_lb<<<1, 32>>>(out, out_size);
}

// round 5
// speedup vs baseline: 6.1042x; 1.0519x over previous
#include <cuda_runtime.h>
#include <cuda_bf16.h>
#include <math.h>
#include <stdint.h>

// ---------------- problem constants ----------------
#define D_      2048
#define NTOK    8192
#define LAT     256
#define NEXP    32
#define EH      1024
#define SH      2048
#define ATOT    (NTOK*4)
#define ATOTP   (ATOT + NEXP*128)   // 36864
#define MAXTILES (ATOTP/128)        // 288

#define BM 128
#define BN 128
#define BK 32
#define STG 3

// ---------------- device scratch ----------------
__device__ float g_hnorm [NTOK*D_];
__device__ __nv_bfloat16 g_hnorm_bf[NTOK*D_];
__device__ float g_scores[NTOK*NEXP];
__device__ __nv_bfloat16 g_latent_bf[NTOK*LAT];
__device__ __nv_bfloat16 g_ACTb[(size_t)ATOTP*EH];
__device__ float g_contrib[(size_t)ATOTP*LAT];
__device__ __nv_bfloat16 g_eout_bf[NTOK*LAT];
__device__ __nv_bfloat16 g_ACTSb[(size_t)NTOK*SH];
__device__ float g_X  [(size_t)NTOK*D_];
__device__ __nv_bfloat16 g_Xb[(size_t)NTOK*D_];
__device__ float g_gate  [NTOK];
__device__ float g_Psum  [NEXP];
__device__ int   g_count [NEXP];
__device__ int   g_off   [NEXP+1];
__device__ int   g_cursor[NEXP];
__device__ int   g_tile_e[MAXTILES];
__device__ int   g_tile_r[MAXTILES];
__device__ int   g_ntiles;
__device__ int   g_assign_tok[ATOTP];
__device__ int   g_assign_pos[ATOT];
__device__ int   g_topi[ATOT];
__device__ float g_topw[ATOT];

// bf16 weights
__device__ __nv_bfloat16 g_ldw_bf[(size_t)D_*LAT];
__device__ __nv_bfloat16 g_luw_bf[(size_t)LAT*D_];
__device__ __nv_bfloat16 g_ew1_bf[(size_t)NEXP*LAT*2*EH];
__device__ __nv_bfloat16 g_ew2_bf[(size_t)NEXP*EH*LAT];
__device__ __nv_bfloat16 g_sw1_bf[(size_t)D_*2*SH];
__device__ __nv_bfloat16 g_sw2_bf[(size_t)SH*D_];
__device__ __nv_bfloat16 g_opw_bf[(size_t)D_*D_];

// ---------------- asm helpers ----------------
__device__ __forceinline__ uint32_t s2u(const void* p) {
    uint32_t a;
    asm("{ .reg .u64 t; cvta.to.shared.u64 t, %1; cvt.u32.u64 %0, t; }" : "=r"(a) : "l"(p));
    return a;
}
__device__ __forceinline__ void cp16(uint32_t d, const void* s) {
    asm volatile("cp.async.cg.shared.global [%0], [%1], 16;" :: "r"(d), "l"(s));
}
__device__ __forceinline__ void ldmx4(uint32_t* r, uint32_t a) {
    asm volatile("ldmatrix.sync.aligned.m8n8.x4.shared.b16 {%0,%1,%2,%3}, [%4];"
        : "=r"(r[0]), "=r"(r[1]), "=r"(r[2]), "=r"(r[3]) : "r"(a));
}
__device__ __forceinline__ void ldmx4t(uint32_t* r, uint32_t a) {
    asm volatile("ldmatrix.sync.aligned.m8n8.x4.trans.shared.b16 {%0,%1,%2,%3}, [%4];"
        : "=r"(r[0]), "=r"(r[1]), "=r"(r[2]), "=r"(r[3]) : "r"(a));
}
__device__ __forceinline__ void mma16816(float* c, const uint32_t* a, const uint32_t* b) {
    asm volatile("mma.sync.aligned.m16n8k16.row.col.f32.bf16.bf16.f32 "
        "{%0,%1,%2,%3},{%4,%5,%6,%7},{%8,%9},{%0,%1,%2,%3};"
        : "+f"(c[0]), "+f"(c[1]), "+f"(c[2]), "+f"(c[3])
        : "r"(a[0]), "r"(a[1]), "r"(a[2]), "r"(a[3]), "r"(b[0]), "r"(b[1]));
}

// ---------------- rmsnorm + fused shared gate ----------------
__global__ void k_rmsnorm(const float* __restrict__ h, const float* __restrict__ w,
                          const float* __restrict__ gw)
{
    int n = blockIdx.x;
    const float4* hp = (const float4*)(h + (size_t)n * D_);
    const float4* wp = (const float4*)w;
    const float4* gp = (const float4*)gw;
    float ss = 0.f, gg = 0.f;
    for (int i = threadIdx.x; i < D_/4; i += 256) {
        float4 v = hp[i], wv = wp[i], gv = gp[i];
        ss += v.x*v.x + v.y*v.y + v.z*v.z + v.w*v.w;
        gg += v.x*wv.x*gv.x + v.y*wv.y*gv.y + v.z*wv.z*gv.z + v.w*wv.w*gv.w;
    }
    __shared__ float red[256], red2[256];
    red[threadIdx.x] = ss; red2[threadIdx.x] = gg; __syncthreads();
    for (int s = 128; s; s >>= 1) {
        if (threadIdx.x < s) { red[threadIdx.x] += red[threadIdx.x + s];
                               red2[threadIdx.x] += red2[threadIdx.x + s]; }
        __syncthreads();
    }
    float rs = rsqrtf(red[0] * (1.f / D_) + 1e-6f);
    if (threadIdx.x == 0) g_gate[n] = 1.f / (1.f + expf(-rs * red2[0]));
    float4* op = (float4*)(g_hnorm + (size_t)n * D_);
    __nv_bfloat162* bp = (__nv_bfloat162*)(g_hnorm_bf + (size_t)n * D_);
    for (int i = threadIdx.x; i < D_/4; i += 256) {
        float4 v = hp[i], wv = wp[i];
        v.x *= rs*wv.x; v.y *= rs*wv.y; v.z *= rs*wv.z; v.w *= rs*wv.w;
        op[i] = v;
        bp[i*2+0] = __floats2bfloat162_rn(v.x, v.y);
        bp[i*2+1] = __floats2bfloat162_rn(v.z, v.w);
    }
}

__global__ void k_router(const float* __restrict__ rw, const float* __restrict__ rb)
{
    __shared__ float hs[32][64];
    __shared__ float ws[64][32];
    int n0 = blockIdx.x * 32;
    int tid = threadIdx.x;
    int e = tid & 31, tr = tid >> 5;
    float acc[4] = {0.f,0.f,0.f,0.f};
    for (int k0 = 0; k0 < D_; k0 += 64) {
        #pragma unroll
        for (int i = 0; i < 8; i++) {
            int lin = tid + i*256;
            int t = lin >> 6, k = lin & 63;
            hs[t][k] = g_hnorm[(size_t)(n0 + t)*D_ + k0 + k];
            int kw = lin >> 5, ew = lin & 31;
            ws[kw][ew] = rw[(size_t)(k0 + kw)*NEXP + ew];
        }
        __syncthreads();
        #pragma unroll
        for (int kk = 0; kk < 64; kk++)
            #pragma unroll
            for (int i = 0; i < 4; i++)
                acc[i] += hs[tr + 8*i][kk] * ws[kk][e];
        __syncthreads();
    }
    float bias = rb[e];
    #pragma unroll
    for (int i = 0; i < 4; i++) {
        float v = acc[i] + bias;
        g_scores[(n0 + tr + 8*i)*NEXP + e] = 1.f / (1.f + expf(-v));
    }
}

__global__ void k_topk()
{
    int warp = threadIdx.x >> 5, lane = threadIdx.x & 31;
    int n = blockIdx.x * 8 + warp;
    float s = g_scores[n*NEXP + lane];
    float topv[4]; int topi[4];
    #pragma unroll
    for (int k = 0; k < 4; k++) {
        float v = s; int bi = lane;
        #pragma unroll
        for (int off = 16; off; off >>= 1) {
            float v2 = __shfl_xor_sync(0xffffffffu, v, off);
            int   i2 = __shfl_xor_sync(0xffffffffu, bi, off);
            if (v2 > v || (v2 == v && i2 < bi)) { v = v2; bi = i2; }
        }
        topv[k] = v; topi[k] = bi;
        if (lane == bi) s = -1e30f;
    }
    if (lane == 0) {
        float inv = 1.f / (topv[0]+topv[1]+topv[2]+topv[3] + 1e-8f);
        #pragma unroll
        for (int k = 0; k < 4; k++) {
            g_topw[n*4 + k] = topv[k] * inv;
            g_topi[n*4 + k] = topi[k];
            atomicAdd(&g_count[topi[k]], 1);
        }
    }
}

__global__ void k_colsum()
{
    int e = blockIdx.x;
    float s = 0.f;
    for (int n = threadIdx.x; n < NTOK; n += 256) s += g_scores[n*NEXP + e];
    __shared__ float red[256];
    red[threadIdx.x] = s; __syncthreads();
    for (int st = 128; st; st >>= 1) {
        if (threadIdx.x < st) red[threadIdx.x] += red[threadIdx.x + st];
        __syncthreads();
    }
    if (threadIdx.x == 0) g_Psum[e] = red[0];
}

__global__ void k_offsets()
{
    if (threadIdx.x == 0) {
        int acc = 0, nt = 0;
        for (int e = 0; e < NEXP; e++) {
            g_off[e] = acc; g_cursor[e] = acc;
            int nep = (g_count[e] + 127) & ~127;
            for (int r = 0; r < nep; r += 128) {
                g_tile_e[nt] = e; g_tile_r[nt] = acc + r; nt++;
            }
            acc += nep;
        }
        g_off[NEXP] = acc;
        g_ntiles = nt;
    }
}

__global__ void k_assign()
{
    int n = blockIdx.x * 256 + threadIdx.x;
    if (n >= NTOK) return;
    #pragma unroll
    for (int k = 0; k < 4; k++) {
        int e = g_topi[n*4 + k];
        int pos = atomicAdd(&g_cursor[e], 1);
        g_assign_tok[pos] = n;
        g_assign_pos[n*4 + k] = pos;
    }
}

__global__ void k_combine()
{
    int n = blockIdx.x, c = threadIdx.x;
    float acc = 0.f;
    #pragma unroll
    for (int k = 0; k < 4; k++) {
        int pos = g_assign_pos[n*4 + k];
        acc += g_topw[n*4 + k] * g_contrib[(size_t)pos * LAT + c];
    }
    g_eout_bf[(size_t)n * LAT + c] = __float2bfloat16(acc);
}

__global__ void k_lb(float* out, int out_size)
{
    if (threadIdx.x == 0 && out_size > NTOK * D_) {
        float s = 0.f;
        for (int e = 0; e < NEXP; e++)
            s += ((float)g_count[e] / NTOK) * (g_Psum[e] / NTOK);
        out[NTOK * D_] = (float)NEXP * s * 1e-4f;
    }
}

__global__ void k_cvt(const float* __restrict__ a, __nv_bfloat16* __restrict__ b, long n)
{
    long i = ((long)blockIdx.x*256 + threadIdx.x) * 16;
    if (i >= n) return;
    float4 v0 = *(const float4*)(a + i);
    float4 v1 = *(const float4*)(a + i + 4);
    float4 v2 = *(const float4*)(a + i + 8);
    float4 v3 = *(const float4*)(a + i + 12);
    __nv_bfloat162 o[8];
    o[0] = __floats2bfloat162_rn(v0.x, v0.y);
    o[1] = __floats2bfloat162_rn(v0.z, v0.w);
    o[2] = __floats2bfloat162_rn(v1.x, v1.y);
    o[3] = __floats2bfloat162_rn(v1.z, v1.w);
    o[4] = __floats2bfloat162_rn(v2.x, v2.y);
    o[5] = __floats2bfloat162_rn(v2.z, v2.w);
    o[6] = __floats2bfloat162_rn(v3.x, v3.y);
    o[7] = __floats2bfloat162_rn(v3.z, v3.w);
    *(uint4*)(b + i)     = *(uint4*)&o[0];
    *(uint4*)(b + i + 8) = *(uint4*)&o[4];
}

// ====== DUAL mma GEMM (gate+lin, fused spike): 256 thr, warp 64x32, BK=32, 3-stage ======
template<bool GROUPED, bool GATHER, bool GATED>
__global__ void __launch_bounds__(256)
k_mmdual(const __nv_bfloat16* __restrict__ A, int lda,
         const __nv_bfloat16* __restrict__ Bt, long bstride, int ldb,
         __nv_bfloat16* __restrict__ Cout, int ldc,
         const float* __restrict__ vth, int HID, int K)
{
    extern __shared__ __align__(16) char smem[];
    __shared__ int s_tok[BM];

    const int tid = threadIdx.x;
    const int lane = tid & 31;
    const int wid = tid >> 5;
    const int wm = wid >> 2, wn = wid & 3;

    int e = 0, r0, n0;
    if (GROUPED) {
        int bt = blockIdx.x;
        if (bt >= g_ntiles) return;
        e = g_tile_e[bt]; r0 = g_tile_r[bt]; n0 = blockIdx.y * BN;
    } else {
        r0 = blockIdx.y * BM; n0 = blockIdx.x * BN;
    }
    const __nv_bfloat16* B = Bt + (GROUPED ? (size_t)e * bstride : 0);

    const uint32_t sb = s2u(smem);
    const uint32_t LDA_B = (BK + 8) * 2;
    const uint32_t LDB_B = (BN + 8) * 2;
    const uint32_t A_ST = BM * LDA_B;
    const uint32_t B_ST = BK * LDB_B;
    const uint32_t bOff  = STG * A_ST;
    const uint32_t b2Off = STG * (A_ST + B_ST);

    if (GATHER) {
        if (tid < BM) s_tok[tid] = g_assign_tok[r0 + tid];
        __syncthreads();
    }

    const int nk = K / BK;

    auto issue = [&](int kt) {
        int st = kt % STG;
        uint32_t sa  = sb + st * A_ST;
        uint32_t sbb = sb + bOff + st * B_ST;
        uint32_t sb2 = sb + b2Off + st * B_ST;
        #pragma unroll
        for (int i = 0; i < 2; i++) {
            int lin = i*256 + tid;
            int row = lin >> 2, c8 = (lin & 3) * 8;
            const __nv_bfloat16* src = GATHER
                ? A + (size_t)s_tok[row]*lda + kt*BK + c8
                : A + (size_t)(r0 + row)*lda + kt*BK + c8;
            cp16(sa + row*LDA_B + c8*2, src);
        }
        #pragma unroll
        for (int i = 0; i < 2; i++) {
            int lin = i*256 + tid;
            int row = lin >> 4, c8 = (lin & 15) * 8;
            cp16(sbb + row*LDB_B + c8*2, B + (size_t)(kt*BK + row)*ldb + n0 + c8);
            cp16(sb2 + row*LDB_B + c8*2, B + (size_t)(kt*BK + row)*ldb + (n0 + HID) + c8);
        }
        asm volatile("cp.async.commit_group;" ::: "memory");
    };

    float acc [4][4][4], acc2[4][4][4];
    #pragma unroll
    for (int i = 0; i < 4; i++)
        #pragma unroll
        for (int j = 0; j < 4; j++)
            #pragma unroll
            for (int t = 0; t < 4; t++) { acc[i][j][t] = 0.f; acc2[i][j][t] = 0.f; }

    issue(0); issue(1);

    for (int kt = 0; kt < nk; kt++) {
        if (kt + 2 < nk) asm volatile("cp.async.wait_group 1;" ::: "memory");
        else             asm volatile("cp.async.wait_group 0;" ::: "memory");
        __syncthreads();
        if (kt + 2 < nk) issue(kt + 2);

        int st = kt % STG;
        uint32_t sa  = sb + st * A_ST;
        uint32_t sbb = sb + bOff + st * B_ST;
        uint32_t sb2 = sb + b2Off + st * B_ST;

        #pragma unroll
        for (int k16 = 0; k16 < 2; k16++) {
            uint32_t a[4][4];
            #pragma unroll
            for (int mi = 0; mi < 4; mi++) {
                uint32_t addr = sa + (wm*64 + mi*16 + (lane & 15))*LDA_B
                                   + (k16*16 + (lane >> 4)*8)*2;
                ldmx4(a[mi], addr);
            }
            uint32_t b[4][2], b2[4][2];
            #pragma unroll
            for (int nj = 0; nj < 2; nj++) {
                uint32_t addr = sbb + (k16*16 + (lane & 15))*LDB_B
                                    + (wn*32 + nj*16 + (lane >> 4)*8)*2;
                uint32_t r[4]; ldmx4t(r, addr);
                b[nj*2][0] = r[0]; b[nj*2][1] = r[1];
                b[nj*2+1][0] = r[2]; b[nj*2+1][1] = r[3];
                uint32_t addr2 = sb2 + (k16*16 + (lane & 15))*LDB_B
                                     + (wn*32 + nj*16 + (lane >> 4)*8)*2;
                uint32_t r2[4]; ldmx4t(r2, addr2);
                b2[nj*2][0] = r2[0]; b2[nj*2][1] = r2[1];
                b2[nj*2+1][0] = r2[2]; b2[nj*2+1][1] = r2[3];
            }
            #pragma unroll
            for (int mi = 0; mi < 4; mi++)
                #pragma unroll
                for (int n8 = 0; n8 < 4; n8++) {
                    mma16816(acc[mi][n8], a[mi], b[n8]);
                    mma16816(acc2[mi][n8], a[mi], b2[n8]);
                }
        }
    }

    const int rbase = r0 + wm*64;
    const int cbase = wn*32;
    const float* vthE = vth + (GROUPED ? (size_t)e * HID : 0);
    #pragma unroll
    for (int mi = 0; mi < 4; mi++) {
        int r = rbase + mi*16 + (lane >> 2);
        float gs0 = GATED ? g_gate[r]     : 1.f;
        float gs1 = GATED ? g_gate[r + 8] : 1.f;
        #pragma unroll
        for (int n8 = 0; n8 < 4; n8++) {
            int c = n0 + cbase + n8*8 + (lane & 3)*2;
            float v0 = vthE[c], v1 = vthE[c + 1];
            float o0 = (acc[mi][n8][0] >= v0 ? v0 : 0.f) * acc2[mi][n8][0] * gs0;
            float o1 = (acc[mi][n8][1] >= v1 ? v1 : 0.f) * acc2[mi][n8][1] * gs0;
            float o2 = (acc[mi][n8][2] >= v0 ? v0 : 0.f) * acc2[mi][n8][2] * gs1;
            float o3 = (acc[mi][n8][3] >= v1 ? v1 : 0.f) * acc2[mi][n8][3] * gs1;
            *(__nv_bfloat162*)(Cout + (size_t)r*ldc + c)     = __floats2bfloat162_rn(o0, o1);
            *(__nv_bfloat162*)(Cout + (size_t)(r+8)*ldc + c) = __floats2bfloat162_rn(o2, o3);
        }
    }
}

// ====== non-dual mma GEMM: 128 thr, 4 warps (2x2), warp 64x64, BK=32, 3-stage ======
template<bool GROUPED, bool RESID, bool OUTBF>
__global__ void __launch_bounds__(128)
k_mm64(const __nv_bfloat16* __restrict__ A, int lda,
       const __nv_bfloat16* __restrict__ Bt, long bstride, int ldb,
       void* __restrict__ Cout, int ldc,
       const float* __restrict__ resid, int ldr, int K)
{
    extern __shared__ __align__(16) char smem[];

    const int tid = threadIdx.x;
    const int lane = tid & 31;
    const int wid = tid >> 5;
    const int wm = wid >> 1, wn = wid & 1;

    int e = 0, r0, n0;
    if (GROUPED) {
        int bt = blockIdx.x;
        if (bt >= g_ntiles) return;
        e = g_tile_e[bt]; r0 = g_tile_r[bt]; n0 = blockIdx.y * BN;
    } else {
        r0 = blockIdx.y * BM; n0 = blockIdx.x * BN;
    }
    const __nv_bfloat16* B = Bt + (GROUPED ? (size_t)e * bstride : 0);

    const uint32_t sb = s2u(smem);
    const uint32_t LDA_B = (BK + 8) * 2;
    const uint32_t LDB_B = (BN + 8) * 2;
    const uint32_t A_ST = BM * LDA_B;
    const uint32_t B_ST = BK * LDB_B;
    const uint32_t bOff = STG * A_ST;

    const int nk = K / BK;

    auto issue = [&](int kt) {
        int st = kt % STG;
        uint32_t sa  = sb + st * A_ST;
        uint32_t sbb = sb + bOff + st * B_ST;
        #pragma unroll
        for (int i = 0; i < 4; i++) {
            int lin = i*128 + tid;
            int row = lin >> 2, c8 = (lin & 3) * 8;
            cp16(sa + row*LDA_B + c8*2, A + (size_t)(r0 + row)*lda + kt*BK + c8);
        }
        #pragma unroll
        for (int i = 0; i < 4; i++) {
            int lin = i*128 + tid;
            int row = lin >> 4, c8 = (lin & 15) * 8;
            cp16(sbb + row*LDB_B + c8*2, B + (size_t)(kt*BK + row)*ldb + n0 + c8);
        }
        asm volatile("cp.async.commit_group;" ::: "memory");
    };

    float acc[4][8][4];
    #pragma unroll
    for (int i = 0; i < 4; i++)
        #pragma unroll
        for (int j = 0; j < 8; j++)
            #pragma unroll
            for (int t = 0; t < 4; t++) acc[i][j][t] = 0.f;

    issue(0); issue(1);

    for (int kt = 0; kt < nk; kt++) {
        if (kt + 2 < nk) asm volatile("cp.async.wait_group 1;" ::: "memory");
        else             asm volatile("cp.async.wait_group 0;" ::: "memory");
        __syncthreads();
        if (kt + 2 < nk) issue(kt + 2);

        int st = kt % STG;
        uint32_t sa  = sb + st * A_ST;
        uint32_t sbb = sb + bOff + st * B_ST;

        #pragma unroll
        for (int k16 = 0; k16 < 2; k16++) {
            uint32_t a[4][4];
            #pragma unroll
            for (int mi = 0; mi < 4; mi++) {
                uint32_t addr = sa + (wm*64 + mi*16 + (lane & 15))*LDA_B
                                   + (k16*16 + (lane >> 4)*8)*2;
                ldmx4(a[mi], addr);
            }
            uint32_t b[8][2];
            #pragma unroll
            for (int nj = 0; nj < 4; nj++) {
                uint32_t addr = sbb + (k16*16 + (lane & 15))*LDB_B
                                    + (wn*64 + nj*16 + (lane >> 4)*8)*2;
                uint32_t r[4]; ldmx4t(r, addr);
                b[nj*2][0] = r[0]; b[nj*2][1] = r[1];
                b[nj*2+1][0] = r[2]; b[nj*2+1][1] = r[3];
            }
            #pragma unroll
            for (int mi = 0; mi < 4; mi++)
                #pragma unroll
                for (int n8 = 0; n8 < 8; n8++)
                    mma16816(acc[mi][n8], a[mi], b[n8]);
        }
    }

    const int rbase = r0 + wm*64;
    const int cbase = wn*64;
    #pragma unroll
    for (int mi = 0; mi < 4; mi++) {
        int r = rbase + mi*16 + (lane >> 2);
        #pragma unroll
        for (int n8 = 0; n8 < 8; n8++) {
            int c = n0 + cbase + n8*8 + (lane & 3)*2;
            float o0 = acc[mi][n8][0], o1 = acc[mi][n8][1];
            float o2 = acc[mi][n8][2], o3 = acc[mi][n8][3];
            if (RESID) {
                float2 r0v = *(const float2*)(resid + (size_t)r*ldr + c);
                float2 r1v = *(const float2*)(resid + (size_t)(r+8)*ldr + c);
                o0 += r0v.x; o1 += r0v.y; o2 += r1v.x; o3 += r1v.y;
            }
            if (OUTBF) {
                __nv_bfloat16* op = (__nv_bfloat16*)Cout;
                *(__nv_bfloat162*)(op + (size_t)r*ldc + c)     = __floats2bfloat162_rn(o0, o1);
                *(__nv_bfloat162*)(op + (size_t)(r+8)*ldc + c) = __floats2bfloat162_rn(o2, o3);
            } else {
                float* op = (float*)Cout;
                *(float2*)(op + (size_t)r*ldc + c)     = make_float2(o0, o1);
                *(float2*)(op + (size_t)(r+8)*ldc + c) = make_float2(o2, o3);
            }
        }
    }
}

// ---------------- launch ----------------
static inline int cvtGrid(long n) { return (int)((n/16 + 255) / 256); }

extern "C" void kernel_launch(void* const* d_in, const int* in_sizes, int n_in,
                              void* d_out, int out_size)
{
    const float* h         = (const float*)d_in[0];
    const float* norm_w    = (const float*)d_in[1];
    const float* latent_dw = (const float*)d_in[2];
    const float* latent_uw = (const float*)d_in[3];
    const float* router_w  = (const float*)d_in[4];
    const float* router_b  = (const float*)d_in[5];
    const float* ew1       = (const float*)d_in[6];
    const float* evth      = (const float*)d_in[7];
    const float* ew2       = (const float*)d_in[8];
    const float* sw1       = (const float*)d_in[9];
    const float* svth      = (const float*)d_in[10];
    const float* sw2       = (const float*)d_in[11];
    const float* sgw       = (const float*)d_in[12];
    const float* opw       = (const float*)d_in[13];
    float* out = (float*)d_out;

    auto MMe1 = k_mmdual<true , true , false>;  // exp1 fused spike -> ACTb
    auto MMs1 = k_mmdual<false, false, true >;  // shared_w1 fused spike*gate -> ACTSb
    auto MMld = k_mm64<false, false, true >;    // latent_down -> latent bf16
    auto MMe2 = k_mm64<true , false, false>;    // exp2 -> contrib fp32
    auto MMlu = k_mm64<false, false, false>;    // latent_up -> X fp32
    auto MMs2 = k_mm64<false, true , true >;    // shared_w2 + X -> Xb bf16
    auto MMop = k_mm64<false, true , false>;    // out_proj + h -> out fp32

    const uint32_t A_ST = BM*(BK+8)*2, B_ST = BK*(BN+8)*2;
    const int SM1 = STG*(A_ST + B_ST);          // 56832
    const int SM2 = STG*(A_ST + 2*B_ST);        // 82944
    cudaFuncSetAttribute(MMe1, cudaFuncAttributeMaxDynamicSharedMemorySize, SM2);
    cudaFuncSetAttribute(MMs1, cudaFuncAttributeMaxDynamicSharedMemorySize, SM2);
    cudaFuncSetAttribute(MMld, cudaFuncAttributeMaxDynamicSharedMemorySize, SM1);
    cudaFuncSetAttribute(MMe2, cudaFuncAttributeMaxDynamicSharedMemorySize, SM1);
    cudaFuncSetAttribute(MMlu, cudaFuncAttributeMaxDynamicSharedMemorySize, SM1);
    cudaFuncSetAttribute(MMs2, cudaFuncAttributeMaxDynamicSharedMemorySize, SM1);
    cudaFuncSetAttribute(MMop, cudaFuncAttributeMaxDynamicSharedMemorySize, SM1);

    void *p_count, *p_atok, *p_hbf, *p_lbf, *p_ACTb, *p_contrib, *p_eout, *p_ACTSb, *p_X, *p_Xb;
    void *p_ldw, *p_luw, *p_ew1, *p_ew2, *p_sw1, *p_sw2, *p_opw;
    cudaGetSymbolAddress(&p_count, g_count);
    cudaGetSymbolAddress(&p_atok,  g_assign_tok);
    cudaGetSymbolAddress(&p_hbf,   g_hnorm_bf);
    cudaGetSymbolAddress(&p_lbf,   g_latent_bf);
    cudaGetSymbolAddress(&p_ACTb,  g_ACTb);
    cudaGetSymbolAddress(&p_contrib, g_contrib);
    cudaGetSymbolAddress(&p_eout,  g_eout_bf);
    cudaGetSymbolAddress(&p_ACTSb, g_ACTSb);
    cudaGetSymbolAddress(&p_X,     g_X);
    cudaGetSymbolAddress(&p_Xb,    g_Xb);
    cudaGetSymbolAddress(&p_ldw,   g_ldw_bf);
    cudaGetSymbolAddress(&p_luw,   g_luw_bf);
    cudaGetSymbolAddress(&p_ew1,   g_ew1_bf);
    cudaGetSymbolAddress(&p_ew2,   g_ew2_bf);
    cudaGetSymbolAddress(&p_sw1,   g_sw1_bf);
    cudaGetSymbolAddress(&p_sw2,   g_sw2_bf);
    cudaGetSymbolAddress(&p_opw,   g_opw_bf);

    cudaMemsetAsync(p_count, 0, NEXP * sizeof(int));
    cudaMemsetAsync(p_atok,  0, ATOTP * sizeof(int));

    // weight conversions
    k_cvt<<<cvtGrid((long)D_*LAT), 256>>>(latent_dw, (__nv_bfloat16*)p_ldw, (long)D_*LAT);
    k_cvt<<<cvtGrid((long)LAT*D_), 256>>>(latent_uw, (__nv_bfloat16*)p_luw, (long)LAT*D_);
    k_cvt<<<cvtGrid((long)NEXP*LAT*2*EH), 256>>>(ew1, (__nv_bfloat16*)p_ew1, (long)NEXP*LAT*2*EH);
    k_cvt<<<cvtGrid((long)NEXP*EH*LAT), 256>>>(ew2, (__nv_bfloat16*)p_ew2, (long)NEXP*EH*LAT);
    k_cvt<<<cvtGrid((long)D_*2*SH), 256>>>(sw1, (__nv_bfloat16*)p_sw1, (long)D_*2*SH);
    k_cvt<<<cvtGrid((long)SH*D_), 256>>>(sw2, (__nv_bfloat16*)p_sw2, (long)SH*D_);
    k_cvt<<<cvtGrid((long)D_*D_), 256>>>(opw, (__nv_bfloat16*)p_opw, (long)D_*D_);

    // normalization + routing (fp32) — gate fused into rmsnorm
    k_rmsnorm<<<NTOK, 256>>>(h, norm_w, sgw);
    k_router <<<NTOK/32, 256>>>(router_w, router_b);
    k_topk   <<<NTOK/8, 256>>>();
    k_colsum <<<NEXP, 256>>>();
    k_offsets<<<1, 32>>>();
    k_assign <<<NTOK/256, 256>>>();

    // latent = hnorm @ latent_down  -> bf16
    MMld<<<dim3(LAT/128, NTOK/128), 128, SM1>>>((const __nv_bfloat16*)p_hbf, D_,
        (const __nv_bfloat16*)p_ldw, 0, LAT, p_lbf, LAT, nullptr, 0, D_);

    // exp1 fused spike -> ACTb bf16
    MMe1<<<dim3(MAXTILES, EH/128), 256, SM2>>>((const __nv_bfloat16*)p_lbf, LAT,
        (const __nv_bfloat16*)p_ew1, (long)LAT*2*EH, 2*EH,
        (__nv_bfloat16*)p_ACTb, EH, evth, EH, LAT);

    // exp2 -> contrib fp32
    MMe2<<<dim3(MAXTILES, LAT/128), 128, SM1>>>((const __nv_bfloat16*)p_ACTb, EH,
        (const __nv_bfloat16*)p_ew2, (long)EH*LAT, LAT, p_contrib, LAT, nullptr, 0, EH);

    k_combine<<<NTOK, LAT>>>();

    // X = eout @ latent_up  (fp32)
    MMlu<<<dim3(D_/128, NTOK/128), 128, SM1>>>((const __nv_bfloat16*)p_eout, LAT,
        (const __nv_bfloat16*)p_luw, 0, D_, p_X, D_, nullptr, 0, LAT);

    // shared_w1 fused spike * gate -> ACTSb bf16
    MMs1<<<dim3(SH/128, NTOK/128), 256, SM2>>>((const __nv_bfloat16*)p_hbf, D_,
        (const __nv_bfloat16*)p_sw1, 0, 2*SH, (__nv_bfloat16*)p_ACTSb, SH, svth, SH, D_);

    // Xb = bf16(ACTS @ shared_w2 + X)
    MMs2<<<dim3(D_/128, NTOK/128), 128, SM1>>>((const __nv_bfloat16*)p_ACTSb, SH,
        (const __nv_bfloat16*)p_sw2, 0, D_, p_Xb, D_, (const float*)p_X, D_, SH);

    // out = h + Xb @ out_proj  (fp32)
    MMop<<<dim3(D_/128, NTOK/128), 128, SM1>>>((const __nv_bfloat16*)p_Xb, D_,
        (const __nv_bfloat16*)p_opw, 0, D_, out, D_, h, D_, D_);

    k_lb<<<1, 32>>>(out, out_size);
}

// round 6
// speedup vs baseline: 6.1768x; 1.0119x over previous
#include <cuda_runtime.h>
#include <cuda_bf16.h>
#include <math.h>
#include <stdint.h>

// ---------------- problem constants ----------------
#define D_      2048
#define NTOK    8192
#define LAT     256
#define NEXP    32
#define EH      1024
#define SH      2048
#define ATOT    (NTOK*4)
#define ATOTP   (ATOT + NEXP*128)   // 36864
#define MAXTILES (ATOTP/128)        // 288
#define KCAT    (LAT + SH)          // 2304

#define BM 128
#define BN 128
#define BK 64
#define STG 2

// ---------------- device scratch ----------------
__device__ float g_hnorm [NTOK*D_];
__device__ __nv_bfloat16 g_hnorm_bf[NTOK*D_];
__device__ float g_scores[NTOK*NEXP];
__device__ __nv_bfloat16 g_latent_bf[NTOK*LAT];
__device__ __nv_bfloat16 g_ACTb[(size_t)ATOTP*EH];
__device__ float g_contrib[(size_t)ATOTP*LAT];
__device__ __nv_bfloat16 g_cat[(size_t)NTOK*KCAT];     // [eout | ACTS]
__device__ __nv_bfloat16 g_Xb[(size_t)NTOK*D_];
__device__ float g_gate  [NTOK];
__device__ float g_Psum  [NEXP];
__device__ int   g_count [NEXP];
__device__ int   g_off   [NEXP+1];
__device__ int   g_cursor[NEXP];
__device__ int   g_tile_e[MAXTILES];
__device__ int   g_tile_r[MAXTILES];
__device__ int   g_ntiles;
__device__ int   g_assign_tok[ATOTP];
__device__ int   g_assign_pos[ATOT];
__device__ int   g_topi[ATOT];
__device__ float g_topw[ATOT];

// bf16 weights
__device__ __nv_bfloat16 g_ldw_bf[(size_t)D_*LAT];
__device__ __nv_bfloat16 g_catW  [(size_t)KCAT*D_];    // [latent_up ; shared_w2]
__device__ __nv_bfloat16 g_ew1_bf[(size_t)NEXP*LAT*2*EH];
__device__ __nv_bfloat16 g_ew2_bf[(size_t)NEXP*EH*LAT];
__device__ __nv_bfloat16 g_sw1_bf[(size_t)D_*2*SH];
__device__ __nv_bfloat16 g_opw_bf[(size_t)D_*D_];

// ---------------- asm helpers ----------------
__device__ __forceinline__ uint32_t s2u(const void* p) {
    uint32_t a;
    asm("{ .reg .u64 t; cvta.to.shared.u64 t, %1; cvt.u32.u64 %0, t; }" : "=r"(a) : "l"(p));
    return a;
}
__device__ __forceinline__ void cp16(uint32_t d, const void* s) {
    asm volatile("cp.async.cg.shared.global [%0], [%1], 16;" :: "r"(d), "l"(s));
}
__device__ __forceinline__ void ldmx4(uint32_t* r, uint32_t a) {
    asm volatile("ldmatrix.sync.aligned.m8n8.x4.shared.b16 {%0,%1,%2,%3}, [%4];"
        : "=r"(r[0]), "=r"(r[1]), "=r"(r[2]), "=r"(r[3]) : "r"(a));
}
__device__ __forceinline__ void ldmx4t(uint32_t* r, uint32_t a) {
    asm volatile("ldmatrix.sync.aligned.m8n8.x4.trans.shared.b16 {%0,%1,%2,%3}, [%4];"
        : "=r"(r[0]), "=r"(r[1]), "=r"(r[2]), "=r"(r[3]) : "r"(a));
}
__device__ __forceinline__ void mma16816(float* c, const uint32_t* a, const uint32_t* b) {
    asm volatile("mma.sync.aligned.m16n8k16.row.col.f32.bf16.bf16.f32 "
        "{%0,%1,%2,%3},{%4,%5,%6,%7},{%8,%9},{%0,%1,%2,%3};"
        : "+f"(c[0]), "+f"(c[1]), "+f"(c[2]), "+f"(c[3])
        : "r"(a[0]), "r"(a[1]), "r"(a[2]), "r"(a[3]), "r"(b[0]), "r"(b[1]));
}

// ---------------- rmsnorm + fused shared gate ----------------
__global__ void k_rmsnorm(const float* __restrict__ h, const float* __restrict__ w,
                          const float* __restrict__ gw)
{
    int n = blockIdx.x;
    const float4* hp = (const float4*)(h + (size_t)n * D_);
    const float4* wp = (const float4*)w;
    const float4* gp = (const float4*)gw;
    float ss = 0.f, gg = 0.f;
    for (int i = threadIdx.x; i < D_/4; i += 256) {
        float4 v = hp[i], wv = wp[i], gv = gp[i];
        ss += v.x*v.x + v.y*v.y + v.z*v.z + v.w*v.w;
        gg += v.x*wv.x*gv.x + v.y*wv.y*gv.y + v.z*wv.z*gv.z + v.w*wv.w*gv.w;
    }
    __shared__ float red[256], red2[256];
    red[threadIdx.x] = ss; red2[threadIdx.x] = gg; __syncthreads();
    for (int s = 128; s; s >>= 1) {
        if (threadIdx.x < s) { red[threadIdx.x] += red[threadIdx.x + s];
                               red2[threadIdx.x] += red2[threadIdx.x + s]; }
        __syncthreads();
    }
    float rs = rsqrtf(red[0] * (1.f / D_) + 1e-6f);
    if (threadIdx.x == 0) g_gate[n] = 1.f / (1.f + expf(-rs * red2[0]));
    float4* op = (float4*)(g_hnorm + (size_t)n * D_);
    __nv_bfloat162* bp = (__nv_bfloat162*)(g_hnorm_bf + (size_t)n * D_);
    for (int i = threadIdx.x; i < D_/4; i += 256) {
        float4 v = hp[i], wv = wp[i];
        v.x *= rs*wv.x; v.y *= rs*wv.y; v.z *= rs*wv.z; v.w *= rs*wv.w;
        op[i] = v;
        bp[i*2+0] = __floats2bfloat162_rn(v.x, v.y);
        bp[i*2+1] = __floats2bfloat162_rn(v.z, v.w);
    }
}

__global__ void k_router(const float* __restrict__ rw, const float* __restrict__ rb)
{
    __shared__ float hs[32][64];
    __shared__ float ws[64][32];
    int n0 = blockIdx.x * 32;
    int tid = threadIdx.x;
    int e = tid & 31, tr = tid >> 5;
    float acc[4] = {0.f,0.f,0.f,0.f};
    for (int k0 = 0; k0 < D_; k0 += 64) {
        #pragma unroll
        for (int i = 0; i < 8; i++) {
            int lin = tid + i*256;
            int t = lin >> 6, k = lin & 63;
            hs[t][k] = g_hnorm[(size_t)(n0 + t)*D_ + k0 + k];
            int kw = lin >> 5, ew = lin & 31;
            ws[kw][ew] = rw[(size_t)(k0 + kw)*NEXP + ew];
        }
        __syncthreads();
        #pragma unroll
        for (int kk = 0; kk < 64; kk++)
            #pragma unroll
            for (int i = 0; i < 4; i++)
                acc[i] += hs[tr + 8*i][kk] * ws[kk][e];
        __syncthreads();
    }
    float bias = rb[e];
    #pragma unroll
    for (int i = 0; i < 4; i++) {
        float v = acc[i] + bias;
        g_scores[(n0 + tr + 8*i)*NEXP + e] = 1.f / (1.f + expf(-v));
    }
}

__global__ void k_topk()
{
    int warp = threadIdx.x >> 5, lane = threadIdx.x & 31;
    int n = blockIdx.x * 8 + warp;
    float s = g_scores[n*NEXP + lane];
    float topv[4]; int topi[4];
    #pragma unroll
    for (int k = 0; k < 4; k++) {
        float v = s; int bi = lane;
        #pragma unroll
        for (int off = 16; off; off >>= 1) {
            float v2 = __shfl_xor_sync(0xffffffffu, v, off);
            int   i2 = __shfl_xor_sync(0xffffffffu, bi, off);
            if (v2 > v || (v2 == v && i2 < bi)) { v = v2; bi = i2; }
        }
        topv[k] = v; topi[k] = bi;
        if (lane == bi) s = -1e30f;
    }
    if (lane == 0) {
        float inv = 1.f / (topv[0]+topv[1]+topv[2]+topv[3] + 1e-8f);
        #pragma unroll
        for (int k = 0; k < 4; k++) {
            g_topw[n*4 + k] = topv[k] * inv;
            g_topi[n*4 + k] = topi[k];
            atomicAdd(&g_count[topi[k]], 1);
        }
    }
}

__global__ void k_colsum()
{
    int e = blockIdx.x;
    float s = 0.f;
    for (int n = threadIdx.x; n < NTOK; n += 256) s += g_scores[n*NEXP + e];
    __shared__ float red[256];
    red[threadIdx.x] = s; __syncthreads();
    for (int st = 128; st; st >>= 1) {
        if (threadIdx.x < st) red[threadIdx.x] += red[threadIdx.x + st];
        __syncthreads();
    }
    if (threadIdx.x == 0) g_Psum[e] = red[0];
}

__global__ void k_offsets()
{
    if (threadIdx.x == 0) {
        int acc = 0, nt = 0;
        for (int e = 0; e < NEXP; e++) {
            g_off[e] = acc; g_cursor[e] = acc;
            int nep = (g_count[e] + 127) & ~127;
            for (int r = 0; r < nep; r += 128) {
                g_tile_e[nt] = e; g_tile_r[nt] = acc + r; nt++;
            }
            acc += nep;
        }
        g_off[NEXP] = acc;
        g_ntiles = nt;
    }
}

__global__ void k_assign()
{
    int n = blockIdx.x * 256 + threadIdx.x;
    if (n >= NTOK) return;
    #pragma unroll
    for (int k = 0; k < 4; k++) {
        int e = g_topi[n*4 + k];
        int pos = atomicAdd(&g_cursor[e], 1);
        g_assign_tok[pos] = n;
        g_assign_pos[n*4 + k] = pos;
    }
}

__global__ void k_combine()
{
    int n = blockIdx.x, c = threadIdx.x;   // 256 threads == LAT
    float acc = 0.f;
    #pragma unroll
    for (int k = 0; k < 4; k++) {
        int pos = g_assign_pos[n*4 + k];
        acc += g_topw[n*4 + k] * g_contrib[(size_t)pos * LAT + c];
    }
    g_cat[(size_t)n * KCAT + c] = __float2bfloat16(acc);
}

__global__ void k_lb(float* out, int out_size)
{
    if (threadIdx.x == 0 && out_size > NTOK * D_) {
        float s = 0.f;
        for (int e = 0; e < NEXP; e++)
            s += ((float)g_count[e] / NTOK) * (g_Psum[e] / NTOK);
        out[NTOK * D_] = (float)NEXP * s * 1e-4f;
    }
}

__global__ void k_cvt(const float* __restrict__ a, __nv_bfloat16* __restrict__ b, long n)
{
    long i = ((long)blockIdx.x*256 + threadIdx.x) * 16;
    if (i >= n) return;
    float4 v0 = *(const float4*)(a + i);
    float4 v1 = *(const float4*)(a + i + 4);
    float4 v2 = *(const float4*)(a + i + 8);
    float4 v3 = *(const float4*)(a + i + 12);
    __nv_bfloat162 o[8];
    o[0] = __floats2bfloat162_rn(v0.x, v0.y);
    o[1] = __floats2bfloat162_rn(v0.z, v0.w);
    o[2] = __floats2bfloat162_rn(v1.x, v1.y);
    o[3] = __floats2bfloat162_rn(v1.z, v1.w);
    o[4] = __floats2bfloat162_rn(v2.x, v2.y);
    o[5] = __floats2bfloat162_rn(v2.z, v2.w);
    o[6] = __floats2bfloat162_rn(v3.x, v3.y);
    o[7] = __floats2bfloat162_rn(v3.z, v3.w);
    *(uint4*)(b + i)     = *(uint4*)&o[0];
    *(uint4*)(b + i + 8) = *(uint4*)&o[4];
}

// ====== DUAL mma GEMM (gate+lin, fused spike): 256 thr, warp 64x32, BK=64, 2-stage ======
template<bool GROUPED, bool GATHER, bool GATED>
__global__ void __launch_bounds__(256)
k_mmdual(const __nv_bfloat16* __restrict__ A, int lda,
         const __nv_bfloat16* __restrict__ Bt, long bstride, int ldb,
         __nv_bfloat16* __restrict__ Cout, int ldc,
         const float* __restrict__ vth, int HID, int K)
{
    extern __shared__ __align__(16) char smem[];
    __shared__ int s_tok[BM];

    const int tid = threadIdx.x;
    const int lane = tid & 31;
    const int wid = tid >> 5;
    const int wm = wid >> 2, wn = wid & 3;

    int e = 0, r0, n0;
    if (GROUPED) {
        int bt = blockIdx.x;
        if (bt >= g_ntiles) return;
        e = g_tile_e[bt]; r0 = g_tile_r[bt]; n0 = blockIdx.y * BN;
    } else {
        r0 = blockIdx.y * BM; n0 = blockIdx.x * BN;
    }
    const __nv_bfloat16* B = Bt + (GROUPED ? (size_t)e * bstride : 0);

    const uint32_t sb = s2u(smem);
    const uint32_t LDA_B = (BK + 8) * 2;   // 144
    const uint32_t LDB_B = (BN + 8) * 2;   // 272
    const uint32_t A_ST = BM * LDA_B;      // 18432
    const uint32_t B_ST = BK * LDB_B;      // 17408
    const uint32_t bOff  = STG * A_ST;
    const uint32_t b2Off = STG * (A_ST + B_ST);

    if (GATHER) {
        if (tid < BM) s_tok[tid] = g_assign_tok[r0 + tid];
        __syncthreads();
    }

    const int nk = K / BK;

    auto issue = [&](int kt) {
        int st = kt & 1;
        uint32_t sa  = sb + st * A_ST;
        uint32_t sbb = sb + bOff + st * B_ST;
        uint32_t sb2 = sb + b2Off + st * B_ST;
        #pragma unroll
        for (int i = 0; i < 4; i++) {
            int lin = i*256 + tid;
            int row = lin >> 3, c8 = (lin & 7) * 8;
            const __nv_bfloat16* src = GATHER
                ? A + (size_t)s_tok[row]*lda + kt*BK + c8
                : A + (size_t)(r0 + row)*lda + kt*BK + c8;
            cp16(sa + row*LDA_B + c8*2, src);
        }
        #pragma unroll
        for (int i = 0; i < 4; i++) {
            int lin = i*256 + tid;
            int row = lin >> 4, c8 = (lin & 15) * 8;
            cp16(sbb + row*LDB_B + c8*2, B + (size_t)(kt*BK + row)*ldb + n0 + c8);
            cp16(sb2 + row*LDB_B + c8*2, B + (size_t)(kt*BK + row)*ldb + (n0 + HID) + c8);
        }
        asm volatile("cp.async.commit_group;" ::: "memory");
    };

    float acc [4][4][4], acc2[4][4][4];
    #pragma unroll
    for (int i = 0; i < 4; i++)
        #pragma unroll
        for (int j = 0; j < 4; j++)
            #pragma unroll
            for (int t = 0; t < 4; t++) { acc[i][j][t] = 0.f; acc2[i][j][t] = 0.f; }

    issue(0);

    for (int kt = 0; kt < nk; kt++) {
        asm volatile("cp.async.wait_group 0;" ::: "memory");
        __syncthreads();
        if (kt + 1 < nk) issue(kt + 1);

        int st = kt & 1;
        uint32_t sa  = sb + st * A_ST;
        uint32_t sbb = sb + bOff + st * B_ST;
        uint32_t sb2 = sb + b2Off + st * B_ST;

        #pragma unroll
        for (int k16 = 0; k16 < BK/16; k16++) {
            uint32_t a[4][4];
            #pragma unroll
            for (int mi = 0; mi < 4; mi++) {
                uint32_t addr = sa + (wm*64 + mi*16 + (lane & 15))*LDA_B
                                   + (k16*16 + (lane >> 4)*8)*2;
                ldmx4(a[mi], addr);
            }
            uint32_t b[4][2], b2[4][2];
            #pragma unroll
            for (int nj = 0; nj < 2; nj++) {
                uint32_t addr = sbb + (k16*16 + (lane & 15))*LDB_B
                                    + (wn*32 + nj*16 + (lane >> 4)*8)*2;
                uint32_t r[4]; ldmx4t(r, addr);
                b[nj*2][0] = r[0]; b[nj*2][1] = r[1];
                b[nj*2+1][0] = r[2]; b[nj*2+1][1] = r[3];
                uint32_t addr2 = sb2 + (k16*16 + (lane & 15))*LDB_B
                                     + (wn*32 + nj*16 + (lane >> 4)*8)*2;
                uint32_t r2[4]; ldmx4t(r2, addr2);
                b2[nj*2][0] = r2[0]; b2[nj*2][1] = r2[1];
                b2[nj*2+1][0] = r2[2]; b2[nj*2+1][1] = r2[3];
            }
            #pragma unroll
            for (int mi = 0; mi < 4; mi++)
                #pragma unroll
                for (int n8 = 0; n8 < 4; n8++) {
                    mma16816(acc[mi][n8], a[mi], b[n8]);
                    mma16816(acc2[mi][n8], a[mi], b2[n8]);
                }
        }
    }

    const int rbase = r0 + wm*64;
    const int cbase = wn*32;
    const float* vthE = vth + (GROUPED ? (size_t)e * HID : 0);
    #pragma unroll
    for (int mi = 0; mi < 4; mi++) {
        int r = rbase + mi*16 + (lane >> 2);
        float gs0 = GATED ? g_gate[r]     : 1.f;
        float gs1 = GATED ? g_gate[r + 8] : 1.f;
        #pragma unroll
        for (int n8 = 0; n8 < 4; n8++) {
            int c = n0 + cbase + n8*8 + (lane & 3)*2;
            float v0 = vthE[c], v1 = vthE[c + 1];
            float o0 = (acc[mi][n8][0] >= v0 ? v0 : 0.f) * acc2[mi][n8][0] * gs0;
            float o1 = (acc[mi][n8][1] >= v1 ? v1 : 0.f) * acc2[mi][n8][1] * gs0;
            float o2 = (acc[mi][n8][2] >= v0 ? v0 : 0.f) * acc2[mi][n8][2] * gs1;
            float o3 = (acc[mi][n8][3] >= v1 ? v1 : 0.f) * acc2[mi][n8][3] * gs1;
            *(__nv_bfloat162*)(Cout + (size_t)r*ldc + c)     = __floats2bfloat162_rn(o0, o1);
            *(__nv_bfloat162*)(Cout + (size_t)(r+8)*ldc + c) = __floats2bfloat162_rn(o2, o3);
        }
    }
}

// ====== non-dual mma GEMM: 128 thr, 4 warps (2x2), warp 64x64, BK=64, 2-stage ======
template<bool GROUPED, bool RESID, bool OUTBF>
__global__ void __launch_bounds__(128)
k_mm64(const __nv_bfloat16* __restrict__ A, int lda,
       const __nv_bfloat16* __restrict__ Bt, long bstride, int ldb,
       void* __restrict__ Cout, int ldc,
       const float* __restrict__ resid, int ldr, int K)
{
    extern __shared__ __align__(16) char smem[];

    const int tid = threadIdx.x;
    const int lane = tid & 31;
    const int wid = tid >> 5;
    const int wm = wid >> 1, wn = wid & 1;

    int e = 0, r0, n0;
    if (GROUPED) {
        int bt = blockIdx.x;
        if (bt >= g_ntiles) return;
        e = g_tile_e[bt]; r0 = g_tile_r[bt]; n0 = blockIdx.y * BN;
    } else {
        r0 = blockIdx.y * BM; n0 = blockIdx.x * BN;
    }
    const __nv_bfloat16* B = Bt + (GROUPED ? (size_t)e * bstride : 0);

    const uint32_t sb = s2u(smem);
    const uint32_t LDA_B = (BK + 8) * 2;
    const uint32_t LDB_B = (BN + 8) * 2;
    const uint32_t A_ST = BM * LDA_B;
    const uint32_t B_ST = BK * LDB_B;
    const uint32_t bOff = STG * A_ST;

    const int nk = K / BK;

    auto issue = [&](int kt) {
        int st = kt & 1;
        uint32_t sa  = sb + st * A_ST;
        uint32_t sbb = sb + bOff + st * B_ST;
        #pragma unroll
        for (int i = 0; i < 8; i++) {
            int lin = i*128 + tid;
            int row = lin >> 3, c8 = (lin & 7) * 8;
            cp16(sa + row*LDA_B + c8*2, A + (size_t)(r0 + row)*lda + kt*BK + c8);
        }
        #pragma unroll
        for (int i = 0; i < 8; i++) {
            int lin = i*128 + tid;
            int row = lin >> 4, c8 = (lin & 15) * 8;
            cp16(sbb + row*LDB_B + c8*2, B + (size_t)(kt*BK + row)*ldb + n0 + c8);
        }
        asm volatile("cp.async.commit_group;" ::: "memory");
    };

    float acc[4][8][4];
    #pragma unroll
    for (int i = 0; i < 4; i++)
        #pragma unroll
        for (int j = 0; j < 8; j++)
            #pragma unroll
            for (int t = 0; t < 4; t++) acc[i][j][t] = 0.f;

    issue(0);

    for (int kt = 0; kt < nk; kt++) {
        asm volatile("cp.async.wait_group 0;" ::: "memory");
        __syncthreads();
        if (kt + 1 < nk) issue(kt + 1);

        int st = kt & 1;
        uint32_t sa  = sb + st * A_ST;
        uint32_t sbb = sb + bOff + st * B_ST;

        #pragma unroll
        for (int k16 = 0; k16 < BK/16; k16++) {
            uint32_t a[4][4];
            #pragma unroll
            for (int mi = 0; mi < 4; mi++) {
                uint32_t addr = sa + (wm*64 + mi*16 + (lane & 15))*LDA_B
                                   + (k16*16 + (lane >> 4)*8)*2;
                ldmx4(a[mi], addr);
            }
            uint32_t b[8][2];
            #pragma unroll
            for (int nj = 0; nj < 4; nj++) {
                uint32_t addr = sbb + (k16*16 + (lane & 15))*LDB_B
                                    + (wn*64 + nj*16 + (lane >> 4)*8)*2;
                uint32_t r[4]; ldmx4t(r, addr);
                b[nj*2][0] = r[0]; b[nj*2][1] = r[1];
                b[nj*2+1][0] = r[2]; b[nj*2+1][1] = r[3];
            }
            #pragma unroll
            for (int mi = 0; mi < 4; mi++)
                #pragma unroll
                for (int n8 = 0; n8 < 8; n8++)
                    mma16816(acc[mi][n8], a[mi], b[n8]);
        }
    }

    const int rbase = r0 + wm*64;
    const int cbase = wn*64;
    #pragma unroll
    for (int mi = 0; mi < 4; mi++) {
        int r = rbase + mi*16 + (lane >> 2);
        #pragma unroll
        for (int n8 = 0; n8 < 8; n8++) {
            int c = n0 + cbase + n8*8 + (lane & 3)*2;
            float o0 = acc[mi][n8][0], o1 = acc[mi][n8][1];
            float o2 = acc[mi][n8][2], o3 = acc[mi][n8][3];
            if (RESID) {
                float2 r0v = *(const float2*)(resid + (size_t)r*ldr + c);
                float2 r1v = *(const float2*)(resid + (size_t)(r+8)*ldr + c);
                o0 += r0v.x; o1 += r0v.y; o2 += r1v.x; o3 += r1v.y;
            }
            if (OUTBF) {
                __nv_bfloat16* op = (__nv_bfloat16*)Cout;
                *(__nv_bfloat162*)(op + (size_t)r*ldc + c)     = __floats2bfloat162_rn(o0, o1);
                *(__nv_bfloat162*)(op + (size_t)(r+8)*ldc + c) = __floats2bfloat162_rn(o2, o3);
            } else {
                float* op = (float*)Cout;
                *(float2*)(op + (size_t)r*ldc + c)     = make_float2(o0, o1);
                *(float2*)(op + (size_t)(r+8)*ldc + c) = make_float2(o2, o3);
            }
        }
    }
}

// ---------------- launch ----------------
static inline int cvtGrid(long n) { return (int)((n/16 + 255) / 256); }

extern "C" void kernel_launch(void* const* d_in, const int* in_sizes, int n_in,
                              void* d_out, int out_size)
{
    const float* h         = (const float*)d_in[0];
    const float* norm_w    = (const float*)d_in[1];
    const float* latent_dw = (const float*)d_in[2];
    const float* latent_uw = (const float*)d_in[3];
    const float* router_w  = (const float*)d_in[4];
    const float* router_b  = (const float*)d_in[5];
    const float* ew1       = (const float*)d_in[6];
    const float* evth      = (const float*)d_in[7];
    const float* ew2       = (const float*)d_in[8];
    const float* sw1       = (const float*)d_in[9];
    const float* svth      = (const float*)d_in[10];
    const float* sw2       = (const float*)d_in[11];
    const float* sgw       = (const float*)d_in[12];
    const float* opw       = (const float*)d_in[13];
    float* out = (float*)d_out;

    auto MMe1 = k_mmdual<true , true , false>;  // exp1 fused spike -> ACTb
    auto MMs1 = k_mmdual<false, false, true >;  // shared_w1 fused spike*gate -> g_cat[:,256:]
    auto MMld = k_mm64<false, false, true >;    // latent_down -> latent bf16
    auto MMe2 = k_mm64<true , false, false>;    // exp2 -> contrib fp32
    auto MMct = k_mm64<false, false, true >;    // cat-GEMM -> Xb bf16
    auto MMop = k_mm64<false, true , false>;    // out_proj + h -> out fp32

    const uint32_t A_ST = BM*(BK+8)*2, B_ST = BK*(BN+8)*2;
    const int SM1 = STG*(A_ST + B_ST);          // 71680
    const int SM2 = STG*(A_ST + 2*B_ST);        // 106496
    cudaFuncSetAttribute(MMe1, cudaFuncAttributeMaxDynamicSharedMemorySize, SM2);
    cudaFuncSetAttribute(MMs1, cudaFuncAttributeMaxDynamicSharedMemorySize, SM2);
    cudaFuncSetAttribute(MMld, cudaFuncAttributeMaxDynamicSharedMemorySize, SM1);
    cudaFuncSetAttribute(MMe2, cudaFuncAttributeMaxDynamicSharedMemorySize, SM1);
    cudaFuncSetAttribute(MMct, cudaFuncAttributeMaxDynamicSharedMemorySize, SM1);
    cudaFuncSetAttribute(MMop, cudaFuncAttributeMaxDynamicSharedMemorySize, SM1);

    void *p_count, *p_atok, *p_hbf, *p_lbf, *p_ACTb, *p_contrib, *p_cat, *p_Xb;
    void *p_ldw, *p_catW, *p_ew1, *p_ew2, *p_sw1, *p_opw;
    cudaGetSymbolAddress(&p_count, g_count);
    cudaGetSymbolAddress(&p_atok,  g_assign_tok);
    cudaGetSymbolAddress(&p_hbf,   g_hnorm_bf);
    cudaGetSymbolAddress(&p_lbf,   g_latent_bf);
    cudaGetSymbolAddress(&p_ACTb,  g_ACTb);
    cudaGetSymbolAddress(&p_contrib, g_contrib);
    cudaGetSymbolAddress(&p_cat,   g_cat);
    cudaGetSymbolAddress(&p_Xb,    g_Xb);
    cudaGetSymbolAddress(&p_ldw,   g_ldw_bf);
    cudaGetSymbolAddress(&p_catW,  g_catW);
    cudaGetSymbolAddress(&p_ew1,   g_ew1_bf);
    cudaGetSymbolAddress(&p_ew2,   g_ew2_bf);
    cudaGetSymbolAddress(&p_sw1,   g_sw1_bf);
    cudaGetSymbolAddress(&p_opw,   g_opw_bf);

    // --- launches 1-5: rmsnorm + the conversions MMs1 needs (ncu -s 5 lands on #6) ---
    k_rmsnorm<<<NTOK, 256>>>(h, norm_w, sgw);                                       // 1
    k_cvt<<<cvtGrid((long)D_*2*SH), 256>>>(sw1, (__nv_bfloat16*)p_sw1, (long)D_*2*SH);          // 2
    k_cvt<<<cvtGrid((long)D_*LAT), 256>>>(latent_dw, (__nv_bfloat16*)p_ldw, (long)D_*LAT);      // 3
    k_cvt<<<cvtGrid((long)LAT*D_), 256>>>(latent_uw, (__nv_bfloat16*)p_catW, (long)LAT*D_);     // 4
    k_cvt<<<cvtGrid((long)NEXP*LAT*2*EH), 256>>>(ew1, (__nv_bfloat16*)p_ew1, (long)NEXP*LAT*2*EH); // 5

    // --- launch 6: the big DUAL shared_w1 GEMM (profiling target) ---
    MMs1<<<dim3(SH/128, NTOK/128), 256, SM2>>>((const __nv_bfloat16*)p_hbf, D_,     // 6
        (const __nv_bfloat16*)p_sw1, 0, 2*SH,
        (__nv_bfloat16*)p_cat + LAT, KCAT, svth, SH, D_);

    // --- remaining conversions / routing ---
    k_cvt<<<cvtGrid((long)NEXP*EH*LAT), 256>>>(ew2, (__nv_bfloat16*)p_ew2, (long)NEXP*EH*LAT);
    k_cvt<<<cvtGrid((long)SH*D_), 256>>>(sw2, (__nv_bfloat16*)p_catW + (size_t)LAT*D_, (long)SH*D_);
    k_cvt<<<cvtGrid((long)D_*D_), 256>>>(opw, (__nv_bfloat16*)p_opw, (long)D_*D_);

    cudaMemsetAsync(p_count, 0, NEXP * sizeof(int));
    cudaMemsetAsync(p_atok,  0, ATOTP * sizeof(int));

    k_router <<<NTOK/32, 256>>>(router_w, router_b);
    k_topk   <<<NTOK/8, 256>>>();
    k_colsum <<<NEXP, 256>>>();
    k_offsets<<<1, 32>>>();
    k_assign <<<NTOK/256, 256>>>();

    // latent = hnorm @ latent_down  -> bf16
    MMld<<<dim3(LAT/128, NTOK/128), 128, SM1>>>((const __nv_bfloat16*)p_hbf, D_,
        (const __nv_bfloat16*)p_ldw, 0, LAT, p_lbf, LAT, nullptr, 0, D_);

    // exp1 fused spike -> ACTb bf16
    MMe1<<<dim3(MAXTILES, EH/128), 256, SM2>>>((const __nv_bfloat16*)p_lbf, LAT,
        (const __nv_bfloat16*)p_ew1, (long)LAT*2*EH, 2*EH,
        (__nv_bfloat16*)p_ACTb, EH, evth, EH, LAT);

    // exp2 -> contrib fp32
    MMe2<<<dim3(MAXTILES, LAT/128), 128, SM1>>>((const __nv_bfloat16*)p_ACTb, EH,
        (const __nv_bfloat16*)p_ew2, (long)EH*LAT, LAT, p_contrib, LAT, nullptr, 0, EH);

    k_combine<<<NTOK, LAT>>>();

    // Xb = bf16([eout|ACTS] @ [latent_up; shared_w2])   K=2304
    MMct<<<dim3(D_/128, NTOK/128), 128, SM1>>>((const __nv_bfloat16*)p_cat, KCAT,
        (const __nv_bfloat16*)p_catW, 0, D_, p_Xb, D_, nullptr, 0, KCAT);

    // out = h + Xb @ out_proj  (fp32)
    MMop<<<dim3(D_/128, NTOK/128), 128, SM1>>>((const __nv_bfloat16*)p_Xb, D_,
        (const __nv_bfloat16*)p_opw, 0, D_, out, D_, h, D_, D_);

    k_lb<<<1, 32>>>(out, out_size);
}

// round 7
// speedup vs baseline: 6.8040x; 1.1015x over previous
#include <cuda_runtime.h>
#include <cuda_bf16.h>
#include <math.h>
#include <stdint.h>

// ---------------- problem constants ----------------
#define D_      2048
#define NTOK    8192
#define LAT     256
#define NEXP    32
#define EH      1024
#define SH      2048
#define ATOT    (NTOK*4)
#define ATOTP   (ATOT + NEXP*128)   // 36864
#define MAXTILES (ATOTP/128)        // 288
#define KCAT    (LAT + SH)          // 2304

#define BM 128
#define BN 128
#define BK 64
#define STG 3          // non-dual stages
#define DSTG 2         // dual stages
#define BND 64         // dual per-set N tile

// ---------------- device scratch ----------------
__device__ float g_hnorm [NTOK*D_];
__device__ __nv_bfloat16 g_hnorm_bf[NTOK*D_];
__device__ float g_scores[NTOK*NEXP];
__device__ __nv_bfloat16 g_latent_bf[NTOK*LAT];
__device__ __nv_bfloat16 g_ACTb[(size_t)ATOTP*EH];
__device__ float g_contrib[(size_t)ATOTP*LAT];
__device__ __nv_bfloat16 g_cat[(size_t)NTOK*KCAT];     // [eout | ACTS]
__device__ __nv_bfloat16 g_Xb[(size_t)NTOK*D_];
__device__ float g_gate  [NTOK];
__device__ float g_Psum  [NEXP];
__device__ int   g_count [NEXP];
__device__ int   g_off   [NEXP+1];
__device__ int   g_cursor[NEXP];
__device__ int   g_tile_e[MAXTILES];
__device__ int   g_tile_r[MAXTILES];
__device__ int   g_ntiles;
__device__ int   g_assign_tok[ATOTP];
__device__ int   g_assign_pos[ATOT];
__device__ int   g_topi[ATOT];
__device__ float g_topw[ATOT];

// bf16 weights
__device__ __nv_bfloat16 g_ldw_bf[(size_t)D_*LAT];
__device__ __nv_bfloat16 g_catW  [(size_t)KCAT*D_];    // [latent_up ; shared_w2]
__device__ __nv_bfloat16 g_ew1_bf[(size_t)NEXP*LAT*2*EH];
__device__ __nv_bfloat16 g_ew2_bf[(size_t)NEXP*EH*LAT];
__device__ __nv_bfloat16 g_sw1_bf[(size_t)D_*2*SH];
__device__ __nv_bfloat16 g_opw_bf[(size_t)D_*D_];

// ---------------- asm helpers ----------------
__device__ __forceinline__ uint32_t s2u(const void* p) {
    uint32_t a;
    asm("{ .reg .u64 t; cvta.to.shared.u64 t, %1; cvt.u32.u64 %0, t; }" : "=r"(a) : "l"(p));
    return a;
}
__device__ __forceinline__ void cp16(uint32_t d, const void* s) {
    asm volatile("cp.async.cg.shared.global [%0], [%1], 16;" :: "r"(d), "l"(s));
}
__device__ __forceinline__ void ldmx4(uint32_t* r, uint32_t a) {
    asm volatile("ldmatrix.sync.aligned.m8n8.x4.shared.b16 {%0,%1,%2,%3}, [%4];"
        : "=r"(r[0]), "=r"(r[1]), "=r"(r[2]), "=r"(r[3]) : "r"(a));
}
__device__ __forceinline__ void ldmx4t(uint32_t* r, uint32_t a) {
    asm volatile("ldmatrix.sync.aligned.m8n8.x4.trans.shared.b16 {%0,%1,%2,%3}, [%4];"
        : "=r"(r[0]), "=r"(r[1]), "=r"(r[2]), "=r"(r[3]) : "r"(a));
}
__device__ __forceinline__ void mma16816(float* c, const uint32_t* a, const uint32_t* b) {
    asm volatile("mma.sync.aligned.m16n8k16.row.col.f32.bf16.bf16.f32 "
        "{%0,%1,%2,%3},{%4,%5,%6,%7},{%8,%9},{%0,%1,%2,%3};"
        : "+f"(c[0]), "+f"(c[1]), "+f"(c[2]), "+f"(c[3])
        : "r"(a[0]), "r"(a[1]), "r"(a[2]), "r"(a[3]), "r"(b[0]), "r"(b[1]));
}

// ---------------- rmsnorm + fused shared gate ----------------
__global__ void k_rmsnorm(const float* __restrict__ h, const float* __restrict__ w,
                          const float* __restrict__ gw)
{
    int n = blockIdx.x;
    const float4* hp = (const float4*)(h + (size_t)n * D_);
    const float4* wp = (const float4*)w;
    const float4* gp = (const float4*)gw;
    float ss = 0.f, gg = 0.f;
    for (int i = threadIdx.x; i < D_/4; i += 256) {
        float4 v = hp[i], wv = wp[i], gv = gp[i];
        ss += v.x*v.x + v.y*v.y + v.z*v.z + v.w*v.w;
        gg += v.x*wv.x*gv.x + v.y*wv.y*gv.y + v.z*wv.z*gv.z + v.w*wv.w*gv.w;
    }
    __shared__ float red[256], red2[256];
    red[threadIdx.x] = ss; red2[threadIdx.x] = gg; __syncthreads();
    for (int s = 128; s; s >>= 1) {
        if (threadIdx.x < s) { red[threadIdx.x] += red[threadIdx.x + s];
                               red2[threadIdx.x] += red2[threadIdx.x + s]; }
        __syncthreads();
    }
    float rs = rsqrtf(red[0] * (1.f / D_) + 1e-6f);
    if (threadIdx.x == 0) g_gate[n] = 1.f / (1.f + expf(-rs * red2[0]));
    float4* op = (float4*)(g_hnorm + (size_t)n * D_);
    __nv_bfloat162* bp = (__nv_bfloat162*)(g_hnorm_bf + (size_t)n * D_);
    for (int i = threadIdx.x; i < D_/4; i += 256) {
        float4 v = hp[i], wv = wp[i];
        v.x *= rs*wv.x; v.y *= rs*wv.y; v.z *= rs*wv.z; v.w *= rs*wv.w;
        op[i] = v;
        bp[i*2+0] = __floats2bfloat162_rn(v.x, v.y);
        bp[i*2+1] = __floats2bfloat162_rn(v.z, v.w);
    }
}

__global__ void k_router(const float* __restrict__ rw, const float* __restrict__ rb)
{
    __shared__ float hs[32][64];
    __shared__ float ws[64][32];
    int n0 = blockIdx.x * 32;
    int tid = threadIdx.x;
    int e = tid & 31, tr = tid >> 5;
    float acc[4] = {0.f,0.f,0.f,0.f};
    for (int k0 = 0; k0 < D_; k0 += 64) {
        #pragma unroll
        for (int i = 0; i < 8; i++) {
            int lin = tid + i*256;
            int t = lin >> 6, k = lin & 63;
            hs[t][k] = g_hnorm[(size_t)(n0 + t)*D_ + k0 + k];
            int kw = lin >> 5, ew = lin & 31;
            ws[kw][ew] = rw[(size_t)(k0 + kw)*NEXP + ew];
        }
        __syncthreads();
        #pragma unroll
        for (int kk = 0; kk < 64; kk++)
            #pragma unroll
            for (int i = 0; i < 4; i++)
                acc[i] += hs[tr + 8*i][kk] * ws[kk][e];
        __syncthreads();
    }
    float bias = rb[e];
    #pragma unroll
    for (int i = 0; i < 4; i++) {
        float v = acc[i] + bias;
        g_scores[(n0 + tr + 8*i)*NEXP + e] = 1.f / (1.f + expf(-v));
    }
}

__global__ void k_topk()
{
    int warp = threadIdx.x >> 5, lane = threadIdx.x & 31;
    int n = blockIdx.x * 8 + warp;
    float s = g_scores[n*NEXP + lane];
    float topv[4]; int topi[4];
    #pragma unroll
    for (int k = 0; k < 4; k++) {
        float v = s; int bi = lane;
        #pragma unroll
        for (int off = 16; off; off >>= 1) {
            float v2 = __shfl_xor_sync(0xffffffffu, v, off);
            int   i2 = __shfl_xor_sync(0xffffffffu, bi, off);
            if (v2 > v || (v2 == v && i2 < bi)) { v = v2; bi = i2; }
        }
        topv[k] = v; topi[k] = bi;
        if (lane == bi) s = -1e30f;
    }
    if (lane == 0) {
        float inv = 1.f / (topv[0]+topv[1]+topv[2]+topv[3] + 1e-8f);
        #pragma unroll
        for (int k = 0; k < 4; k++) {
            g_topw[n*4 + k] = topv[k] * inv;
            g_topi[n*4 + k] = topi[k];
            atomicAdd(&g_count[topi[k]], 1);
        }
    }
}

__global__ void k_colsum()
{
    int e = blockIdx.x;
    float s = 0.f;
    for (int n = threadIdx.x; n < NTOK; n += 256) s += g_scores[n*NEXP + e];
    __shared__ float red[256];
    red[threadIdx.x] = s; __syncthreads();
    for (int st = 128; st; st >>= 1) {
        if (threadIdx.x < st) red[threadIdx.x] += red[threadIdx.x + st];
        __syncthreads();
    }
    if (threadIdx.x == 0) g_Psum[e] = red[0];
}

__global__ void k_offsets()
{
    if (threadIdx.x == 0) {
        int acc = 0, nt = 0;
        for (int e = 0; e < NEXP; e++) {
            g_off[e] = acc; g_cursor[e] = acc;
            int nep = (g_count[e] + 127) & ~127;
            for (int r = 0; r < nep; r += 128) {
                g_tile_e[nt] = e; g_tile_r[nt] = acc + r; nt++;
            }
            acc += nep;
        }
        g_off[NEXP] = acc;
        g_ntiles = nt;
    }
}

__global__ void k_assign()
{
    int n = blockIdx.x * 256 + threadIdx.x;
    if (n >= NTOK) return;
    #pragma unroll
    for (int k = 0; k < 4; k++) {
        int e = g_topi[n*4 + k];
        int pos = atomicAdd(&g_cursor[e], 1);
        g_assign_tok[pos] = n;
        g_assign_pos[n*4 + k] = pos;
    }
}

__global__ void k_combine()
{
    int n = blockIdx.x, c = threadIdx.x;   // 256 threads == LAT
    float acc = 0.f;
    #pragma unroll
    for (int k = 0; k < 4; k++) {
        int pos = g_assign_pos[n*4 + k];
        acc += g_topw[n*4 + k] * g_contrib[(size_t)pos * LAT + c];
    }
    g_cat[(size_t)n * KCAT + c] = __float2bfloat16(acc);
}

__global__ void k_lb(float* out, int out_size)
{
    if (threadIdx.x == 0 && out_size > NTOK * D_) {
        float s = 0.f;
        for (int e = 0; e < NEXP; e++)
            s += ((float)g_count[e] / NTOK) * (g_Psum[e] / NTOK);
        out[NTOK * D_] = (float)NEXP * s * 1e-4f;
    }
}

__global__ void k_cvt(const float* __restrict__ a, __nv_bfloat16* __restrict__ b, long n)
{
    long i = ((long)blockIdx.x*256 + threadIdx.x) * 16;
    if (i >= n) return;
    float4 v0 = *(const float4*)(a + i);
    float4 v1 = *(const float4*)(a + i + 4);
    float4 v2 = *(const float4*)(a + i + 8);
    float4 v3 = *(const float4*)(a + i + 12);
    __nv_bfloat162 o[8];
    o[0] = __floats2bfloat162_rn(v0.x, v0.y);
    o[1] = __floats2bfloat162_rn(v0.z, v0.w);
    o[2] = __floats2bfloat162_rn(v1.x, v1.y);
    o[3] = __floats2bfloat162_rn(v1.z, v1.w);
    o[4] = __floats2bfloat162_rn(v2.x, v2.y);
    o[5] = __floats2bfloat162_rn(v2.z, v2.w);
    o[6] = __floats2bfloat162_rn(v3.x, v3.y);
    o[7] = __floats2bfloat162_rn(v3.z, v3.w);
    *(uint4*)(b + i)     = *(uint4*)&o[0];
    *(uint4*)(b + i + 8) = *(uint4*)&o[4];
}

// ====== DUAL mma GEMM (gate+lin, fused spike): 128 thr, 4 warps (2x2), warp 64x32 dual,
//        BN=64 per set, BK=64, 2-stage. 2 CTAs/SM. ======
template<bool GROUPED, bool GATHER, bool GATED>
__global__ void __launch_bounds__(128)
k_mmdual(const __nv_bfloat16* __restrict__ A, int lda,
         const __nv_bfloat16* __restrict__ Bt, long bstride, int ldb,
         __nv_bfloat16* __restrict__ Cout, int ldc,
         const float* __restrict__ vth, int HID, int K)
{
    extern __shared__ __align__(16) char smem[];
    __shared__ int s_tok[BM];

    const int tid = threadIdx.x;
    const int lane = tid & 31;
    const int wid = tid >> 5;
    const int wm = wid >> 1, wn = wid & 1;

    int e = 0, r0, n0;
    if (GROUPED) {
        int bt = blockIdx.x;
        if (bt >= g_ntiles) return;
        e = g_tile_e[bt]; r0 = g_tile_r[bt]; n0 = blockIdx.y * BND;
    } else {
        r0 = blockIdx.y * BM; n0 = blockIdx.x * BND;
    }
    const __nv_bfloat16* B = Bt + (GROUPED ? (size_t)e * bstride : 0);

    const uint32_t sb = s2u(smem);
    const uint32_t LDA_B = (BK + 8) * 2;    // 144
    const uint32_t LDB_B = (BND + 8) * 2;   // 144
    const uint32_t A_ST = BM * LDA_B;       // 18432
    const uint32_t B_ST = BK * LDB_B;       // 9216
    const uint32_t bOff  = DSTG * A_ST;
    const uint32_t b2Off = DSTG * (A_ST + B_ST);

    if (GATHER) {
        s_tok[tid] = g_assign_tok[r0 + tid];
        __syncthreads();
    }

    const int nk = K / BK;

    auto issue = [&](int kt) {
        int st = kt & 1;
        uint32_t sa  = sb + st * A_ST;
        uint32_t sbb = sb + bOff + st * B_ST;
        uint32_t sb2 = sb + b2Off + st * B_ST;
        #pragma unroll
        for (int i = 0; i < 8; i++) {
            int lin = i*128 + tid;
            int row = lin >> 3, c8 = (lin & 7) * 8;
            const __nv_bfloat16* src = GATHER
                ? A + (size_t)s_tok[row]*lda + kt*BK + c8
                : A + (size_t)(r0 + row)*lda + kt*BK + c8;
            cp16(sa + row*LDA_B + c8*2, src);
        }
        #pragma unroll
        for (int i = 0; i < 4; i++) {
            int lin = i*128 + tid;
            int row = lin >> 3, c8 = (lin & 7) * 8;
            cp16(sbb + row*LDB_B + c8*2, B + (size_t)(kt*BK + row)*ldb + n0 + c8);
            cp16(sb2 + row*LDB_B + c8*2, B + (size_t)(kt*BK + row)*ldb + (n0 + HID) + c8);
        }
        asm volatile("cp.async.commit_group;" ::: "memory");
    };

    float acc [4][4][4], acc2[4][4][4];
    #pragma unroll
    for (int i = 0; i < 4; i++)
        #pragma unroll
        for (int j = 0; j < 4; j++)
            #pragma unroll
            for (int t = 0; t < 4; t++) { acc[i][j][t] = 0.f; acc2[i][j][t] = 0.f; }

    issue(0);

    for (int kt = 0; kt < nk; kt++) {
        asm volatile("cp.async.wait_group 0;" ::: "memory");
        __syncthreads();
        if (kt + 1 < nk) issue(kt + 1);

        int st = kt & 1;
        uint32_t sa  = sb + st * A_ST;
        uint32_t sbb = sb + bOff + st * B_ST;
        uint32_t sb2 = sb + b2Off + st * B_ST;

        #pragma unroll
        for (int k16 = 0; k16 < BK/16; k16++) {
            uint32_t a[4][4];
            #pragma unroll
            for (int mi = 0; mi < 4; mi++) {
                uint32_t addr = sa + (wm*64 + mi*16 + (lane & 15))*LDA_B
                                   + (k16*16 + (lane >> 4)*8)*2;
                ldmx4(a[mi], addr);
            }
            uint32_t b[4][2], b2[4][2];
            #pragma unroll
            for (int nj = 0; nj < 2; nj++) {
                uint32_t addr = sbb + (k16*16 + (lane & 15))*LDB_B
                                    + (wn*32 + nj*16 + (lane >> 4)*8)*2;
                uint32_t r[4]; ldmx4t(r, addr);
                b[nj*2][0] = r[0]; b[nj*2][1] = r[1];
                b[nj*2+1][0] = r[2]; b[nj*2+1][1] = r[3];
                uint32_t addr2 = sb2 + (k16*16 + (lane & 15))*LDB_B
                                     + (wn*32 + nj*16 + (lane >> 4)*8)*2;
                uint32_t r2[4]; ldmx4t(r2, addr2);
                b2[nj*2][0] = r2[0]; b2[nj*2][1] = r2[1];
                b2[nj*2+1][0] = r2[2]; b2[nj*2+1][1] = r2[3];
            }
            #pragma unroll
            for (int mi = 0; mi < 4; mi++)
                #pragma unroll
                for (int n8 = 0; n8 < 4; n8++) {
                    mma16816(acc[mi][n8], a[mi], b[n8]);
                    mma16816(acc2[mi][n8], a[mi], b2[n8]);
                }
        }
    }

    const int rbase = r0 + wm*64;
    const int cbase = wn*32;
    const float* vthE = vth + (GROUPED ? (size_t)e * HID : 0);
    #pragma unroll
    for (int mi = 0; mi < 4; mi++) {
        int r = rbase + mi*16 + (lane >> 2);
        float gs0 = GATED ? g_gate[r]     : 1.f;
        float gs1 = GATED ? g_gate[r + 8] : 1.f;
        #pragma unroll
        for (int n8 = 0; n8 < 4; n8++) {
            int c = n0 + cbase + n8*8 + (lane & 3)*2;
            float v0 = vthE[c], v1 = vthE[c + 1];
            float o0 = (acc[mi][n8][0] >= v0 ? v0 : 0.f) * acc2[mi][n8][0] * gs0;
            float o1 = (acc[mi][n8][1] >= v1 ? v1 : 0.f) * acc2[mi][n8][1] * gs0;
            float o2 = (acc[mi][n8][2] >= v0 ? v0 : 0.f) * acc2[mi][n8][2] * gs1;
            float o3 = (acc[mi][n8][3] >= v1 ? v1 : 0.f) * acc2[mi][n8][3] * gs1;
            *(__nv_bfloat162*)(Cout + (size_t)r*ldc + c)     = __floats2bfloat162_rn(o0, o1);
            *(__nv_bfloat162*)(Cout + (size_t)(r+8)*ldc + c) = __floats2bfloat162_rn(o2, o3);
        }
    }
}

// ====== non-dual mma GEMM: 128 thr, 4 warps (2x2), warp 64x64, BK=64, 3-stage ======
template<bool GROUPED, bool RESID, bool OUTBF>
__global__ void __launch_bounds__(128)
k_mm64(const __nv_bfloat16* __restrict__ A, int lda,
       const __nv_bfloat16* __restrict__ Bt, long bstride, int ldb,
       void* __restrict__ Cout, int ldc,
       const float* __restrict__ resid, int ldr, int K)
{
    extern __shared__ __align__(16) char smem[];

    const int tid = threadIdx.x;
    const int lane = tid & 31;
    const int wid = tid >> 5;
    const int wm = wid >> 1, wn = wid & 1;

    int e = 0, r0, n0;
    if (GROUPED) {
        int bt = blockIdx.x;
        if (bt >= g_ntiles) return;
        e = g_tile_e[bt]; r0 = g_tile_r[bt]; n0 = blockIdx.y * BN;
    } else {
        r0 = blockIdx.y * BM; n0 = blockIdx.x * BN;
    }
    const __nv_bfloat16* B = Bt + (GROUPED ? (size_t)e * bstride : 0);

    const uint32_t sb = s2u(smem);
    const uint32_t LDA_B = (BK + 8) * 2;
    const uint32_t LDB_B = (BN + 8) * 2;
    const uint32_t A_ST = BM * LDA_B;
    const uint32_t B_ST = BK * LDB_B;
    const uint32_t bOff = STG * A_ST;

    const int nk = K / BK;

    auto issue = [&](int kt) {
        int st = kt % STG;
        uint32_t sa  = sb + st * A_ST;
        uint32_t sbb = sb + bOff + st * B_ST;
        #pragma unroll
        for (int i = 0; i < 8; i++) {
            int lin = i*128 + tid;
            int row = lin >> 3, c8 = (lin & 7) * 8;
            cp16(sa + row*LDA_B + c8*2, A + (size_t)(r0 + row)*lda + kt*BK + c8);
        }
        #pragma unroll
        for (int i = 0; i < 8; i++) {
            int lin = i*128 + tid;
            int row = lin >> 4, c8 = (lin & 15) * 8;
            cp16(sbb + row*LDB_B + c8*2, B + (size_t)(kt*BK + row)*ldb + n0 + c8);
        }
        asm volatile("cp.async.commit_group;" ::: "memory");
    };

    float acc[4][8][4];
    #pragma unroll
    for (int i = 0; i < 4; i++)
        #pragma unroll
        for (int j = 0; j < 8; j++)
            #pragma unroll
            for (int t = 0; t < 4; t++) acc[i][j][t] = 0.f;

    issue(0);
    if (nk > 1) issue(1);

    for (int kt = 0; kt < nk; kt++) {
        if (kt + 2 < nk) asm volatile("cp.async.wait_group 1;" ::: "memory");
        else             asm volatile("cp.async.wait_group 0;" ::: "memory");
        __syncthreads();
        if (kt + 2 < nk) issue(kt + 2);

        int st = kt % STG;
        uint32_t sa  = sb + st * A_ST;
        uint32_t sbb = sb + bOff + st * B_ST;

        #pragma unroll
        for (int k16 = 0; k16 < BK/16; k16++) {
            uint32_t a[4][4];
            #pragma unroll
            for (int mi = 0; mi < 4; mi++) {
                uint32_t addr = sa + (wm*64 + mi*16 + (lane & 15))*LDA_B
                                   + (k16*16 + (lane >> 4)*8)*2;
                ldmx4(a[mi], addr);
            }
            uint32_t b[8][2];
            #pragma unroll
            for (int nj = 0; nj < 4; nj++) {
                uint32_t addr = sbb + (k16*16 + (lane & 15))*LDB_B
                                    + (wn*64 + nj*16 + (lane >> 4)*8)*2;
                uint32_t r[4]; ldmx4t(r, addr);
                b[nj*2][0] = r[0]; b[nj*2][1] = r[1];
                b[nj*2+1][0] = r[2]; b[nj*2+1][1] = r[3];
            }
            #pragma unroll
            for (int mi = 0; mi < 4; mi++)
                #pragma unroll
                for (int n8 = 0; n8 < 8; n8++)
                    mma16816(acc[mi][n8], a[mi], b[n8]);
        }
    }

    const int rbase = r0 + wm*64;
    const int cbase = wn*64;
    #pragma unroll
    for (int mi = 0; mi < 4; mi++) {
        int r = rbase + mi*16 + (lane >> 2);
        #pragma unroll
        for (int n8 = 0; n8 < 8; n8++) {
            int c = n0 + cbase + n8*8 + (lane & 3)*2;
            float o0 = acc[mi][n8][0], o1 = acc[mi][n8][1];
            float o2 = acc[mi][n8][2], o3 = acc[mi][n8][3];
            if (RESID) {
                float2 r0v = *(const float2*)(resid + (size_t)r*ldr + c);
                float2 r1v = *(const float2*)(resid + (size_t)(r+8)*ldr + c);
                o0 += r0v.x; o1 += r0v.y; o2 += r1v.x; o3 += r1v.y;
            }
            if (OUTBF) {
                __nv_bfloat16* op = (__nv_bfloat16*)Cout;
                *(__nv_bfloat162*)(op + (size_t)r*ldc + c)     = __floats2bfloat162_rn(o0, o1);
                *(__nv_bfloat162*)(op + (size_t)(r+8)*ldc + c) = __floats2bfloat162_rn(o2, o3);
            } else {
                float* op = (float*)Cout;
                *(float2*)(op + (size_t)r*ldc + c)     = make_float2(o0, o1);
                *(float2*)(op + (size_t)(r+8)*ldc + c) = make_float2(o2, o3);
            }
        }
    }
}

// ---------------- launch ----------------
static inline int cvtGrid(long n) { return (int)((n/16 + 255) / 256); }

extern "C" void kernel_launch(void* const* d_in, const int* in_sizes, int n_in,
                              void* d_out, int out_size)
{
    const float* h         = (const float*)d_in[0];
    const float* norm_w    = (const float*)d_in[1];
    const float* latent_dw = (const float*)d_in[2];
    const float* latent_uw = (const float*)d_in[3];
    const float* router_w  = (const float*)d_in[4];
    const float* router_b  = (const float*)d_in[5];
    const float* ew1       = (const float*)d_in[6];
    const float* evth      = (const float*)d_in[7];
    const float* ew2       = (const float*)d_in[8];
    const float* sw1       = (const float*)d_in[9];
    const float* svth      = (const float*)d_in[10];
    const float* sw2       = (const float*)d_in[11];
    const float* sgw       = (const float*)d_in[12];
    const float* opw       = (const float*)d_in[13];
    float* out = (float*)d_out;

    auto MMe1 = k_mmdual<true , true , false>;  // exp1 fused spike -> ACTb
    auto MMs1 = k_mmdual<false, false, true >;  // shared_w1 fused spike*gate -> g_cat[:,256:]
    auto MMld = k_mm64<false, false, true >;    // latent_down -> latent bf16
    auto MMe2 = k_mm64<true , false, false>;    // exp2 -> contrib fp32
    auto MMct = k_mm64<false, false, true >;    // cat-GEMM -> Xb bf16
    auto MMop = k_mm64<false, true , false>;    // out_proj + h -> out fp32

    const uint32_t A_ST  = BM*(BK+8)*2;         // 18432
    const uint32_t B_ST  = BK*(BN+8)*2;         // 17408
    const uint32_t BD_ST = BK*(BND+8)*2;        // 9216
    const int SM1 = STG*(A_ST + B_ST);          // 107520
    const int SM2 = DSTG*(A_ST + 2*BD_ST);      // 73728
    cudaFuncSetAttribute(MMe1, cudaFuncAttributeMaxDynamicSharedMemorySize, SM2);
    cudaFuncSetAttribute(MMs1, cudaFuncAttributeMaxDynamicSharedMemorySize, SM2);
    cudaFuncSetAttribute(MMld, cudaFuncAttributeMaxDynamicSharedMemorySize, SM1);
    cudaFuncSetAttribute(MMe2, cudaFuncAttributeMaxDynamicSharedMemorySize, SM1);
    cudaFuncSetAttribute(MMct, cudaFuncAttributeMaxDynamicSharedMemorySize, SM1);
    cudaFuncSetAttribute(MMop, cudaFuncAttributeMaxDynamicSharedMemorySize, SM1);

    void *p_count, *p_atok, *p_hbf, *p_lbf, *p_ACTb, *p_contrib, *p_cat, *p_Xb;
    void *p_ldw, *p_catW, *p_ew1, *p_ew2, *p_sw1, *p_opw;
    cudaGetSymbolAddress(&p_count, g_count);
    cudaGetSymbolAddress(&p_atok,  g_assign_tok);
    cudaGetSymbolAddress(&p_hbf,   g_hnorm_bf);
    cudaGetSymbolAddress(&p_lbf,   g_latent_bf);
    cudaGetSymbolAddress(&p_ACTb,  g_ACTb);
    cudaGetSymbolAddress(&p_contrib, g_contrib);
    cudaGetSymbolAddress(&p_cat,   g_cat);
    cudaGetSymbolAddress(&p_Xb,    g_Xb);
    cudaGetSymbolAddress(&p_ldw,   g_ldw_bf);
    cudaGetSymbolAddress(&p_catW,  g_catW);
    cudaGetSymbolAddress(&p_ew1,   g_ew1_bf);
    cudaGetSymbolAddress(&p_ew2,   g_ew2_bf);
    cudaGetSymbolAddress(&p_sw1,   g_sw1_bf);
    cudaGetSymbolAddress(&p_opw,   g_opw_bf);

    // --- launches 1-5 ---
    k_rmsnorm<<<NTOK, 256>>>(h, norm_w, sgw);
    k_cvt<<<cvtGrid((long)D_*2*SH), 256>>>(sw1, (__nv_bfloat16*)p_sw1, (long)D_*2*SH);
    k_cvt<<<cvtGrid((long)D_*LAT), 256>>>(latent_dw, (__nv_bfloat16*)p_ldw, (long)D_*LAT);
    k_cvt<<<cvtGrid((long)LAT*D_), 256>>>(latent_uw, (__nv_bfloat16*)p_catW, (long)LAT*D_);
    k_cvt<<<cvtGrid((long)NEXP*LAT*2*EH), 256>>>(ew1, (__nv_bfloat16*)p_ew1, (long)NEXP*LAT*2*EH);

    // --- launch 6: big DUAL shared_w1 GEMM ---
    MMs1<<<dim3(SH/BND, NTOK/128), 128, SM2>>>((const __nv_bfloat16*)p_hbf, D_,
        (const __nv_bfloat16*)p_sw1, 0, 2*SH,
        (__nv_bfloat16*)p_cat + LAT, KCAT, svth, SH, D_);

    // --- remaining conversions / routing ---
    k_cvt<<<cvtGrid((long)NEXP*EH*LAT), 256>>>(ew2, (__nv_bfloat16*)p_ew2, (long)NEXP*EH*LAT);
    k_cvt<<<cvtGrid((long)SH*D_), 256>>>(sw2, (__nv_bfloat16*)p_catW + (size_t)LAT*D_, (long)SH*D_);
    k_cvt<<<cvtGrid((long)D_*D_), 256>>>(opw, (__nv_bfloat16*)p_opw, (long)D_*D_);

    cudaMemsetAsync(p_count, 0, NEXP * sizeof(int));
    cudaMemsetAsync(p_atok,  0, ATOTP * sizeof(int));

    k_router <<<NTOK/32, 256>>>(router_w, router_b);
    k_topk   <<<NTOK/8, 256>>>();
    k_colsum <<<NEXP, 256>>>();
    k_offsets<<<1, 32>>>();
    k_assign <<<NTOK/256, 256>>>();

    // latent = hnorm @ latent_down  -> bf16
    MMld<<<dim3(LAT/128, NTOK/128), 128, SM1>>>((const __nv_bfloat16*)p_hbf, D_,
        (const __nv_bfloat16*)p_ldw, 0, LAT, p_lbf, LAT, nullptr, 0, D_);

    // exp1 fused spike -> ACTb bf16
    MMe1<<<dim3(MAXTILES, EH/BND), 128, SM2>>>((const __nv_bfloat16*)p_lbf, LAT,
        (const __nv_bfloat16*)p_ew1, (long)LAT*2*EH, 2*EH,
        (__nv_bfloat16*)p_ACTb, EH, evth, EH, LAT);

    // exp2 -> contrib fp32
    MMe2<<<dim3(MAXTILES, LAT/128), 128, SM1>>>((const __nv_bfloat16*)p_ACTb, EH,
        (const __nv_bfloat16*)p_ew2, (long)EH*LAT, LAT, p_contrib, LAT, nullptr, 0, EH);

    k_combine<<<NTOK, LAT>>>();

    // Xb = bf16([eout|ACTS] @ [latent_up; shared_w2])   K=2304
    MMct<<<dim3(D_/128, NTOK/128), 128, SM1>>>((const __nv_bfloat16*)p_cat, KCAT,
        (const __nv_bfloat16*)p_catW, 0, D_, p_Xb, D_, nullptr, 0, KCAT);

    // out = h + Xb @ out_proj  (fp32)
    MMop<<<dim3(D_/128, NTOK/128), 128, SM1>>>((const __nv_bfloat16*)p_Xb, D_,
        (const __nv_bfloat16*)p_opw, 0, D_, out, D_, h, D_, D_);

    k_lb<<<1, 32>>>(out, out_size);
}

// round 8
// speedup vs baseline: 7.6038x; 1.1175x over previous
#include <cuda_runtime.h>
#include <cuda_bf16.h>
#include <math.h>
#include <stdint.h>

// ---------------- problem constants ----------------
#define D_      2048
#define NTOK    8192
#define LAT     256
#define NEXP    32
#define EH      1024
#define SH      2048
#define ATOT    (NTOK*4)
#define ATOTP   (ATOT + NEXP*128)   // 36864
#define MAXTILES (ATOTP/128)        // 288
#define KCAT    (LAT + SH)          // 2304

#define BM 128
#define BN 128
#define BK 64
#define STG 3          // non-dual stages
#define DSTG 2         // dual stages
#define BND 64         // dual per-set N tile

// ---------------- device scratch ----------------
__device__ __nv_bfloat16 g_hnorm_bf[NTOK*D_];
__device__ float g_rrms  [NTOK];
__device__ float g_scores[NTOK*NEXP];
__device__ __nv_bfloat16 g_latent_bf[NTOK*LAT];
__device__ __nv_bfloat16 g_ACTb[(size_t)ATOTP*EH];
__device__ float g_contrib[(size_t)ATOTP*LAT];
__device__ __nv_bfloat16 g_cat[(size_t)NTOK*KCAT];     // [eout | ACTS]
__device__ float g_gate  [NTOK];
__device__ float g_Psum  [NEXP];
__device__ int   g_count [NEXP];
__device__ int   g_off   [NEXP+1];
__device__ int   g_cursor[NEXP];
__device__ int   g_tile_e[MAXTILES];
__device__ int   g_tile_r[MAXTILES];
__device__ int   g_ntiles;
__device__ int   g_assign_tok[ATOTP];
__device__ int   g_assign_pos[ATOT];
__device__ int   g_topi[ATOT];
__device__ float g_topw[ATOT];

// bf16 weights
__device__ __nv_bfloat16 g_ldw_bf[(size_t)D_*LAT];
__device__ __nv_bfloat16 g_catW  [(size_t)KCAT*D_];    // [latent_up ; shared_w2]
__device__ __nv_bfloat16 g_Wcomb [(size_t)KCAT*D_];    // catW @ opw (bf16)
__device__ __nv_bfloat16 g_ew1_bf[(size_t)NEXP*LAT*2*EH];
__device__ __nv_bfloat16 g_ew2_bf[(size_t)NEXP*EH*LAT];
__device__ __nv_bfloat16 g_sw1_bf[(size_t)D_*2*SH];
__device__ __nv_bfloat16 g_opw_bf[(size_t)D_*D_];

// ---------------- asm helpers ----------------
__device__ __forceinline__ uint32_t s2u(const void* p) {
    uint32_t a;
    asm("{ .reg .u64 t; cvta.to.shared.u64 t, %1; cvt.u32.u64 %0, t; }" : "=r"(a) : "l"(p));
    return a;
}
__device__ __forceinline__ void cp16(uint32_t d, const void* s) {
    asm volatile("cp.async.cg.shared.global [%0], [%1], 16;" :: "r"(d), "l"(s));
}
__device__ __forceinline__ void ldmx4(uint32_t* r, uint32_t a) {
    asm volatile("ldmatrix.sync.aligned.m8n8.x4.shared.b16 {%0,%1,%2,%3}, [%4];"
        : "=r"(r[0]), "=r"(r[1]), "=r"(r[2]), "=r"(r[3]) : "r"(a));
}
__device__ __forceinline__ void ldmx4t(uint32_t* r, uint32_t a) {
    asm volatile("ldmatrix.sync.aligned.m8n8.x4.trans.shared.b16 {%0,%1,%2,%3}, [%4];"
        : "=r"(r[0]), "=r"(r[1]), "=r"(r[2]), "=r"(r[3]) : "r"(a));
}
__device__ __forceinline__ void mma16816(float* c, const uint32_t* a, const uint32_t* b) {
    asm volatile("mma.sync.aligned.m16n8k16.row.col.f32.bf16.bf16.f32 "
        "{%0,%1,%2,%3},{%4,%5,%6,%7},{%8,%9},{%0,%1,%2,%3};"
        : "+f"(c[0]), "+f"(c[1]), "+f"(c[2]), "+f"(c[3])
        : "r"(a[0]), "r"(a[1]), "r"(a[2]), "r"(a[3]), "r"(b[0]), "r"(b[1]));
}

// ---------------- rmsnorm: bf16 hnorm + rrms + fused shared gate ----------------
__global__ void k_rmsnorm(const float* __restrict__ h, const float* __restrict__ w,
                          const float* __restrict__ gw)
{
    int n = blockIdx.x;
    const float4* hp = (const float4*)(h + (size_t)n * D_);
    const float4* wp = (const float4*)w;
    const float4* gp = (const float4*)gw;
    float ss = 0.f, gg = 0.f;
    for (int i = threadIdx.x; i < D_/4; i += 256) {
        float4 v = hp[i], wv = wp[i], gv = gp[i];
        ss += v.x*v.x + v.y*v.y + v.z*v.z + v.w*v.w;
        gg += v.x*wv.x*gv.x + v.y*wv.y*gv.y + v.z*wv.z*gv.z + v.w*wv.w*gv.w;
    }
    __shared__ float red[256], red2[256];
    red[threadIdx.x] = ss; red2[threadIdx.x] = gg; __syncthreads();
    for (int s = 128; s; s >>= 1) {
        if (threadIdx.x < s) { red[threadIdx.x] += red[threadIdx.x + s];
                               red2[threadIdx.x] += red2[threadIdx.x + s]; }
        __syncthreads();
    }
    float rs = rsqrtf(red[0] * (1.f / D_) + 1e-6f);
    if (threadIdx.x == 0) {
        g_gate[n] = 1.f / (1.f + expf(-rs * red2[0]));
        g_rrms[n] = rs;
    }
    __nv_bfloat162* bp = (__nv_bfloat162*)(g_hnorm_bf + (size_t)n * D_);
    for (int i = threadIdx.x; i < D_/4; i += 256) {
        float4 v = hp[i], wv = wp[i];
        v.x *= rs*wv.x; v.y *= rs*wv.y; v.z *= rs*wv.z; v.w *= rs*wv.w;
        bp[i*2+0] = __floats2bfloat162_rn(v.x, v.y);
        bp[i*2+1] = __floats2bfloat162_rn(v.z, v.w);
    }
}

// ---------------- router: recomputes hnorm = h*(rrms*w) in fp32 (bit-identical) ----------------
__global__ void k_router(const float* __restrict__ h, const float* __restrict__ rw,
                         const float* __restrict__ rb, const float* __restrict__ nw)
{
    __shared__ float hs[32][64];
    __shared__ float ws[64][32];
    __shared__ float s_r[32];
    int n0 = blockIdx.x * 32;
    int tid = threadIdx.x;
    int e = tid & 31, tr = tid >> 5;
    if (tid < 32) s_r[tid] = g_rrms[n0 + tid];
    __syncthreads();
    float acc[4] = {0.f,0.f,0.f,0.f};
    for (int k0 = 0; k0 < D_; k0 += 64) {
        #pragma unroll
        for (int i = 0; i < 8; i++) {
            int lin = tid + i*256;
            int t = lin >> 6, k = lin & 63;
            hs[t][k] = h[(size_t)(n0 + t)*D_ + k0 + k] * (s_r[t] * nw[k0 + k]);
            int kw = lin >> 5, ew = lin & 31;
            ws[kw][ew] = rw[(size_t)(k0 + kw)*NEXP + ew];
        }
        __syncthreads();
        #pragma unroll
        for (int kk = 0; kk < 64; kk++)
            #pragma unroll
            for (int i = 0; i < 4; i++)
                acc[i] += hs[tr + 8*i][kk] * ws[kk][e];
        __syncthreads();
    }
    float bias = rb[e];
    #pragma unroll
    for (int i = 0; i < 4; i++) {
        float v = acc[i] + bias;
        g_scores[(n0 + tr + 8*i)*NEXP + e] = 1.f / (1.f + expf(-v));
    }
}

__global__ void k_topk()
{
    int warp = threadIdx.x >> 5, lane = threadIdx.x & 31;
    int n = blockIdx.x * 8 + warp;
    float s = g_scores[n*NEXP + lane];
    float topv[4]; int topi[4];
    #pragma unroll
    for (int k = 0; k < 4; k++) {
        float v = s; int bi = lane;
        #pragma unroll
        for (int off = 16; off; off >>= 1) {
            float v2 = __shfl_xor_sync(0xffffffffu, v, off);
            int   i2 = __shfl_xor_sync(0xffffffffu, bi, off);
            if (v2 > v || (v2 == v && i2 < bi)) { v = v2; bi = i2; }
        }
        topv[k] = v; topi[k] = bi;
        if (lane == bi) s = -1e30f;
    }
    if (lane == 0) {
        float inv = 1.f / (topv[0]+topv[1]+topv[2]+topv[3] + 1e-8f);
        #pragma unroll
        for (int k = 0; k < 4; k++) {
            g_topw[n*4 + k] = topv[k] * inv;
            g_topi[n*4 + k] = topi[k];
            atomicAdd(&g_count[topi[k]], 1);
        }
    }
}

__global__ void k_colsum()
{
    int e = blockIdx.x;
    float s = 0.f;
    for (int n = threadIdx.x; n < NTOK; n += 256) s += g_scores[n*NEXP + e];
    __shared__ float red[256];
    red[threadIdx.x] = s; __syncthreads();
    for (int st = 128; st; st >>= 1) {
        if (threadIdx.x < st) red[threadIdx.x] += red[threadIdx.x + st];
        __syncthreads();
    }
    if (threadIdx.x == 0) g_Psum[e] = red[0];
}

__global__ void k_offsets()
{
    if (threadIdx.x == 0) {
        int acc = 0, nt = 0;
        for (int e = 0; e < NEXP; e++) {
            g_off[e] = acc; g_cursor[e] = acc;
            int nep = (g_count[e] + 127) & ~127;
            for (int r = 0; r < nep; r += 128) {
                g_tile_e[nt] = e; g_tile_r[nt] = acc + r; nt++;
            }
            acc += nep;
        }
        g_off[NEXP] = acc;
        g_ntiles = nt;
    }
}

__global__ void k_assign()
{
    int n = blockIdx.x * 256 + threadIdx.x;
    if (n >= NTOK) return;
    #pragma unroll
    for (int k = 0; k < 4; k++) {
        int e = g_topi[n*4 + k];
        int pos = atomicAdd(&g_cursor[e], 1);
        g_assign_tok[pos] = n;
        g_assign_pos[n*4 + k] = pos;
    }
}

__global__ void k_combine()
{
    int n = blockIdx.x, c = threadIdx.x;   // 256 threads == LAT
    float acc = 0.f;
    #pragma unroll
    for (int k = 0; k < 4; k++) {
        int pos = g_assign_pos[n*4 + k];
        acc += g_topw[n*4 + k] * g_contrib[(size_t)pos * LAT + c];
    }
    g_cat[(size_t)n * KCAT + c] = __float2bfloat16(acc);
}

__global__ void k_lb(float* out, int out_size)
{
    if (threadIdx.x == 0 && out_size > NTOK * D_) {
        float s = 0.f;
        for (int e = 0; e < NEXP; e++)
            s += ((float)g_count[e] / NTOK) * (g_Psum[e] / NTOK);
        out[NTOK * D_] = (float)NEXP * s * 1e-4f;
    }
}

__global__ void k_cvt(const float* __restrict__ a, __nv_bfloat16* __restrict__ b, long n)
{
    long i = ((long)blockIdx.x*256 + threadIdx.x) * 16;
    if (i >= n) return;
    float4 v0 = *(const float4*)(a + i);
    float4 v1 = *(const float4*)(a + i + 4);
    float4 v2 = *(const float4*)(a + i + 8);
    float4 v3 = *(const float4*)(a + i + 12);
    __nv_bfloat162 o[8];
    o[0] = __floats2bfloat162_rn(v0.x, v0.y);
    o[1] = __floats2bfloat162_rn(v0.z, v0.w);
    o[2] = __floats2bfloat162_rn(v1.x, v1.y);
    o[3] = __floats2bfloat162_rn(v1.z, v1.w);
    o[4] = __floats2bfloat162_rn(v2.x, v2.y);
    o[5] = __floats2bfloat162_rn(v2.z, v2.w);
    o[6] = __floats2bfloat162_rn(v3.x, v3.y);
    o[7] = __floats2bfloat162_rn(v3.z, v3.w);
    *(uint4*)(b + i)     = *(uint4*)&o[0];
    *(uint4*)(b + i + 8) = *(uint4*)&o[4];
}

// ====== DUAL mma GEMM (gate+lin, fused spike): 128 thr, 2x2 warps, 64x32 dual, BK=64, 2-stage ======
template<bool GROUPED, bool GATHER, bool GATED>
__global__ void __launch_bounds__(128)
k_mmdual(const __nv_bfloat16* __restrict__ A, int lda,
         const __nv_bfloat16* __restrict__ Bt, long bstride, int ldb,
         __nv_bfloat16* __restrict__ Cout, int ldc,
         const float* __restrict__ vth, int HID, int K)
{
    extern __shared__ __align__(16) char smem[];
    __shared__ int s_tok[BM];

    const int tid = threadIdx.x;
    const int lane = tid & 31;
    const int wid = tid >> 5;
    const int wm = wid >> 1, wn = wid & 1;

    int e = 0, r0, n0;
    if (GROUPED) {
        int bt = blockIdx.x;
        if (bt >= g_ntiles) return;
        e = g_tile_e[bt]; r0 = g_tile_r[bt]; n0 = blockIdx.y * BND;
    } else {
        r0 = blockIdx.y * BM; n0 = blockIdx.x * BND;
    }
    const __nv_bfloat16* B = Bt + (GROUPED ? (size_t)e * bstride : 0);

    const uint32_t sb = s2u(smem);
    const uint32_t LDA_B = (BK + 8) * 2;    // 144
    const uint32_t LDB_B = (BND + 8) * 2;   // 144
    const uint32_t A_ST = BM * LDA_B;       // 18432
    const uint32_t B_ST = BK * LDB_B;       // 9216
    const uint32_t bOff  = DSTG * A_ST;
    const uint32_t b2Off = DSTG * (A_ST + B_ST);

    if (GATHER) {
        s_tok[tid] = g_assign_tok[r0 + tid];
        __syncthreads();
    }

    const int nk = K / BK;

    auto issue = [&](int kt) {
        int st = kt & 1;
        uint32_t sa  = sb + st * A_ST;
        uint32_t sbb = sb + bOff + st * B_ST;
        uint32_t sb2 = sb + b2Off + st * B_ST;
        #pragma unroll
        for (int i = 0; i < 8; i++) {
            int lin = i*128 + tid;
            int row = lin >> 3, c8 = (lin & 7) * 8;
            const __nv_bfloat16* src = GATHER
                ? A + (size_t)s_tok[row]*lda + kt*BK + c8
                : A + (size_t)(r0 + row)*lda + kt*BK + c8;
            cp16(sa + row*LDA_B + c8*2, src);
        }
        #pragma unroll
        for (int i = 0; i < 4; i++) {
            int lin = i*128 + tid;
            int row = lin >> 3, c8 = (lin & 7) * 8;
            cp16(sbb + row*LDB_B + c8*2, B + (size_t)(kt*BK + row)*ldb + n0 + c8);
            cp16(sb2 + row*LDB_B + c8*2, B + (size_t)(kt*BK + row)*ldb + (n0 + HID) + c8);
        }
        asm volatile("cp.async.commit_group;" ::: "memory");
    };

    float acc [4][4][4], acc2[4][4][4];
    #pragma unroll
    for (int i = 0; i < 4; i++)
        #pragma unroll
        for (int j = 0; j < 4; j++)
            #pragma unroll
            for (int t = 0; t < 4; t++) { acc[i][j][t] = 0.f; acc2[i][j][t] = 0.f; }

    issue(0);

    for (int kt = 0; kt < nk; kt++) {
        asm volatile("cp.async.wait_group 0;" ::: "memory");
        __syncthreads();
        if (kt + 1 < nk) issue(kt + 1);

        int st = kt & 1;
        uint32_t sa  = sb + st * A_ST;
        uint32_t sbb = sb + bOff + st * B_ST;
        uint32_t sb2 = sb + b2Off + st * B_ST;

        #pragma unroll
        for (int k16 = 0; k16 < BK/16; k16++) {
            uint32_t a[4][4];
            #pragma unroll
            for (int mi = 0; mi < 4; mi++) {
                uint32_t addr = sa + (wm*64 + mi*16 + (lane & 15))*LDA_B
                                   + (k16*16 + (lane >> 4)*8)*2;
                ldmx4(a[mi], addr);
            }
            uint32_t b[4][2], b2[4][2];
            #pragma unroll
            for (int nj = 0; nj < 2; nj++) {
                uint32_t addr = sbb + (k16*16 + (lane & 15))*LDB_B
                                    + (wn*32 + nj*16 + (lane >> 4)*8)*2;
                uint32_t r[4]; ldmx4t(r, addr);
                b[nj*2][0] = r[0]; b[nj*2][1] = r[1];
                b[nj*2+1][0] = r[2]; b[nj*2+1][1] = r[3];
                uint32_t addr2 = sb2 + (k16*16 + (lane & 15))*LDB_B
                                     + (wn*32 + nj*16 + (lane >> 4)*8)*2;
                uint32_t r2[4]; ldmx4t(r2, addr2);
                b2[nj*2][0] = r2[0]; b2[nj*2][1] = r2[1];
                b2[nj*2+1][0] = r2[2]; b2[nj*2+1][1] = r2[3];
            }
            #pragma unroll
            for (int mi = 0; mi < 4; mi++)
                #pragma unroll
                for (int n8 = 0; n8 < 4; n8++) {
                    mma16816(acc[mi][n8], a[mi], b[n8]);
                    mma16816(acc2[mi][n8], a[mi], b2[n8]);
                }
        }
    }

    const int rbase = r0 + wm*64;
    const int cbase = wn*32;
    const float* vthE = vth + (GROUPED ? (size_t)e * HID : 0);
    #pragma unroll
    for (int mi = 0; mi < 4; mi++) {
        int r = rbase + mi*16 + (lane >> 2);
        float gs0 = GATED ? g_gate[r]     : 1.f;
        float gs1 = GATED ? g_gate[r + 8] : 1.f;
        #pragma unroll
        for (int n8 = 0; n8 < 4; n8++) {
            int c = n0 + cbase + n8*8 + (lane & 3)*2;
            float v0 = vthE[c], v1 = vthE[c + 1];
            float o0 = (acc[mi][n8][0] >= v0 ? v0 : 0.f) * acc2[mi][n8][0] * gs0;
            float o1 = (acc[mi][n8][1] >= v1 ? v1 : 0.f) * acc2[mi][n8][1] * gs0;
            float o2 = (acc[mi][n8][2] >= v0 ? v0 : 0.f) * acc2[mi][n8][2] * gs1;
            float o3 = (acc[mi][n8][3] >= v1 ? v1 : 0.f) * acc2[mi][n8][3] * gs1;
            *(__nv_bfloat162*)(Cout + (size_t)r*ldc + c)     = __floats2bfloat162_rn(o0, o1);
            *(__nv_bfloat162*)(Cout + (size_t)(r+8)*ldc + c) = __floats2bfloat162_rn(o2, o3);
        }
    }
}

// ====== non-dual mma GEMM: 128 thr, 4 warps (2x2), warp 64x64, BK=64, 3-stage ======
template<bool GROUPED, bool RESID, bool OUTBF>
__global__ void __launch_bounds__(128)
k_mm64(const __nv_bfloat16* __restrict__ A, int lda,
       const __nv_bfloat16* __restrict__ Bt, long bstride, int ldb,
       void* __restrict__ Cout, int ldc,
       const float* __restrict__ resid, int ldr, int K)
{
    extern __shared__ __align__(16) char smem[];

    const int tid = threadIdx.x;
    const int lane = tid & 31;
    const int wid = tid >> 5;
    const int wm = wid >> 1, wn = wid & 1;

    int e = 0, r0, n0;
    if (GROUPED) {
        int bt = blockIdx.x;
        if (bt >= g_ntiles) return;
        e = g_tile_e[bt]; r0 = g_tile_r[bt]; n0 = blockIdx.y * BN;
    } else {
        r0 = blockIdx.y * BM; n0 = blockIdx.x * BN;
    }
    const __nv_bfloat16* B = Bt + (GROUPED ? (size_t)e * bstride : 0);

    const uint32_t sb = s2u(smem);
    const uint32_t LDA_B = (BK + 8) * 2;
    const uint32_t LDB_B = (BN + 8) * 2;
    const uint32_t A_ST = BM * LDA_B;
    const uint32_t B_ST = BK * LDB_B;
    const uint32_t bOff = STG * A_ST;

    const int nk = K / BK;

    auto issue = [&](int kt) {
        int st = kt % STG;
        uint32_t sa  = sb + st * A_ST;
        uint32_t sbb = sb + bOff + st * B_ST;
        #pragma unroll
        for (int i = 0; i < 8; i++) {
            int lin = i*128 + tid;
            int row = lin >> 3, c8 = (lin & 7) * 8;
            cp16(sa + row*LDA_B + c8*2, A + (size_t)(r0 + row)*lda + kt*BK + c8);
        }
        #pragma unroll
        for (int i = 0; i < 8; i++) {
            int lin = i*128 + tid;
            int row = lin >> 4, c8 = (lin & 15) * 8;
            cp16(sbb + row*LDB_B + c8*2, B + (size_t)(kt*BK + row)*ldb + n0 + c8);
        }
        asm volatile("cp.async.commit_group;" ::: "memory");
    };

    float acc[4][8][4];
    #pragma unroll
    for (int i = 0; i < 4; i++)
        #pragma unroll
        for (int j = 0; j < 8; j++)
            #pragma unroll
            for (int t = 0; t < 4; t++) acc[i][j][t] = 0.f;

    issue(0);
    if (nk > 1) issue(1);

    for (int kt = 0; kt < nk; kt++) {
        if (kt + 2 < nk) asm volatile("cp.async.wait_group 1;" ::: "memory");
        else             asm volatile("cp.async.wait_group 0;" ::: "memory");
        __syncthreads();
        if (kt + 2 < nk) issue(kt + 2);

        int st = kt % STG;
        uint32_t sa  = sb + st * A_ST;
        uint32_t sbb = sb + bOff + st * B_ST;

        #pragma unroll
        for (int k16 = 0; k16 < BK/16; k16++) {
            uint32_t a[4][4];
            #pragma unroll
            for (int mi = 0; mi < 4; mi++) {
                uint32_t addr = sa + (wm*64 + mi*16 + (lane & 15))*LDA_B
                                   + (k16*16 + (lane >> 4)*8)*2;
                ldmx4(a[mi], addr);
            }
            uint32_t b[8][2];
            #pragma unroll
            for (int nj = 0; nj < 4; nj++) {
                uint32_t addr = sbb + (k16*16 + (lane & 15))*LDB_B
                                    + (wn*64 + nj*16 + (lane >> 4)*8)*2;
                uint32_t r[4]; ldmx4t(r, addr);
                b[nj*2][0] = r[0]; b[nj*2][1] = r[1];
                b[nj*2+1][0] = r[2]; b[nj*2+1][1] = r[3];
            }
            #pragma unroll
            for (int mi = 0; mi < 4; mi++)
                #pragma unroll
                for (int n8 = 0; n8 < 8; n8++)
                    mma16816(acc[mi][n8], a[mi], b[n8]);
        }
    }

    const int rbase = r0 + wm*64;
    const int cbase = wn*64;
    #pragma unroll
    for (int mi = 0; mi < 4; mi++) {
        int r = rbase + mi*16 + (lane >> 2);
        #pragma unroll
        for (int n8 = 0; n8 < 8; n8++) {
            int c = n0 + cbase + n8*8 + (lane & 3)*2;
            float o0 = acc[mi][n8][0], o1 = acc[mi][n8][1];
            float o2 = acc[mi][n8][2], o3 = acc[mi][n8][3];
            if (RESID) {
                float2 r0v = *(const float2*)(resid + (size_t)r*ldr + c);
                float2 r1v = *(const float2*)(resid + (size_t)(r+8)*ldr + c);
                o0 += r0v.x; o1 += r0v.y; o2 += r1v.x; o3 += r1v.y;
            }
            if (OUTBF) {
                __nv_bfloat16* op = (__nv_bfloat16*)Cout;
                *(__nv_bfloat162*)(op + (size_t)r*ldc + c)     = __floats2bfloat162_rn(o0, o1);
                *(__nv_bfloat162*)(op + (size_t)(r+8)*ldc + c) = __floats2bfloat162_rn(o2, o3);
            } else {
                float* op = (float*)Cout;
                *(float2*)(op + (size_t)r*ldc + c)     = make_float2(o0, o1);
                *(float2*)(op + (size_t)(r+8)*ldc + c) = make_float2(o2, o3);
            }
        }
    }
}

// ---------------- launch ----------------
static inline int cvtGrid(long n) { return (int)((n/16 + 255) / 256); }

extern "C" void kernel_launch(void* const* d_in, const int* in_sizes, int n_in,
                              void* d_out, int out_size)
{
    const float* h         = (const float*)d_in[0];
    const float* norm_w    = (const float*)d_in[1];
    const float* latent_dw = (const float*)d_in[2];
    const float* latent_uw = (const float*)d_in[3];
    const float* router_w  = (const float*)d_in[4];
    const float* router_b  = (const float*)d_in[5];
    const float* ew1       = (const float*)d_in[6];
    const float* evth      = (const float*)d_in[7];
    const float* ew2       = (const float*)d_in[8];
    const float* sw1       = (const float*)d_in[9];
    const float* svth      = (const float*)d_in[10];
    const float* sw2       = (const float*)d_in[11];
    const float* sgw       = (const float*)d_in[12];
    const float* opw       = (const float*)d_in[13];
    float* out = (float*)d_out;

    auto MMe1 = k_mmdual<true , true , false>;  // exp1 fused spike -> ACTb
    auto MMs1 = k_mmdual<false, false, true >;  // shared_w1 fused spike*gate -> g_cat[:,256:]
    auto MMld = k_mm64<false, false, true >;    // latent_down -> latent bf16
    auto MMe2 = k_mm64<true , false, false>;    // exp2 -> contrib fp32
    auto MMwc = k_mm64<false, false, true >;    // W_comb = catW @ opw -> bf16
    auto MMfin= k_mm64<false, true , false>;    // out = h + cat @ W_comb (fp32)

    const uint32_t A_ST  = BM*(BK+8)*2;         // 18432
    const uint32_t B_ST  = BK*(BN+8)*2;         // 17408
    const uint32_t BD_ST = BK*(BND+8)*2;        // 9216
    const int SM1 = STG*(A_ST + B_ST);          // 107520
    const int SM2 = DSTG*(A_ST + 2*BD_ST);      // 73728
    cudaFuncSetAttribute(MMe1, cudaFuncAttributeMaxDynamicSharedMemorySize, SM2);
    cudaFuncSetAttribute(MMs1, cudaFuncAttributeMaxDynamicSharedMemorySize, SM2);
    cudaFuncSetAttribute(MMld, cudaFuncAttributeMaxDynamicSharedMemorySize, SM1);
    cudaFuncSetAttribute(MMe2, cudaFuncAttributeMaxDynamicSharedMemorySize, SM1);
    cudaFuncSetAttribute(MMwc, cudaFuncAttributeMaxDynamicSharedMemorySize, SM1);
    cudaFuncSetAttribute(MMfin,cudaFuncAttributeMaxDynamicSharedMemorySize, SM1);

    void *p_count, *p_atok, *p_hbf, *p_lbf, *p_ACTb, *p_contrib, *p_cat;
    void *p_ldw, *p_catW, *p_Wcomb, *p_ew1, *p_ew2, *p_sw1, *p_opw;
    cudaGetSymbolAddress(&p_count, g_count);
    cudaGetSymbolAddress(&p_atok,  g_assign_tok);
    cudaGetSymbolAddress(&p_hbf,   g_hnorm_bf);
    cudaGetSymbolAddress(&p_lbf,   g_latent_bf);
    cudaGetSymbolAddress(&p_ACTb,  g_ACTb);
    cudaGetSymbolAddress(&p_contrib, g_contrib);
    cudaGetSymbolAddress(&p_cat,   g_cat);
    cudaGetSymbolAddress(&p_ldw,   g_ldw_bf);
    cudaGetSymbolAddress(&p_catW,  g_catW);
    cudaGetSymbolAddress(&p_Wcomb, g_Wcomb);
    cudaGetSymbolAddress(&p_ew1,   g_ew1_bf);
    cudaGetSymbolAddress(&p_ew2,   g_ew2_bf);
    cudaGetSymbolAddress(&p_sw1,   g_sw1_bf);
    cudaGetSymbolAddress(&p_opw,   g_opw_bf);

    // --- launches 1-5 ---
    k_rmsnorm<<<NTOK, 256>>>(h, norm_w, sgw);
    k_cvt<<<cvtGrid((long)D_*2*SH), 256>>>(sw1, (__nv_bfloat16*)p_sw1, (long)D_*2*SH);
    k_cvt<<<cvtGrid((long)D_*LAT), 256>>>(latent_dw, (__nv_bfloat16*)p_ldw, (long)D_*LAT);
    k_cvt<<<cvtGrid((long)LAT*D_), 256>>>(latent_uw, (__nv_bfloat16*)p_catW, (long)LAT*D_);
    k_cvt<<<cvtGrid((long)NEXP*LAT*2*EH), 256>>>(ew1, (__nv_bfloat16*)p_ew1, (long)NEXP*LAT*2*EH);

    // --- launch 6: big DUAL shared_w1 GEMM (profiling target) ---
    MMs1<<<dim3(SH/BND, NTOK/128), 128, SM2>>>((const __nv_bfloat16*)p_hbf, D_,
        (const __nv_bfloat16*)p_sw1, 0, 2*SH,
        (__nv_bfloat16*)p_cat + LAT, KCAT, svth, SH, D_);

    // --- remaining conversions ---
    k_cvt<<<cvtGrid((long)NEXP*EH*LAT), 256>>>(ew2, (__nv_bfloat16*)p_ew2, (long)NEXP*EH*LAT);
    k_cvt<<<cvtGrid((long)SH*D_), 256>>>(sw2, (__nv_bfloat16*)p_catW + (size_t)LAT*D_, (long)SH*D_);
    k_cvt<<<cvtGrid((long)D_*D_), 256>>>(opw, (__nv_bfloat16*)p_opw, (long)D_*D_);

    // W_comb = [latent_up; shared_w2] @ opw   (2304 x 2048, K=2048) -> bf16
    MMwc<<<dim3(D_/128, KCAT/128), 128, SM1>>>((const __nv_bfloat16*)p_catW, D_,
        (const __nv_bfloat16*)p_opw, 0, D_, p_Wcomb, D_, nullptr, 0, D_);

    cudaMemsetAsync(p_count, 0, NEXP * sizeof(int));
    cudaMemsetAsync(p_atok,  0, ATOTP * sizeof(int));

    k_router <<<NTOK/32, 256>>>(h, router_w, router_b, norm_w);
    k_topk   <<<NTOK/8, 256>>>();
    k_colsum <<<NEXP, 256>>>();
    k_offsets<<<1, 32>>>();
    k_assign <<<NTOK/256, 256>>>();

    // latent = hnorm @ latent_down  -> bf16
    MMld<<<dim3(LAT/128, NTOK/128), 128, SM1>>>((const __nv_bfloat16*)p_hbf, D_,
        (const __nv_bfloat16*)p_ldw, 0, LAT, p_lbf, LAT, nullptr, 0, D_);

    // exp1 fused spike -> ACTb bf16
    MMe1<<<dim3(MAXTILES, EH/BND), 128, SM2>>>((const __nv_bfloat16*)p_lbf, LAT,
        (const __nv_bfloat16*)p_ew1, (long)LAT*2*EH, 2*EH,
        (__nv_bfloat16*)p_ACTb, EH, evth, EH, LAT);

    // exp2 -> contrib fp32
    MMe2<<<dim3(MAXTILES, LAT/128), 128, SM1>>>((const __nv_bfloat16*)p_ACTb, EH,
        (const __nv_bfloat16*)p_ew2, (long)EH*LAT, LAT, p_contrib, LAT, nullptr, 0, EH);

    k_combine<<<NTOK, LAT>>>();

    // out = h + [eout|ACTS] @ W_comb   (K=2304, fp32 out)
    MMfin<<<dim3(D_/128, NTOK/128), 128, SM1>>>((const __nv_bfloat16*)p_cat, KCAT,
        (const __nv_bfloat16*)p_Wcomb, 0, D_, out, D_, h, D_, KCAT);

    k_lb<<<1, 32>>>(out, out_size);
}